// round 1
// baseline (speedup 1.0000x reference)
#include <cuda_runtime.h>
#include <cstdint>
#include <cstddef>

// Problem constants
#define BB   4
#define LQ   1024
#define LK   2048
#define NH   16
#define HD   64
#define QD   1024
#define KD   512
#define SCALE 0.125f   // 1/sqrt(64)

// Scratch (device globals: allocation-free per harness rules). ~96 MB total.
__device__ float g_q  [(size_t)BB * LQ * QD];   // 16 MB
__device__ float g_k  [(size_t)BB * LK * QD];   // 32 MB
__device__ float g_v  [(size_t)BB * LK * QD];   // 32 MB
__device__ float g_ctx[(size_t)BB * LQ * QD];   // 16 MB

// ---------------------------------------------------------------------------
// Generic NT GEMM + bias:  C[M,N] = A[M,K] @ W[N,K]^T + bias[N]
// 64x64 tile, BK=16, 256 threads, 4x4 register micro-tile per thread.
// Requires M,N % 64 == 0, K % 16 == 0 (true for all call sites).
// ---------------------------------------------------------------------------
__global__ void gemm_nt_bias_k(const float* __restrict__ A, const float* __restrict__ W,
                               const float* __restrict__ bias, float* __restrict__ C,
                               int M, int N, int K) {
    __shared__ float As[16][68];
    __shared__ float Ws[16][68];
    const int bm = blockIdx.y * 64;
    const int bn = blockIdx.x * 64;
    const int tid = threadIdx.x;
    const int ty = tid >> 4, tx = tid & 15;
    const int lrow = tid >> 2;          // 0..63
    const int lc4  = (tid & 3) << 2;    // 0,4,8,12

    float acc[4][4] = {};
    for (int k0 = 0; k0 < K; k0 += 16) {
        float4 a = *(const float4*)(A + (size_t)(bm + lrow) * K + k0 + lc4);
        float4 w = *(const float4*)(W + (size_t)(bn + lrow) * K + k0 + lc4);
        As[lc4 + 0][lrow] = a.x; As[lc4 + 1][lrow] = a.y;
        As[lc4 + 2][lrow] = a.z; As[lc4 + 3][lrow] = a.w;
        Ws[lc4 + 0][lrow] = w.x; Ws[lc4 + 1][lrow] = w.y;
        Ws[lc4 + 2][lrow] = w.z; Ws[lc4 + 3][lrow] = w.w;
        __syncthreads();
        #pragma unroll
        for (int k = 0; k < 16; k++) {
            float ar[4], wr[4];
            #pragma unroll
            for (int i = 0; i < 4; i++) ar[i] = As[k][ty * 4 + i];
            #pragma unroll
            for (int j = 0; j < 4; j++) wr[j] = Ws[k][tx * 4 + j];
            #pragma unroll
            for (int i = 0; i < 4; i++)
                #pragma unroll
                for (int j = 0; j < 4; j++) acc[i][j] += ar[i] * wr[j];
        }
        __syncthreads();
    }
    #pragma unroll
    for (int i = 0; i < 4; i++) {
        #pragma unroll
        for (int j = 0; j < 4; j++) {
            int n = bn + tx * 4 + j;
            C[(size_t)(bm + ty * 4 + i) * N + n] = acc[i][j] + bias[n];
        }
    }
}

// ---------------------------------------------------------------------------
// Scores:  attn_raw[bh, m, n] = SCALE * sum_d q[b, m, h*64+d] * k[b, n, h*64+d]
// Per-(b,h) NT GEMM with lda = ldb = QD, K = 64.
// Grid: (LK/64, LQ/64, BB*NH)
// ---------------------------------------------------------------------------
__global__ void scores_k(const float* __restrict__ qm, const float* __restrict__ km,
                         float* __restrict__ attn) {
    __shared__ float As[16][68];
    __shared__ float Ws[16][68];
    const int bh = blockIdx.z;
    const int b = bh >> 4, h = bh & 15;
    const float* Aq = qm + (size_t)b * LQ * QD + h * HD;
    const float* Ak = km + (size_t)b * LK * QD + h * HD;
    float* Cp = attn + (size_t)bh * LQ * LK;

    const int bm = blockIdx.y * 64;
    const int bn = blockIdx.x * 64;
    const int tid = threadIdx.x;
    const int ty = tid >> 4, tx = tid & 15;
    const int lrow = tid >> 2;
    const int lc4  = (tid & 3) << 2;

    float acc[4][4] = {};
    for (int k0 = 0; k0 < HD; k0 += 16) {
        float4 a = *(const float4*)(Aq + (size_t)(bm + lrow) * QD + k0 + lc4);
        float4 w = *(const float4*)(Ak + (size_t)(bn + lrow) * QD + k0 + lc4);
        As[lc4 + 0][lrow] = a.x; As[lc4 + 1][lrow] = a.y;
        As[lc4 + 2][lrow] = a.z; As[lc4 + 3][lrow] = a.w;
        Ws[lc4 + 0][lrow] = w.x; Ws[lc4 + 1][lrow] = w.y;
        Ws[lc4 + 2][lrow] = w.z; Ws[lc4 + 3][lrow] = w.w;
        __syncthreads();
        #pragma unroll
        for (int k = 0; k < 16; k++) {
            float ar[4], wr[4];
            #pragma unroll
            for (int i = 0; i < 4; i++) ar[i] = As[k][ty * 4 + i];
            #pragma unroll
            for (int j = 0; j < 4; j++) wr[j] = Ws[k][tx * 4 + j];
            #pragma unroll
            for (int i = 0; i < 4; i++)
                #pragma unroll
                for (int j = 0; j < 4; j++) acc[i][j] += ar[i] * wr[j];
        }
        __syncthreads();
    }
    #pragma unroll
    for (int i = 0; i < 4; i++)
        #pragma unroll
        for (int j = 0; j < 4; j++)
            Cp[(size_t)(bm + ty * 4 + i) * LK + bn + tx * 4 + j] = acc[i][j] * SCALE;
}

// ---------------------------------------------------------------------------
// Row softmax in place: one block per row of 2048.
// ---------------------------------------------------------------------------
__device__ __forceinline__ float warp_max(float v) {
    #pragma unroll
    for (int o = 16; o > 0; o >>= 1) v = fmaxf(v, __shfl_xor_sync(0xFFFFFFFFu, v, o));
    return v;
}
__device__ __forceinline__ float warp_sum(float v) {
    #pragma unroll
    for (int o = 16; o > 0; o >>= 1) v += __shfl_xor_sync(0xFFFFFFFFu, v, o);
    return v;
}

__global__ void softmax_k(float* __restrict__ attn) {
    __shared__ float red[8];
    float* row = attn + (size_t)blockIdx.x * LK;
    const int tid = threadIdx.x;

    float v[8];
    float m = -1e30f;
    #pragma unroll
    for (int i = 0; i < 8; i++) { v[i] = row[tid + i * 256]; m = fmaxf(m, v[i]); }
    m = warp_max(m);
    if ((tid & 31) == 0) red[tid >> 5] = m;
    __syncthreads();
    if (tid < 32) {
        float t = (tid < 8) ? red[tid] : -1e30f;
        t = warp_max(t);
        if (tid == 0) red[0] = t;
    }
    __syncthreads();
    m = red[0];
    __syncthreads();

    float s = 0.f;
    #pragma unroll
    for (int i = 0; i < 8; i++) { v[i] = __expf(v[i] - m); s += v[i]; }
    s = warp_sum(s);
    if ((tid & 31) == 0) red[tid >> 5] = s;
    __syncthreads();
    if (tid < 32) {
        float t = (tid < 8) ? red[tid] : 0.f;
        t = warp_sum(t);
        if (tid == 0) red[0] = t;
    }
    __syncthreads();
    const float inv = 1.0f / red[0];
    #pragma unroll
    for (int i = 0; i < 8; i++) row[tid + i * 256] = v[i] * inv;
}

// ---------------------------------------------------------------------------
// Context: ctx[b, m, h*64+d] = sum_n attn[bh, m, n] * v[b, n, h*64+d]
// NN GEMM per (b,h): M-tile 64, N = 64 (= HD), K = 2048.
// Grid: (LQ/64, BB*NH)
// ---------------------------------------------------------------------------
__global__ void context_k(const float* __restrict__ attn, const float* __restrict__ vm,
                          float* __restrict__ ctx) {
    __shared__ float As[16][68];
    __shared__ float Vs[16][68];
    const int bh = blockIdx.y;
    const int b = bh >> 4, h = bh & 15;
    const float* Ap = attn + (size_t)bh * LQ * LK;
    const float* Vp = vm + (size_t)b * LK * QD + h * HD;

    const int bm = blockIdx.x * 64;
    const int tid = threadIdx.x;
    const int ty = tid >> 4, tx = tid & 15;
    const int lrow = tid >> 2;          // attn tile: 0..63 rows
    const int lc4  = (tid & 3) << 2;
    const int vr   = tid >> 4;          // V tile: 0..15 k-rows
    const int vc4  = (tid & 15) << 2;   // 0..60

    float acc[4][4] = {};
    for (int k0 = 0; k0 < LK; k0 += 16) {
        float4 a = *(const float4*)(Ap + (size_t)(bm + lrow) * LK + k0 + lc4);
        float4 w = *(const float4*)(Vp + (size_t)(k0 + vr) * QD + vc4);
        As[lc4 + 0][lrow] = a.x; As[lc4 + 1][lrow] = a.y;
        As[lc4 + 2][lrow] = a.z; As[lc4 + 3][lrow] = a.w;
        Vs[vr][vc4 + 0] = w.x; Vs[vr][vc4 + 1] = w.y;
        Vs[vr][vc4 + 2] = w.z; Vs[vr][vc4 + 3] = w.w;
        __syncthreads();
        #pragma unroll
        for (int k = 0; k < 16; k++) {
            float ar[4], wr[4];
            #pragma unroll
            for (int i = 0; i < 4; i++) ar[i] = As[k][ty * 4 + i];
            #pragma unroll
            for (int j = 0; j < 4; j++) wr[j] = Vs[k][tx * 4 + j];
            #pragma unroll
            for (int i = 0; i < 4; i++)
                #pragma unroll
                for (int j = 0; j < 4; j++) acc[i][j] += ar[i] * wr[j];
        }
        __syncthreads();
    }
    #pragma unroll
    for (int i = 0; i < 4; i++)
        #pragma unroll
        for (int j = 0; j < 4; j++)
            ctx[(size_t)(b * LQ + bm + ty * 4 + i) * QD + h * HD + tx * 4 + j] = acc[i][j];
}

// ---------------------------------------------------------------------------
// kernel_launch
// Inputs (metadata order): query, key, value, Wq, bq, Wk, bk, Wv, bv, Wo, bo
// Output: concat( output[B,Lq,1024] , attn[B,H,Lq,Lk] ) as fp32.
// ---------------------------------------------------------------------------
extern "C" void kernel_launch(void* const* d_in, const int* in_sizes, int n_in,
                              void* d_out, int out_size) {
    const float* query = (const float*)d_in[0];
    const float* key   = (const float*)d_in[1];
    const float* value = (const float*)d_in[2];
    const float* Wq = (const float*)d_in[3];
    const float* bq = (const float*)d_in[4];
    const float* Wk = (const float*)d_in[5];
    const float* bk = (const float*)d_in[6];
    const float* Wv = (const float*)d_in[7];
    const float* bv = (const float*)d_in[8];
    const float* Wo = (const float*)d_in[9];
    const float* bo = (const float*)d_in[10];

    float* out  = (float*)d_out;
    float* attn = out + (size_t)BB * LQ * QD;

    float *qs, *ks, *vs, *cs;
    cudaGetSymbolAddress((void**)&qs, g_q);
    cudaGetSymbolAddress((void**)&ks, g_k);
    cudaGetSymbolAddress((void**)&vs, g_v);
    cudaGetSymbolAddress((void**)&cs, g_ctx);

    // Projections
    gemm_nt_bias_k<<<dim3(QD / 64, (BB * LQ) / 64), 256>>>(query, Wq, bq, qs, BB * LQ, QD, QD);
    gemm_nt_bias_k<<<dim3(QD / 64, (BB * LK) / 64), 256>>>(key,   Wk, bk, ks, BB * LK, QD, KD);
    gemm_nt_bias_k<<<dim3(QD / 64, (BB * LK) / 64), 256>>>(value, Wv, bv, vs, BB * LK, QD, KD);

    // Attention
    scores_k<<<dim3(LK / 64, LQ / 64, BB * NH), 256>>>(qs, ks, attn);
    softmax_k<<<BB * NH * LQ, 256>>>(attn);
    context_k<<<dim3(LQ / 64, BB * NH), 256>>>(attn, vs, cs);

    // Output projection
    gemm_nt_bias_k<<<dim3(QD / 64, (BB * LQ) / 64), 256>>>(cs, Wo, bo, out, BB * LQ, QD, QD);
}

// round 2
// speedup vs baseline: 1.6894x; 1.6894x over previous
#include <cuda_runtime.h>
#include <cstdint>
#include <cstddef>

// Problem constants
#define BB   4
#define LQ   1024
#define LK   2048
#define NH   16
#define HD   64
#define QD   1024
#define KD   512
#define SCALE 0.125f   // 1/sqrt(64)

// Scratch (device globals: allocation-free per harness rules). ~96 MB total.
__device__ float g_q  [(size_t)BB * LQ * QD];   // 16 MB
__device__ float g_k  [(size_t)BB * LK * QD];   // 32 MB
__device__ float g_v  [(size_t)BB * LK * QD];   // 32 MB
__device__ float g_ctx[(size_t)BB * LQ * QD];   // 16 MB

// ---------------------------------------------------------------------------
// TF32 helpers
// ---------------------------------------------------------------------------
__device__ __forceinline__ uint32_t f2tf(float f) {
    uint32_t r;
    asm("cvt.rna.tf32.f32 %0, %1;" : "=r"(r) : "f"(f));
    return r;
}

__device__ __forceinline__ void mma_tf32(float c[4],
                                         const uint32_t a[4],
                                         const uint32_t b[2]) {
    asm volatile(
        "mma.sync.aligned.m16n8k8.row.col.f32.tf32.tf32.f32 "
        "{%0,%1,%2,%3}, {%4,%5,%6,%7}, {%8,%9}, {%0,%1,%2,%3};\n"
        : "+f"(c[0]), "+f"(c[1]), "+f"(c[2]), "+f"(c[3])
        : "r"(a[0]), "r"(a[1]), "r"(a[2]), "r"(a[3]),
          "r"(b[0]), "r"(b[1]));
}

// ===========================================================================
// GEMM NT (tensor core):  C[M,N] = A[M,K] @ W[N,K]^T + bias[N]
// Block tile 128x128, BK=32, 256 threads = 8 warps, warp tile 32x64.
// lda = ldw = K, ldc = N.  M%128==0, N%128==0, K%32==0 at all call sites.
// Shared stored K-major with stride 136 (mod 32 == 8 -> conflict-free frags).
// ===========================================================================
__global__ void gemm_nt_tc(const float* __restrict__ A, const float* __restrict__ W,
                           const float* __restrict__ bias, float* __restrict__ C,
                           int M, int N, int K) {
    __shared__ uint32_t As[32][136];
    __shared__ uint32_t Bs[32][136];
    const int tid = threadIdx.x;
    const int bm = blockIdx.y * 128;
    const int bn = blockIdx.x * 128;
    const int w = tid >> 5, lane = tid & 31;
    const int g = lane >> 2, tig = lane & 3;
    const int wm = (w & 3) * 32, wn = (w >> 2) * 64;
    const int lrow = tid >> 3;       // 0..31
    const int lkc  = (tid & 7) * 4;  // 0..28

    float acc[2][8][4] = {};

    for (int k0 = 0; k0 < K; k0 += 32) {
        #pragma unroll
        for (int i = 0; i < 4; i++) {
            int row = i * 32 + lrow;
            float4 a = *(const float4*)(A + (size_t)(bm + row) * K + k0 + lkc);
            As[lkc + 0][row] = f2tf(a.x); As[lkc + 1][row] = f2tf(a.y);
            As[lkc + 2][row] = f2tf(a.z); As[lkc + 3][row] = f2tf(a.w);
            float4 b = *(const float4*)(W + (size_t)(bn + row) * K + k0 + lkc);
            Bs[lkc + 0][row] = f2tf(b.x); Bs[lkc + 1][row] = f2tf(b.y);
            Bs[lkc + 2][row] = f2tf(b.z); Bs[lkc + 3][row] = f2tf(b.w);
        }
        __syncthreads();
        #pragma unroll
        for (int kk = 0; kk < 32; kk += 8) {
            uint32_t af[2][4], bf[8][2];
            #pragma unroll
            for (int mf = 0; mf < 2; mf++) {
                int mb = wm + mf * 16;
                af[mf][0] = As[kk + tig][mb + g];
                af[mf][1] = As[kk + tig][mb + g + 8];
                af[mf][2] = As[kk + tig + 4][mb + g];
                af[mf][3] = As[kk + tig + 4][mb + g + 8];
            }
            #pragma unroll
            for (int nf = 0; nf < 8; nf++) {
                int nb = wn + nf * 8 + g;
                bf[nf][0] = Bs[kk + tig][nb];
                bf[nf][1] = Bs[kk + tig + 4][nb];
            }
            #pragma unroll
            for (int mf = 0; mf < 2; mf++)
                #pragma unroll
                for (int nf = 0; nf < 8; nf++)
                    mma_tf32(acc[mf][nf], af[mf], bf[nf]);
        }
        __syncthreads();
    }

    #pragma unroll
    for (int mf = 0; mf < 2; mf++) {
        #pragma unroll
        for (int nf = 0; nf < 8; nf++) {
            int row = bm + wm + mf * 16 + g;
            int col = bn + wn + nf * 8 + tig * 2;
            float b0 = bias ? __ldg(bias + col)     : 0.f;
            float b1 = bias ? __ldg(bias + col + 1) : 0.f;
            *(float2*)(C + (size_t)row * N + col) =
                make_float2(acc[mf][nf][0] + b0, acc[mf][nf][1] + b1);
            *(float2*)(C + (size_t)(row + 8) * N + col) =
                make_float2(acc[mf][nf][2] + b0, acc[mf][nf][3] + b1);
        }
    }
}

// ===========================================================================
// Scores (tensor core): attn[bh,m,n] = SCALE * sum_d q[b,m,h*64+d]*k[b,n,h*64+d]
// Per-(b,h) NT GEMM, lda = ldb = QD, K = 64. Block 128x128.
// Grid: (LK/128, LQ/128, BB*NH)
// ===========================================================================
__global__ void scores_tc(const float* __restrict__ qm, const float* __restrict__ km,
                          float* __restrict__ attn) {
    __shared__ uint32_t As[32][136];
    __shared__ uint32_t Bs[32][136];
    const int bh = blockIdx.z;
    const int b = bh >> 4, h = bh & 15;
    const float* Aq = qm + (size_t)b * LQ * QD + h * HD;
    const float* Ak = km + (size_t)b * LK * QD + h * HD;
    float* Cp = attn + (size_t)bh * LQ * LK;

    const int tid = threadIdx.x;
    const int bm = blockIdx.y * 128;
    const int bn = blockIdx.x * 128;
    const int w = tid >> 5, lane = tid & 31;
    const int g = lane >> 2, tig = lane & 3;
    const int wm = (w & 3) * 32, wn = (w >> 2) * 64;
    const int lrow = tid >> 3;
    const int lkc  = (tid & 7) * 4;

    float acc[2][8][4] = {};

    for (int k0 = 0; k0 < HD; k0 += 32) {
        #pragma unroll
        for (int i = 0; i < 4; i++) {
            int row = i * 32 + lrow;
            float4 a = *(const float4*)(Aq + (size_t)(bm + row) * QD + k0 + lkc);
            As[lkc + 0][row] = f2tf(a.x); As[lkc + 1][row] = f2tf(a.y);
            As[lkc + 2][row] = f2tf(a.z); As[lkc + 3][row] = f2tf(a.w);
            float4 b4 = *(const float4*)(Ak + (size_t)(bn + row) * QD + k0 + lkc);
            Bs[lkc + 0][row] = f2tf(b4.x); Bs[lkc + 1][row] = f2tf(b4.y);
            Bs[lkc + 2][row] = f2tf(b4.z); Bs[lkc + 3][row] = f2tf(b4.w);
        }
        __syncthreads();
        #pragma unroll
        for (int kk = 0; kk < 32; kk += 8) {
            uint32_t af[2][4], bf[8][2];
            #pragma unroll
            for (int mf = 0; mf < 2; mf++) {
                int mb = wm + mf * 16;
                af[mf][0] = As[kk + tig][mb + g];
                af[mf][1] = As[kk + tig][mb + g + 8];
                af[mf][2] = As[kk + tig + 4][mb + g];
                af[mf][3] = As[kk + tig + 4][mb + g + 8];
            }
            #pragma unroll
            for (int nf = 0; nf < 8; nf++) {
                int nb = wn + nf * 8 + g;
                bf[nf][0] = Bs[kk + tig][nb];
                bf[nf][1] = Bs[kk + tig + 4][nb];
            }
            #pragma unroll
            for (int mf = 0; mf < 2; mf++)
                #pragma unroll
                for (int nf = 0; nf < 8; nf++)
                    mma_tf32(acc[mf][nf], af[mf], bf[nf]);
        }
        __syncthreads();
    }

    #pragma unroll
    for (int mf = 0; mf < 2; mf++) {
        #pragma unroll
        for (int nf = 0; nf < 8; nf++) {
            int row = bm + wm + mf * 16 + g;
            int col = bn + wn + nf * 8 + tig * 2;
            *(float2*)(Cp + (size_t)row * LK + col) =
                make_float2(acc[mf][nf][0] * SCALE, acc[mf][nf][1] * SCALE);
            *(float2*)(Cp + (size_t)(row + 8) * LK + col) =
                make_float2(acc[mf][nf][2] * SCALE, acc[mf][nf][3] * SCALE);
        }
    }
}

// ===========================================================================
// Context (tensor core): ctx[b,m,h*64+d] = sum_n attn[bh,m,n] * v[b,n,h*64+d]
// NN GEMM per (b,h): block 128x64, BK=32, warp tile 32x32.
// Grid: (LQ/128, BB*NH)
// ===========================================================================
__global__ void context_tc(const float* __restrict__ attn, const float* __restrict__ vm,
                           float* __restrict__ ctx) {
    __shared__ uint32_t As[32][136];
    __shared__ uint32_t Vs[32][72];
    const int bh = blockIdx.y;
    const int b = bh >> 4, h = bh & 15;
    const float* Ap = attn + (size_t)bh * LQ * LK;
    const float* Vp = vm + (size_t)b * LK * QD + h * HD;

    const int tid = threadIdx.x;
    const int bm = blockIdx.x * 128;
    const int w = tid >> 5, lane = tid & 31;
    const int g = lane >> 2, tig = lane & 3;
    const int wm = (w & 3) * 32, wn = (w >> 2) * 32;
    const int lrow = tid >> 3;
    const int lkc  = (tid & 7) * 4;
    const int vk = tid >> 4;          // 0..15
    const int vc = (tid & 15) * 4;    // 0..60

    float acc[2][4][4] = {};

    for (int k0 = 0; k0 < LK; k0 += 32) {
        #pragma unroll
        for (int i = 0; i < 4; i++) {
            int row = i * 32 + lrow;
            float4 a = *(const float4*)(Ap + (size_t)(bm + row) * LK + k0 + lkc);
            As[lkc + 0][row] = f2tf(a.x); As[lkc + 1][row] = f2tf(a.y);
            As[lkc + 2][row] = f2tf(a.z); As[lkc + 3][row] = f2tf(a.w);
        }
        #pragma unroll
        for (int i = 0; i < 2; i++) {
            int kr = i * 16 + vk;
            float4 v4 = *(const float4*)(Vp + (size_t)(k0 + kr) * QD + vc);
            Vs[kr][vc + 0] = f2tf(v4.x); Vs[kr][vc + 1] = f2tf(v4.y);
            Vs[kr][vc + 2] = f2tf(v4.z); Vs[kr][vc + 3] = f2tf(v4.w);
        }
        __syncthreads();
        #pragma unroll
        for (int kk = 0; kk < 32; kk += 8) {
            uint32_t af[2][4], bf[4][2];
            #pragma unroll
            for (int mf = 0; mf < 2; mf++) {
                int mb = wm + mf * 16;
                af[mf][0] = As[kk + tig][mb + g];
                af[mf][1] = As[kk + tig][mb + g + 8];
                af[mf][2] = As[kk + tig + 4][mb + g];
                af[mf][3] = As[kk + tig + 4][mb + g + 8];
            }
            #pragma unroll
            for (int nf = 0; nf < 4; nf++) {
                int nb = wn + nf * 8 + g;
                bf[nf][0] = Vs[kk + tig][nb];
                bf[nf][1] = Vs[kk + tig + 4][nb];
            }
            #pragma unroll
            for (int mf = 0; mf < 2; mf++)
                #pragma unroll
                for (int nf = 0; nf < 4; nf++)
                    mma_tf32(acc[mf][nf], af[mf], bf[nf]);
        }
        __syncthreads();
    }

    #pragma unroll
    for (int mf = 0; mf < 2; mf++) {
        #pragma unroll
        for (int nf = 0; nf < 4; nf++) {
            int row = bm + wm + mf * 16 + g;
            int col = h * HD + wn + nf * 8 + tig * 2;
            *(float2*)(ctx + (size_t)(b * LQ + row) * QD + col) =
                make_float2(acc[mf][nf][0], acc[mf][nf][1]);
            *(float2*)(ctx + (size_t)(b * LQ + row + 8) * QD + col) =
                make_float2(acc[mf][nf][2], acc[mf][nf][3]);
        }
    }
}

// ---------------------------------------------------------------------------
// Row softmax in place: one block per row of 2048.
// ---------------------------------------------------------------------------
__device__ __forceinline__ float warp_max(float v) {
    #pragma unroll
    for (int o = 16; o > 0; o >>= 1) v = fmaxf(v, __shfl_xor_sync(0xFFFFFFFFu, v, o));
    return v;
}
__device__ __forceinline__ float warp_sum(float v) {
    #pragma unroll
    for (int o = 16; o > 0; o >>= 1) v += __shfl_xor_sync(0xFFFFFFFFu, v, o);
    return v;
}

__global__ void softmax_k(float* __restrict__ attn) {
    __shared__ float red[8];
    float* row = attn + (size_t)blockIdx.x * LK;
    const int tid = threadIdx.x;

    float v[8];
    float m = -1e30f;
    #pragma unroll
    for (int i = 0; i < 8; i++) { v[i] = row[tid + i * 256]; m = fmaxf(m, v[i]); }
    m = warp_max(m);
    if ((tid & 31) == 0) red[tid >> 5] = m;
    __syncthreads();
    if (tid < 32) {
        float t = (tid < 8) ? red[tid] : -1e30f;
        t = warp_max(t);
        if (tid == 0) red[0] = t;
    }
    __syncthreads();
    m = red[0];
    __syncthreads();

    float s = 0.f;
    #pragma unroll
    for (int i = 0; i < 8; i++) { v[i] = __expf(v[i] - m); s += v[i]; }
    s = warp_sum(s);
    if ((tid & 31) == 0) red[tid >> 5] = s;
    __syncthreads();
    if (tid < 32) {
        float t = (tid < 8) ? red[tid] : 0.f;
        t = warp_sum(t);
        if (tid == 0) red[0] = t;
    }
    __syncthreads();
    const float inv = 1.0f / red[0];
    #pragma unroll
    for (int i = 0; i < 8; i++) row[tid + i * 256] = v[i] * inv;
}

// ---------------------------------------------------------------------------
// kernel_launch
// Inputs (metadata order): query, key, value, Wq, bq, Wk, bk, Wv, bv, Wo, bo
// Output: concat( output[B,Lq,1024] , attn[B,H,Lq,Lk] ) as fp32.
// ---------------------------------------------------------------------------
extern "C" void kernel_launch(void* const* d_in, const int* in_sizes, int n_in,
                              void* d_out, int out_size) {
    const float* query = (const float*)d_in[0];
    const float* key   = (const float*)d_in[1];
    const float* value = (const float*)d_in[2];
    const float* Wq = (const float*)d_in[3];
    const float* bq = (const float*)d_in[4];
    const float* Wk = (const float*)d_in[5];
    const float* bk = (const float*)d_in[6];
    const float* Wv = (const float*)d_in[7];
    const float* bv = (const float*)d_in[8];
    const float* Wo = (const float*)d_in[9];
    const float* bo = (const float*)d_in[10];

    float* out  = (float*)d_out;
    float* attn = out + (size_t)BB * LQ * QD;

    float *qs, *ks, *vs, *cs;
    cudaGetSymbolAddress((void**)&qs, g_q);
    cudaGetSymbolAddress((void**)&ks, g_k);
    cudaGetSymbolAddress((void**)&vs, g_v);
    cudaGetSymbolAddress((void**)&cs, g_ctx);

    // Projections (tensor core, TF32)
    gemm_nt_tc<<<dim3(QD / 128, (BB * LQ) / 128), 256>>>(query, Wq, bq, qs, BB * LQ, QD, QD);
    gemm_nt_tc<<<dim3(QD / 128, (BB * LK) / 128), 256>>>(key,   Wk, bk, ks, BB * LK, QD, KD);
    gemm_nt_tc<<<dim3(QD / 128, (BB * LK) / 128), 256>>>(value, Wv, bv, vs, BB * LK, QD, KD);

    // Attention
    scores_tc<<<dim3(LK / 128, LQ / 128, BB * NH), 256>>>(qs, ks, attn);
    softmax_k<<<BB * NH * LQ, 256>>>(attn);
    context_tc<<<dim3(LQ / 128, BB * NH), 256>>>(attn, vs, cs);

    // Output projection
    gemm_nt_tc<<<dim3(QD / 128, (BB * LQ) / 128), 256>>>(cs, Wo, bo, out, BB * LQ, QD, QD);
}

// round 3
// speedup vs baseline: 2.7661x; 1.6373x over previous
#include <cuda_runtime.h>
#include <cstdint>
#include <cstddef>

// Problem constants
#define BB   4
#define LQ   1024
#define LK   2048
#define NH   16
#define HD   64
#define QD   1024
#define KD   512
#define SCALE 0.125f   // 1/sqrt(64)

// Scratch (device globals: allocation-free per harness rules). ~96 MB total.
__device__ float g_q  [(size_t)BB * LQ * QD];   // 16 MB
__device__ float g_k  [(size_t)BB * LK * QD];   // 32 MB
__device__ float g_v  [(size_t)BB * LK * QD];   // 32 MB
__device__ float g_ctx[(size_t)BB * LQ * QD];   // 16 MB

// ---------------------------------------------------------------------------
// Helpers
// ---------------------------------------------------------------------------
__device__ __forceinline__ uint32_t f2tf(float f) {
    uint32_t r;
    asm("cvt.rna.tf32.f32 %0, %1;" : "=r"(r) : "f"(f));
    return r;
}

__device__ __forceinline__ void mma_tf32(float c[4],
                                         const uint32_t a[4],
                                         const uint32_t b[2]) {
    asm volatile(
        "mma.sync.aligned.m16n8k8.row.col.f32.tf32.tf32.f32 "
        "{%0,%1,%2,%3}, {%4,%5,%6,%7}, {%8,%9}, {%0,%1,%2,%3};\n"
        : "+f"(c[0]), "+f"(c[1]), "+f"(c[2]), "+f"(c[3])
        : "r"(a[0]), "r"(a[1]), "r"(a[2]), "r"(a[3]),
          "r"(b[0]), "r"(b[1]));
}

__device__ __forceinline__ uint32_t smem_u32(const void* p) {
    uint32_t r;
    asm("{ .reg .u64 t; cvta.to.shared.u64 t, %1; cvt.u32.u64 %0, t; }"
        : "=r"(r) : "l"(p));
    return r;
}

__device__ __forceinline__ void cp16(void* dst_smem, const void* src_gmem) {
    asm volatile("cp.async.cg.shared.global [%0], [%1], 16;\n"
                 :: "r"(smem_u32(dst_smem)), "l"(src_gmem));
}
__device__ __forceinline__ void cp_commit() {
    asm volatile("cp.async.commit_group;\n");
}
template <int N>
__device__ __forceinline__ void cp_wait() {
    asm volatile("cp.async.wait_group %0;\n" :: "n"(N));
}

// smem strides (floats): conflict-free for fragment pattern (g*4+tig lanes)
#define ASTR 36   // 32 k + 4 pad
#define VSTR 68   // 64 n + 4 pad

// ===========================================================================
// GEMM NT (tensor core, cp.async double-buffered):
// C[M,N] = A[M,K] @ W[N,K]^T + bias[N]
// Block 128x128, BK=32, 256 threads = 8 warps (4x2), warp tile 32x64.
// Dynamic smem: As[2][128][36] + Bs[2][128][36] = 73728 B.
// ===========================================================================
__global__ __launch_bounds__(256, 2)
void gemm_nt_tc(const float* __restrict__ A, const float* __restrict__ W,
                const float* __restrict__ bias, float* __restrict__ C,
                int M, int N, int K) {
    extern __shared__ float sm[];
    float* As = sm;                    // [2][128][ASTR]
    float* Bs = sm + 2 * 128 * ASTR;   // [2][128][ASTR]

    const int tid = threadIdx.x;
    const int bm = blockIdx.y * 128;
    const int bn = blockIdx.x * 128;
    const int w = tid >> 5, lane = tid & 31;
    const int g = lane >> 2, tig = lane & 3;
    const int wm = (w & 3) * 32, wn = (w >> 2) * 64;

    float acc[2][8][4] = {};

    const int S = K >> 5;  // number of 32-wide slabs

    // prefetch chunk coords: 4 chunks per matrix per thread
    // chunk ch in [0,1024): row = ch>>3 (0..127), kc = (ch&7)*4
    auto prefetch = [&](int s, int buf) {
        const int k0 = s * 32;
        float* Ab = As + buf * 128 * ASTR;
        float* Bb = Bs + buf * 128 * ASTR;
        #pragma unroll
        for (int i = 0; i < 4; i++) {
            int ch = tid + i * 256;
            int row = ch >> 3;
            int kc = (ch & 7) * 4;
            cp16(Ab + row * ASTR + kc, A + (size_t)(bm + row) * K + k0 + kc);
            cp16(Bb + row * ASTR + kc, W + (size_t)(bn + row) * K + k0 + kc);
        }
    };

    prefetch(0, 0);
    cp_commit();

    for (int s = 0; s < S; s++) {
        const int buf = s & 1;
        if (s + 1 < S) { prefetch(s + 1, buf ^ 1); cp_commit(); cp_wait<1>(); }
        else           { cp_wait<0>(); }
        __syncthreads();

        const float* Ab = As + buf * 128 * ASTR;
        const float* Bb = Bs + buf * 128 * ASTR;
        #pragma unroll
        for (int kk = 0; kk < 32; kk += 8) {
            uint32_t af[2][4], bf[8][2];
            #pragma unroll
            for (int mf = 0; mf < 2; mf++) {
                int mb = wm + mf * 16;
                af[mf][0] = f2tf(Ab[(mb + g) * ASTR + kk + tig]);
                af[mf][1] = f2tf(Ab[(mb + g + 8) * ASTR + kk + tig]);
                af[mf][2] = f2tf(Ab[(mb + g) * ASTR + kk + tig + 4]);
                af[mf][3] = f2tf(Ab[(mb + g + 8) * ASTR + kk + tig + 4]);
            }
            #pragma unroll
            for (int nf = 0; nf < 8; nf++) {
                int nb = wn + nf * 8 + g;
                bf[nf][0] = f2tf(Bb[nb * ASTR + kk + tig]);
                bf[nf][1] = f2tf(Bb[nb * ASTR + kk + tig + 4]);
            }
            #pragma unroll
            for (int mf = 0; mf < 2; mf++)
                #pragma unroll
                for (int nf = 0; nf < 8; nf++)
                    mma_tf32(acc[mf][nf], af[mf], bf[nf]);
        }
        __syncthreads();
    }

    #pragma unroll
    for (int mf = 0; mf < 2; mf++) {
        #pragma unroll
        for (int nf = 0; nf < 8; nf++) {
            int row = bm + wm + mf * 16 + g;
            int col = bn + wn + nf * 8 + tig * 2;
            float b0 = __ldg(bias + col);
            float b1 = __ldg(bias + col + 1);
            *(float2*)(C + (size_t)row * N + col) =
                make_float2(acc[mf][nf][0] + b0, acc[mf][nf][1] + b1);
            *(float2*)(C + (size_t)(row + 8) * N + col) =
                make_float2(acc[mf][nf][2] + b0, acc[mf][nf][3] + b1);
        }
    }
}

// ===========================================================================
// Scores: attn[bh,m,n] = SCALE * sum_d q[b,m,h*64+d]*k[b,n,h*64+d]
// Same structure as gemm_nt_tc; lda=ldb=QD, K=64 (2 slabs).
// Grid: (LK/128, LQ/128, BB*NH)
// ===========================================================================
__global__ __launch_bounds__(256, 2)
void scores_tc(const float* __restrict__ qm, const float* __restrict__ km,
               float* __restrict__ attn) {
    extern __shared__ float sm[];
    float* As = sm;
    float* Bs = sm + 2 * 128 * ASTR;

    const int bh = blockIdx.z;
    const int b = bh >> 4, h = bh & 15;
    const float* Aq = qm + (size_t)b * LQ * QD + h * HD;
    const float* Ak = km + (size_t)b * LK * QD + h * HD;
    float* Cp = attn + (size_t)bh * LQ * LK;

    const int tid = threadIdx.x;
    const int bm = blockIdx.y * 128;
    const int bn = blockIdx.x * 128;
    const int w = tid >> 5, lane = tid & 31;
    const int g = lane >> 2, tig = lane & 3;
    const int wm = (w & 3) * 32, wn = (w >> 2) * 64;

    float acc[2][8][4] = {};

    auto prefetch = [&](int s, int buf) {
        const int k0 = s * 32;
        float* Ab = As + buf * 128 * ASTR;
        float* Bb = Bs + buf * 128 * ASTR;
        #pragma unroll
        for (int i = 0; i < 4; i++) {
            int ch = tid + i * 256;
            int row = ch >> 3;
            int kc = (ch & 7) * 4;
            cp16(Ab + row * ASTR + kc, Aq + (size_t)(bm + row) * QD + k0 + kc);
            cp16(Bb + row * ASTR + kc, Ak + (size_t)(bn + row) * QD + k0 + kc);
        }
    };

    prefetch(0, 0);
    cp_commit();

    #pragma unroll
    for (int s = 0; s < 2; s++) {
        const int buf = s & 1;
        if (s + 1 < 2) { prefetch(s + 1, buf ^ 1); cp_commit(); cp_wait<1>(); }
        else           { cp_wait<0>(); }
        __syncthreads();

        const float* Ab = As + buf * 128 * ASTR;
        const float* Bb = Bs + buf * 128 * ASTR;
        #pragma unroll
        for (int kk = 0; kk < 32; kk += 8) {
            uint32_t af[2][4], bf[8][2];
            #pragma unroll
            for (int mf = 0; mf < 2; mf++) {
                int mb = wm + mf * 16;
                af[mf][0] = f2tf(Ab[(mb + g) * ASTR + kk + tig]);
                af[mf][1] = f2tf(Ab[(mb + g + 8) * ASTR + kk + tig]);
                af[mf][2] = f2tf(Ab[(mb + g) * ASTR + kk + tig + 4]);
                af[mf][3] = f2tf(Ab[(mb + g + 8) * ASTR + kk + tig + 4]);
            }
            #pragma unroll
            for (int nf = 0; nf < 8; nf++) {
                int nb = wn + nf * 8 + g;
                bf[nf][0] = f2tf(Bb[nb * ASTR + kk + tig]);
                bf[nf][1] = f2tf(Bb[nb * ASTR + kk + tig + 4]);
            }
            #pragma unroll
            for (int mf = 0; mf < 2; mf++)
                #pragma unroll
                for (int nf = 0; nf < 8; nf++)
                    mma_tf32(acc[mf][nf], af[mf], bf[nf]);
        }
        __syncthreads();
    }

    #pragma unroll
    for (int mf = 0; mf < 2; mf++) {
        #pragma unroll
        for (int nf = 0; nf < 8; nf++) {
            int row = bm + wm + mf * 16 + g;
            int col = bn + wn + nf * 8 + tig * 2;
            *(float2*)(Cp + (size_t)row * LK + col) =
                make_float2(acc[mf][nf][0] * SCALE, acc[mf][nf][1] * SCALE);
            *(float2*)(Cp + (size_t)(row + 8) * LK + col) =
                make_float2(acc[mf][nf][2] * SCALE, acc[mf][nf][3] * SCALE);
        }
    }
}

// ===========================================================================
// Context: ctx[b,m,h*64+d] = sum_n attn[bh,m,n] * v[b,n,h*64+d]
// NN GEMM per (b,h): block 128x64, BK=32, warp tile 32x32.
// Dynamic smem: As[2][128][36] + Vs[2][32][68] = 54272 B.
// Grid: (LQ/128, BB*NH)
// ===========================================================================
__global__ __launch_bounds__(256, 2)
void context_tc(const float* __restrict__ attn, const float* __restrict__ vm,
                float* __restrict__ ctx) {
    extern __shared__ float sm[];
    float* As = sm;                    // [2][128][ASTR]
    float* Vs = sm + 2 * 128 * ASTR;   // [2][32][VSTR]

    const int bh = blockIdx.y;
    const int b = bh >> 4, h = bh & 15;
    const float* Ap = attn + (size_t)bh * LQ * LK;
    const float* Vp = vm + (size_t)b * LK * QD + h * HD;

    const int tid = threadIdx.x;
    const int bm = blockIdx.x * 128;
    const int w = tid >> 5, lane = tid & 31;
    const int g = lane >> 2, tig = lane & 3;
    const int wm = (w & 3) * 32, wn = (w >> 2) * 32;

    float acc[2][4][4] = {};

    auto prefetch = [&](int s, int buf) {
        const int k0 = s * 32;
        float* Ab = As + buf * 128 * ASTR;
        float* Vb = Vs + buf * 32 * VSTR;
        #pragma unroll
        for (int i = 0; i < 4; i++) {
            int ch = tid + i * 256;
            int row = ch >> 3;
            int kc = (ch & 7) * 4;
            cp16(Ab + row * ASTR + kc, Ap + (size_t)(bm + row) * LK + k0 + kc);
        }
        #pragma unroll
        for (int i = 0; i < 2; i++) {
            int ch = tid + i * 256;
            int kr = ch >> 4;           // 0..31
            int nc = (ch & 15) * 4;     // 0..60
            cp16(Vb + kr * VSTR + nc, Vp + (size_t)(k0 + kr) * QD + nc);
        }
    };

    prefetch(0, 0);
    cp_commit();

    const int S = LK / 32;  // 64 slabs
    for (int s = 0; s < S; s++) {
        const int buf = s & 1;
        if (s + 1 < S) { prefetch(s + 1, buf ^ 1); cp_commit(); cp_wait<1>(); }
        else           { cp_wait<0>(); }
        __syncthreads();

        const float* Ab = As + buf * 128 * ASTR;
        const float* Vb = Vs + buf * 32 * VSTR;
        #pragma unroll
        for (int kk = 0; kk < 32; kk += 8) {
            uint32_t af[2][4], bf[4][2];
            #pragma unroll
            for (int mf = 0; mf < 2; mf++) {
                int mb = wm + mf * 16;
                af[mf][0] = f2tf(Ab[(mb + g) * ASTR + kk + tig]);
                af[mf][1] = f2tf(Ab[(mb + g + 8) * ASTR + kk + tig]);
                af[mf][2] = f2tf(Ab[(mb + g) * ASTR + kk + tig + 4]);
                af[mf][3] = f2tf(Ab[(mb + g + 8) * ASTR + kk + tig + 4]);
            }
            #pragma unroll
            for (int nf = 0; nf < 4; nf++) {
                int nb = wn + nf * 8 + g;
                bf[nf][0] = f2tf(Vb[(kk + tig) * VSTR + nb]);
                bf[nf][1] = f2tf(Vb[(kk + tig + 4) * VSTR + nb]);
            }
            #pragma unroll
            for (int mf = 0; mf < 2; mf++)
                #pragma unroll
                for (int nf = 0; nf < 4; nf++)
                    mma_tf32(acc[mf][nf], af[mf], bf[nf]);
        }
        __syncthreads();
    }

    #pragma unroll
    for (int mf = 0; mf < 2; mf++) {
        #pragma unroll
        for (int nf = 0; nf < 4; nf++) {
            int row = bm + wm + mf * 16 + g;
            int col = h * HD + wn + nf * 8 + tig * 2;
            *(float2*)(ctx + (size_t)(b * LQ + row) * QD + col) =
                make_float2(acc[mf][nf][0], acc[mf][nf][1]);
            *(float2*)(ctx + (size_t)(b * LQ + row + 8) * QD + col) =
                make_float2(acc[mf][nf][2], acc[mf][nf][3]);
        }
    }
}

// ---------------------------------------------------------------------------
// Row softmax in place (float4 vectorized): one block per row of 2048.
// ---------------------------------------------------------------------------
__device__ __forceinline__ float warp_max(float v) {
    #pragma unroll
    for (int o = 16; o > 0; o >>= 1) v = fmaxf(v, __shfl_xor_sync(0xFFFFFFFFu, v, o));
    return v;
}
__device__ __forceinline__ float warp_sum(float v) {
    #pragma unroll
    for (int o = 16; o > 0; o >>= 1) v += __shfl_xor_sync(0xFFFFFFFFu, v, o);
    return v;
}

__global__ void softmax_k(float* __restrict__ attn) {
    __shared__ float red[8];
    float4* row = (float4*)(attn + (size_t)blockIdx.x * LK);  // 512 float4
    const int tid = threadIdx.x;

    float4 v0 = row[tid];
    float4 v1 = row[tid + 256];
    float m = fmaxf(fmaxf(fmaxf(v0.x, v0.y), fmaxf(v0.z, v0.w)),
                    fmaxf(fmaxf(v1.x, v1.y), fmaxf(v1.z, v1.w)));
    m = warp_max(m);
    if ((tid & 31) == 0) red[tid >> 5] = m;
    __syncthreads();
    if (tid < 32) {
        float t = (tid < 8) ? red[tid] : -1e30f;
        t = warp_max(t);
        if (tid == 0) red[0] = t;
    }
    __syncthreads();
    m = red[0];
    __syncthreads();

    v0.x = __expf(v0.x - m); v0.y = __expf(v0.y - m);
    v0.z = __expf(v0.z - m); v0.w = __expf(v0.w - m);
    v1.x = __expf(v1.x - m); v1.y = __expf(v1.y - m);
    v1.z = __expf(v1.z - m); v1.w = __expf(v1.w - m);
    float s = (v0.x + v0.y) + (v0.z + v0.w) + (v1.x + v1.y) + (v1.z + v1.w);
    s = warp_sum(s);
    if ((tid & 31) == 0) red[tid >> 5] = s;
    __syncthreads();
    if (tid < 32) {
        float t = (tid < 8) ? red[tid] : 0.f;
        t = warp_sum(t);
        if (tid == 0) red[0] = t;
    }
    __syncthreads();
    const float inv = 1.0f / red[0];
    v0.x *= inv; v0.y *= inv; v0.z *= inv; v0.w *= inv;
    v1.x *= inv; v1.y *= inv; v1.z *= inv; v1.w *= inv;
    row[tid] = v0;
    row[tid + 256] = v1;
}

// ---------------------------------------------------------------------------
// kernel_launch
// ---------------------------------------------------------------------------
extern "C" void kernel_launch(void* const* d_in, const int* in_sizes, int n_in,
                              void* d_out, int out_size) {
    const float* query = (const float*)d_in[0];
    const float* key   = (const float*)d_in[1];
    const float* value = (const float*)d_in[2];
    const float* Wq = (const float*)d_in[3];
    const float* bq = (const float*)d_in[4];
    const float* Wk = (const float*)d_in[5];
    const float* bk = (const float*)d_in[6];
    const float* Wv = (const float*)d_in[7];
    const float* bv = (const float*)d_in[8];
    const float* Wo = (const float*)d_in[9];
    const float* bo = (const float*)d_in[10];

    float* out  = (float*)d_out;
    float* attn = out + (size_t)BB * LQ * QD;

    float *qs, *ks, *vs, *cs;
    cudaGetSymbolAddress((void**)&qs, g_q);
    cudaGetSymbolAddress((void**)&ks, g_k);
    cudaGetSymbolAddress((void**)&vs, g_v);
    cudaGetSymbolAddress((void**)&cs, g_ctx);

    const int SMEM_GEMM = 2 * 128 * ASTR * 4 * 2;                  // 73728 B
    const int SMEM_CTX  = 2 * 128 * ASTR * 4 + 2 * 32 * VSTR * 4;  // 54272 B
    cudaFuncSetAttribute(gemm_nt_tc, cudaFuncAttributeMaxDynamicSharedMemorySize, SMEM_GEMM);
    cudaFuncSetAttribute(scores_tc,  cudaFuncAttributeMaxDynamicSharedMemorySize, SMEM_GEMM);
    cudaFuncSetAttribute(context_tc, cudaFuncAttributeMaxDynamicSharedMemorySize, SMEM_CTX);

    // Projections (TF32 tensor core, cp.async pipelined)
    gemm_nt_tc<<<dim3(QD / 128, (BB * LQ) / 128), 256, SMEM_GEMM>>>(query, Wq, bq, qs, BB * LQ, QD, QD);
    gemm_nt_tc<<<dim3(QD / 128, (BB * LK) / 128), 256, SMEM_GEMM>>>(key,   Wk, bk, ks, BB * LK, QD, KD);
    gemm_nt_tc<<<dim3(QD / 128, (BB * LK) / 128), 256, SMEM_GEMM>>>(value, Wv, bv, vs, BB * LK, QD, KD);

    // Attention
    scores_tc<<<dim3(LK / 128, LQ / 128, BB * NH), 256, SMEM_GEMM>>>(qs, ks, attn);
    softmax_k<<<BB * NH * LQ, 256>>>(attn);
    context_tc<<<dim3(LQ / 128, BB * NH), 256, SMEM_CTX>>>(attn, vs, cs);

    // Output projection
    gemm_nt_tc<<<dim3(QD / 128, (BB * LQ) / 128), 256, SMEM_GEMM>>>(cs, Wo, bo, out, BB * LQ, QD, QD);
}

// round 4
// speedup vs baseline: 2.8593x; 1.0337x over previous
#include <cuda_runtime.h>
#include <cstdint>
#include <cstddef>

// Problem constants
#define BB   4
#define LQ   1024
#define LK   2048
#define NH   16
#define HD   64
#define QD   1024
#define KD   512
#define SCALE 0.125f   // 1/sqrt(64)

#define NTILES (LK / 128)        // 16 k-tiles per row
#define TOTROWS (BB * NH * LQ)   // 65536 attention rows

// Scratch (device globals: allocation-free per harness rules).
__device__ float g_q  [(size_t)BB * LQ * QD];   // 16 MB
__device__ float g_k  [(size_t)BB * LK * QD];   // 32 MB
__device__ float g_v  [(size_t)BB * LK * QD];   // 32 MB
__device__ float g_ctx[(size_t)BB * LQ * QD];   // 16 MB
__device__ float g_pm [(size_t)TOTROWS * NTILES];  // 4 MB  per-tile row max
__device__ float g_ps [(size_t)TOTROWS * NTILES];  // 4 MB  per-tile row sumexp
__device__ float2 g_stat[(size_t)TOTROWS];         // 512 KB (m, 1/l)

// ---------------------------------------------------------------------------
// Helpers
// ---------------------------------------------------------------------------
__device__ __forceinline__ uint32_t f2tf(float f) {
    uint32_t r;
    asm("cvt.rna.tf32.f32 %0, %1;" : "=r"(r) : "f"(f));
    return r;
}

__device__ __forceinline__ void mma_tf32(float c[4],
                                         const uint32_t a[4],
                                         const uint32_t b[2]) {
    asm volatile(
        "mma.sync.aligned.m16n8k8.row.col.f32.tf32.tf32.f32 "
        "{%0,%1,%2,%3}, {%4,%5,%6,%7}, {%8,%9}, {%0,%1,%2,%3};\n"
        : "+f"(c[0]), "+f"(c[1]), "+f"(c[2]), "+f"(c[3])
        : "r"(a[0]), "r"(a[1]), "r"(a[2]), "r"(a[3]),
          "r"(b[0]), "r"(b[1]));
}

__device__ __forceinline__ uint32_t smem_u32(const void* p) {
    uint32_t r;
    asm("{ .reg .u64 t; cvta.to.shared.u64 t, %1; cvt.u32.u64 %0, t; }"
        : "=r"(r) : "l"(p));
    return r;
}

__device__ __forceinline__ void cp16(void* dst_smem, const void* src_gmem) {
    asm volatile("cp.async.cg.shared.global [%0], [%1], 16;\n"
                 :: "r"(smem_u32(dst_smem)), "l"(src_gmem));
}
__device__ __forceinline__ void cp_commit() {
    asm volatile("cp.async.commit_group;\n");
}
template <int N>
__device__ __forceinline__ void cp_wait() {
    asm volatile("cp.async.wait_group %0;\n" :: "n"(N));
}

// smem strides (floats)
#define ASTR 36   // 32 k + 4 pad
#define VSTR 68   // 64 n + 4 pad

// ===========================================================================
// GEMM NT:  C[M,N] = A[M,K] @ W[N,K]^T + bias[N]
// Block 128x128, BK=32, 256 threads = 8 warps (4x2), warp tile 32x64.
// ===========================================================================
__global__ __launch_bounds__(256, 2)
void gemm_nt_tc(const float* __restrict__ A, const float* __restrict__ W,
                const float* __restrict__ bias, float* __restrict__ C,
                int M, int N, int K) {
    extern __shared__ float sm[];
    float* As = sm;                    // [2][128][ASTR]
    float* Bs = sm + 2 * 128 * ASTR;   // [2][128][ASTR]

    const int tid = threadIdx.x;
    const int bm = blockIdx.y * 128;
    const int bn = blockIdx.x * 128;
    const int w = tid >> 5, lane = tid & 31;
    const int g = lane >> 2, tig = lane & 3;
    const int wm = (w & 3) * 32, wn = (w >> 2) * 64;

    float acc[2][8][4] = {};
    const int S = K >> 5;

    auto prefetch = [&](int s, int buf) {
        const int k0 = s * 32;
        float* Ab = As + buf * 128 * ASTR;
        float* Bb = Bs + buf * 128 * ASTR;
        #pragma unroll
        for (int i = 0; i < 4; i++) {
            int ch = tid + i * 256;
            int row = ch >> 3;
            int kc = (ch & 7) * 4;
            cp16(Ab + row * ASTR + kc, A + (size_t)(bm + row) * K + k0 + kc);
            cp16(Bb + row * ASTR + kc, W + (size_t)(bn + row) * K + k0 + kc);
        }
    };

    prefetch(0, 0);
    cp_commit();

    for (int s = 0; s < S; s++) {
        const int buf = s & 1;
        if (s + 1 < S) { prefetch(s + 1, buf ^ 1); cp_commit(); cp_wait<1>(); }
        else           { cp_wait<0>(); }
        __syncthreads();

        const float* Ab = As + buf * 128 * ASTR;
        const float* Bb = Bs + buf * 128 * ASTR;
        #pragma unroll
        for (int kk = 0; kk < 32; kk += 8) {
            uint32_t af[2][4], bf[8][2];
            #pragma unroll
            for (int mf = 0; mf < 2; mf++) {
                int mb = wm + mf * 16;
                af[mf][0] = f2tf(Ab[(mb + g) * ASTR + kk + tig]);
                af[mf][1] = f2tf(Ab[(mb + g + 8) * ASTR + kk + tig]);
                af[mf][2] = f2tf(Ab[(mb + g) * ASTR + kk + tig + 4]);
                af[mf][3] = f2tf(Ab[(mb + g + 8) * ASTR + kk + tig + 4]);
            }
            #pragma unroll
            for (int nf = 0; nf < 8; nf++) {
                int nb = wn + nf * 8 + g;
                bf[nf][0] = f2tf(Bb[nb * ASTR + kk + tig]);
                bf[nf][1] = f2tf(Bb[nb * ASTR + kk + tig + 4]);
            }
            #pragma unroll
            for (int mf = 0; mf < 2; mf++)
                #pragma unroll
                for (int nf = 0; nf < 8; nf++)
                    mma_tf32(acc[mf][nf], af[mf], bf[nf]);
        }
        __syncthreads();
    }

    #pragma unroll
    for (int mf = 0; mf < 2; mf++) {
        #pragma unroll
        for (int nf = 0; nf < 8; nf++) {
            int row = bm + wm + mf * 16 + g;
            int col = bn + wn + nf * 8 + tig * 2;
            float b0 = __ldg(bias + col);
            float b1 = __ldg(bias + col + 1);
            *(float2*)(C + (size_t)row * N + col) =
                make_float2(acc[mf][nf][0] + b0, acc[mf][nf][1] + b1);
            *(float2*)(C + (size_t)(row + 8) * N + col) =
                make_float2(acc[mf][nf][2] + b0, acc[mf][nf][3] + b1);
        }
    }
}

// ===========================================================================
// Scores + per-tile softmax stats.
// attn_raw[bh,m,n] = SCALE * q.k ; also writes per-(row, k-tile) max & sumexp.
// Grid: (NTILES, LQ/128, BB*NH)
// ===========================================================================
__global__ __launch_bounds__(256, 2)
void scores_tc(const float* __restrict__ qm, const float* __restrict__ km,
               float* __restrict__ attn, float* __restrict__ pm,
               float* __restrict__ ps) {
    extern __shared__ float sm[];
    float* As = sm;
    float* Bs = sm + 2 * 128 * ASTR;

    const int bh = blockIdx.z;
    const int b = bh >> 4, h = bh & 15;
    const float* Aq = qm + (size_t)b * LQ * QD + h * HD;
    const float* Ak = km + (size_t)b * LK * QD + h * HD;
    float* Cp = attn + (size_t)bh * LQ * LK;

    const int tid = threadIdx.x;
    const int bm = blockIdx.y * 128;
    const int bn = blockIdx.x * 128;
    const int w = tid >> 5, lane = tid & 31;
    const int g = lane >> 2, tig = lane & 3;
    const int wm = (w & 3) * 32, wn = (w >> 2) * 64;
    const int wcol = w >> 2;

    float acc[2][8][4] = {};

    auto prefetch = [&](int s, int buf) {
        const int k0 = s * 32;
        float* Ab = As + buf * 128 * ASTR;
        float* Bb = Bs + buf * 128 * ASTR;
        #pragma unroll
        for (int i = 0; i < 4; i++) {
            int ch = tid + i * 256;
            int row = ch >> 3;
            int kc = (ch & 7) * 4;
            cp16(Ab + row * ASTR + kc, Aq + (size_t)(bm + row) * QD + k0 + kc);
            cp16(Bb + row * ASTR + kc, Ak + (size_t)(bn + row) * QD + k0 + kc);
        }
    };

    prefetch(0, 0);
    cp_commit();

    #pragma unroll
    for (int s = 0; s < 2; s++) {
        const int buf = s & 1;
        if (s + 1 < 2) { prefetch(s + 1, buf ^ 1); cp_commit(); cp_wait<1>(); }
        else           { cp_wait<0>(); }
        __syncthreads();

        const float* Ab = As + buf * 128 * ASTR;
        const float* Bb = Bs + buf * 128 * ASTR;
        #pragma unroll
        for (int kk = 0; kk < 32; kk += 8) {
            uint32_t af[2][4], bf[8][2];
            #pragma unroll
            for (int mf = 0; mf < 2; mf++) {
                int mb = wm + mf * 16;
                af[mf][0] = f2tf(Ab[(mb + g) * ASTR + kk + tig]);
                af[mf][1] = f2tf(Ab[(mb + g + 8) * ASTR + kk + tig]);
                af[mf][2] = f2tf(Ab[(mb + g) * ASTR + kk + tig + 4]);
                af[mf][3] = f2tf(Ab[(mb + g + 8) * ASTR + kk + tig + 4]);
            }
            #pragma unroll
            for (int nf = 0; nf < 8; nf++) {
                int nb = wn + nf * 8 + g;
                bf[nf][0] = f2tf(Bb[nb * ASTR + kk + tig]);
                bf[nf][1] = f2tf(Bb[nb * ASTR + kk + tig + 4]);
            }
            #pragma unroll
            for (int mf = 0; mf < 2; mf++)
                #pragma unroll
                for (int nf = 0; nf < 8; nf++)
                    mma_tf32(acc[mf][nf], af[mf], bf[nf]);
        }
        __syncthreads();
    }

    // Scale accumulators once
    #pragma unroll
    for (int mf = 0; mf < 2; mf++)
        #pragma unroll
        for (int nf = 0; nf < 8; nf++)
            #pragma unroll
            for (int q = 0; q < 4; q++) acc[mf][nf][q] *= SCALE;

    // Write scaled raw scores
    #pragma unroll
    for (int mf = 0; mf < 2; mf++) {
        #pragma unroll
        for (int nf = 0; nf < 8; nf++) {
            int row = bm + wm + mf * 16 + g;
            int col = bn + wn + nf * 8 + tig * 2;
            *(float2*)(Cp + (size_t)row * LK + col) =
                make_float2(acc[mf][nf][0], acc[mf][nf][1]);
            *(float2*)(Cp + (size_t)(row + 8) * LK + col) =
                make_float2(acc[mf][nf][2], acc[mf][nf][3]);
        }
    }

    // --- per-row stats over this 128-col tile ---
    // smem reuse for cross-warp-column exchange: [wcol][row] for m and s
    float* sm_m = sm;          // [2][128]
    float* sm_s = sm + 256;    // [2][128]

    #pragma unroll
    for (int mf = 0; mf < 2; mf++) {
        float mA = -1e30f, mB = -1e30f;
        #pragma unroll
        for (int nf = 0; nf < 8; nf++) {
            mA = fmaxf(mA, fmaxf(acc[mf][nf][0], acc[mf][nf][1]));
            mB = fmaxf(mB, fmaxf(acc[mf][nf][2], acc[mf][nf][3]));
        }
        // reduce across tig (quad lanes)
        mA = fmaxf(mA, __shfl_xor_sync(0xFFFFFFFFu, mA, 1));
        mA = fmaxf(mA, __shfl_xor_sync(0xFFFFFFFFu, mA, 2));
        mB = fmaxf(mB, __shfl_xor_sync(0xFFFFFFFFu, mB, 1));
        mB = fmaxf(mB, __shfl_xor_sync(0xFFFFFFFFu, mB, 2));

        float sA = 0.f, sB = 0.f;
        #pragma unroll
        for (int nf = 0; nf < 8; nf++) {
            sA += __expf(acc[mf][nf][0] - mA) + __expf(acc[mf][nf][1] - mA);
            sB += __expf(acc[mf][nf][2] - mB) + __expf(acc[mf][nf][3] - mB);
        }
        sA += __shfl_xor_sync(0xFFFFFFFFu, sA, 1);
        sA += __shfl_xor_sync(0xFFFFFFFFu, sA, 2);
        sB += __shfl_xor_sync(0xFFFFFFFFu, sB, 1);
        sB += __shfl_xor_sync(0xFFFFFFFFu, sB, 2);

        if (tig == 0) {
            int rA = wm + mf * 16 + g;
            sm_m[wcol * 128 + rA] = mA; sm_s[wcol * 128 + rA] = sA;
            sm_m[wcol * 128 + rA + 8] = mB; sm_s[wcol * 128 + rA + 8] = sB;
        }
    }
    __syncthreads();

    if (tid < 128) {
        float m0 = sm_m[tid], m1 = sm_m[128 + tid];
        float s0 = sm_s[tid], s1 = sm_s[128 + tid];
        float m = fmaxf(m0, m1);
        float s = s0 * __expf(m0 - m) + s1 * __expf(m1 - m);
        size_t row = (size_t)bh * LQ + bm + tid;
        pm[row * NTILES + blockIdx.x] = m;
        ps[row * NTILES + blockIdx.x] = s;
    }
}

// ===========================================================================
// Combine per-tile stats -> per-row (max, 1/sumexp)
// ===========================================================================
__global__ void reduce_stats_k(const float* __restrict__ pm,
                               const float* __restrict__ ps,
                               float2* __restrict__ stat) {
    int row = blockIdx.x * 256 + threadIdx.x;
    if (row >= TOTROWS) return;
    const float* pmr = pm + (size_t)row * NTILES;
    const float* psr = ps + (size_t)row * NTILES;
    float m = -1e30f;
    #pragma unroll
    for (int t = 0; t < NTILES; t++) m = fmaxf(m, pmr[t]);
    float l = 0.f;
    #pragma unroll
    for (int t = 0; t < NTILES; t++) l += psr[t] * __expf(pmr[t] - m);
    stat[row] = make_float2(m, 1.0f / l);
}

// ===========================================================================
// Fused softmax-normalize + context GEMM.
// Reads raw scaled scores from attn (in place), writes normalized p back,
// and computes ctx = P @ V.  Grid: (LQ/128, BB*NH)
// ===========================================================================
__global__ __launch_bounds__(256, 2)
void ctx_fused_tc(float* __restrict__ attn, const float* __restrict__ vm,
                  float* __restrict__ ctx, const float2* __restrict__ stat) {
    extern __shared__ float sm[];
    float* As = sm;                    // [2][128][ASTR]  raw -> tf32(p)
    float* Vs = sm + 2 * 128 * ASTR;   // [2][32][VSTR]
    __shared__ float2 st[128];

    const int bh = blockIdx.y;
    const int b = bh >> 4, h = bh & 15;
    float* Ap = attn + (size_t)bh * LQ * LK;
    const float* Vp = vm + (size_t)b * LK * QD + h * HD;

    const int tid = threadIdx.x;
    const int bm = blockIdx.x * 128;
    const int w = tid >> 5, lane = tid & 31;
    const int g = lane >> 2, tig = lane & 3;
    const int wm = (w & 3) * 32, wn = (w >> 2) * 32;

    if (tid < 128) st[tid] = stat[(size_t)bh * LQ + bm + tid];

    float acc[2][4][4] = {};

    auto prefetch = [&](int s, int buf) {
        const int k0 = s * 32;
        float* Ab = As + buf * 128 * ASTR;
        float* Vb = Vs + buf * 32 * VSTR;
        #pragma unroll
        for (int i = 0; i < 4; i++) {
            int ch = tid + i * 256;
            int row = ch >> 3;
            int kc = (ch & 7) * 4;
            cp16(Ab + row * ASTR + kc, Ap + (size_t)(bm + row) * LK + k0 + kc);
        }
        #pragma unroll
        for (int i = 0; i < 2; i++) {
            int ch = tid + i * 256;
            int kr = ch >> 4;
            int nc = (ch & 15) * 4;
            cp16(Vb + kr * VSTR + nc, Vp + (size_t)(k0 + kr) * QD + nc);
        }
    };

    prefetch(0, 0);
    cp_commit();

    const int S = LK / 32;
    for (int s = 0; s < S; s++) {
        const int buf = s & 1;
        if (s + 1 < S) { prefetch(s + 1, buf ^ 1); cp_commit(); cp_wait<1>(); }
        else           { cp_wait<0>(); }
        __syncthreads();

        float* Ab = As + buf * 128 * ASTR;
        const float* Vb = Vs + buf * 32 * VSTR;
        const int k0 = s * 32;

        // Normalize: p = exp(s - m) * invl ; write p to gmem, tf32(p) to smem.
        #pragma unroll
        for (int i = 0; i < 4; i++) {
            int ch = tid + i * 256;
            int row = ch >> 3;
            int kc = (ch & 7) * 4;
            float2 ms = st[row];
            float4 v = *(float4*)(Ab + row * ASTR + kc);
            v.x = __expf(v.x - ms.x) * ms.y;
            v.y = __expf(v.y - ms.x) * ms.y;
            v.z = __expf(v.z - ms.x) * ms.y;
            v.w = __expf(v.w - ms.x) * ms.y;
            *(float4*)(Ap + (size_t)(bm + row) * LK + k0 + kc) = v;
            uint32_t* Au = (uint32_t*)(Ab + row * ASTR + kc);
            Au[0] = f2tf(v.x); Au[1] = f2tf(v.y);
            Au[2] = f2tf(v.z); Au[3] = f2tf(v.w);
        }
        __syncthreads();

        const uint32_t* Abu = (const uint32_t*)Ab;
        #pragma unroll
        for (int kk = 0; kk < 32; kk += 8) {
            uint32_t af[2][4], bf[4][2];
            #pragma unroll
            for (int mf = 0; mf < 2; mf++) {
                int mb = wm + mf * 16;
                af[mf][0] = Abu[(mb + g) * ASTR + kk + tig];
                af[mf][1] = Abu[(mb + g + 8) * ASTR + kk + tig];
                af[mf][2] = Abu[(mb + g) * ASTR + kk + tig + 4];
                af[mf][3] = Abu[(mb + g + 8) * ASTR + kk + tig + 4];
            }
            #pragma unroll
            for (int nf = 0; nf < 4; nf++) {
                int nb = wn + nf * 8 + g;
                bf[nf][0] = f2tf(Vb[(kk + tig) * VSTR + nb]);
                bf[nf][1] = f2tf(Vb[(kk + tig + 4) * VSTR + nb]);
            }
            #pragma unroll
            for (int mf = 0; mf < 2; mf++)
                #pragma unroll
                for (int nf = 0; nf < 4; nf++)
                    mma_tf32(acc[mf][nf], af[mf], bf[nf]);
        }
        __syncthreads();
    }

    #pragma unroll
    for (int mf = 0; mf < 2; mf++) {
        #pragma unroll
        for (int nf = 0; nf < 4; nf++) {
            int row = bm + wm + mf * 16 + g;
            int col = h * HD + wn + nf * 8 + tig * 2;
            *(float2*)(ctx + (size_t)(b * LQ + row) * QD + col) =
                make_float2(acc[mf][nf][0], acc[mf][nf][1]);
            *(float2*)(ctx + (size_t)(b * LQ + row + 8) * QD + col) =
                make_float2(acc[mf][nf][2], acc[mf][nf][3]);
        }
    }
}

// ---------------------------------------------------------------------------
// kernel_launch
// ---------------------------------------------------------------------------
extern "C" void kernel_launch(void* const* d_in, const int* in_sizes, int n_in,
                              void* d_out, int out_size) {
    const float* query = (const float*)d_in[0];
    const float* key   = (const float*)d_in[1];
    const float* value = (const float*)d_in[2];
    const float* Wq = (const float*)d_in[3];
    const float* bq = (const float*)d_in[4];
    const float* Wk = (const float*)d_in[5];
    const float* bk = (const float*)d_in[6];
    const float* Wv = (const float*)d_in[7];
    const float* bv = (const float*)d_in[8];
    const float* Wo = (const float*)d_in[9];
    const float* bo = (const float*)d_in[10];

    float* out  = (float*)d_out;
    float* attn = out + (size_t)BB * LQ * QD;

    float *qs, *ks, *vs, *cs, *pm, *ps;
    float2* stat;
    cudaGetSymbolAddress((void**)&qs, g_q);
    cudaGetSymbolAddress((void**)&ks, g_k);
    cudaGetSymbolAddress((void**)&vs, g_v);
    cudaGetSymbolAddress((void**)&cs, g_ctx);
    cudaGetSymbolAddress((void**)&pm, g_pm);
    cudaGetSymbolAddress((void**)&ps, g_ps);
    cudaGetSymbolAddress((void**)&stat, g_stat);

    const int SMEM_GEMM = 2 * 128 * ASTR * 4 * 2;                  // 73728 B
    const int SMEM_CTX  = 2 * 128 * ASTR * 4 + 2 * 32 * VSTR * 4;  // 54272 B
    cudaFuncSetAttribute(gemm_nt_tc, cudaFuncAttributeMaxDynamicSharedMemorySize, SMEM_GEMM);
    cudaFuncSetAttribute(scores_tc,  cudaFuncAttributeMaxDynamicSharedMemorySize, SMEM_GEMM);
    cudaFuncSetAttribute(ctx_fused_tc, cudaFuncAttributeMaxDynamicSharedMemorySize, SMEM_CTX);

    // Projections
    gemm_nt_tc<<<dim3(QD / 128, (BB * LQ) / 128), 256, SMEM_GEMM>>>(query, Wq, bq, qs, BB * LQ, QD, QD);
    gemm_nt_tc<<<dim3(QD / 128, (BB * LK) / 128), 256, SMEM_GEMM>>>(key,   Wk, bk, ks, BB * LK, QD, KD);
    gemm_nt_tc<<<dim3(QD / 128, (BB * LK) / 128), 256, SMEM_GEMM>>>(value, Wv, bv, vs, BB * LK, QD, KD);

    // Scores (+ per-tile softmax stats), stat reduction, fused normalize+context
    scores_tc<<<dim3(NTILES, LQ / 128, BB * NH), 256, SMEM_GEMM>>>(qs, ks, attn, pm, ps);
    reduce_stats_k<<<TOTROWS / 256, 256>>>(pm, ps, stat);
    ctx_fused_tc<<<dim3(LQ / 128, BB * NH), 256, SMEM_CTX>>>(attn, vs, cs, stat);

    // Output projection
    gemm_nt_tc<<<dim3(QD / 128, (BB * LQ) / 128), 256, SMEM_GEMM>>>(cs, Wo, bo, out, BB * LQ, QD, QD);
}

// round 5
// speedup vs baseline: 3.6636x; 1.2813x over previous
#include <cuda_runtime.h>
#include <cuda_fp16.h>
#include <cstdint>
#include <cstddef>

// Problem constants
#define BB   4
#define LQ   1024
#define LK   2048
#define NH   16
#define HD   64
#define QD   1024
#define KD   512
#define SCALE 0.125f   // 1/sqrt(64)

#define NTILES (LK / 128)        // 16 k-tiles per row
#define TOTROWS (BB * NH * LQ)   // 65536 attention rows

// ---------------------------------------------------------------------------
// Scratch (device globals: allocation-free per harness rules).
// ---------------------------------------------------------------------------
__device__ __half g_inq [(size_t)BB * LQ * QD];      // 8 MB  query (half)
__device__ __half g_ink [(size_t)BB * LK * KD];      // 8 MB  key (half)
__device__ __half g_inv [(size_t)BB * LK * KD];      // 8 MB  value (half)
__device__ __half g_wh  [(size_t)3 * 1024 * 1024];   // 6 MB  Wq|Wk|Wv|Wo (half)
__device__ __half g_qh  [(size_t)BB * LQ * QD];      // 8 MB  q proj (half)
__device__ __half g_kh  [(size_t)BB * LK * QD];      // 16 MB k proj (half)
__device__ float  g_v   [(size_t)BB * LK * QD];      // 32 MB v proj (fp32)
__device__ __half g_ctxh[(size_t)BB * LQ * QD];      // 8 MB  context (half)
__device__ float  g_pm  [(size_t)TOTROWS * NTILES];  // 4 MB
__device__ float  g_ps  [(size_t)TOTROWS * NTILES];  // 4 MB
__device__ float2 g_stat[(size_t)TOTROWS];           // 512 KB

// weight offsets in g_wh (halves)
#define WQ_OFF 0
#define WK_OFF (1024 * 1024)
#define WV_OFF (1024 * 1024 + 512 * 1024)
#define WO_OFF (2 * 1024 * 1024)

// ---------------------------------------------------------------------------
// Helpers
// ---------------------------------------------------------------------------
__device__ __forceinline__ void mma_f16(float c[4],
                                        const uint32_t a[4],
                                        const uint32_t b[2]) {
    asm volatile(
        "mma.sync.aligned.m16n8k16.row.col.f32.f16.f16.f32 "
        "{%0,%1,%2,%3}, {%4,%5,%6,%7}, {%8,%9}, {%0,%1,%2,%3};\n"
        : "+f"(c[0]), "+f"(c[1]), "+f"(c[2]), "+f"(c[3])
        : "r"(a[0]), "r"(a[1]), "r"(a[2]), "r"(a[3]),
          "r"(b[0]), "r"(b[1]));
}

__device__ __forceinline__ uint32_t smem_u32(const void* p) {
    uint32_t r;
    asm("{ .reg .u64 t; cvta.to.shared.u64 t, %1; cvt.u32.u64 %0, t; }"
        : "=r"(r) : "l"(p));
    return r;
}
__device__ __forceinline__ void cp16(void* dst_smem, const void* src_gmem) {
    asm volatile("cp.async.cg.shared.global [%0], [%1], 16;\n"
                 :: "r"(smem_u32(dst_smem)), "l"(src_gmem));
}
__device__ __forceinline__ void cp_commit() {
    asm volatile("cp.async.commit_group;\n");
}
template <int N>
__device__ __forceinline__ void cp_wait() {
    asm volatile("cp.async.wait_group %0;\n" :: "n"(N));
}

__device__ __forceinline__ uint32_t lds32h(const __half* p) {
    return *(const uint32_t*)p;
}
__device__ __forceinline__ uint32_t packh2(float lo, float hi) {
    __half2 h = __floats2half2_rn(lo, hi);
    return *(uint32_t*)&h;
}

// smem strides
#define STRH   40   // half stride for BK=32 tiles (conflict-free)
#define STRH64 72   // half stride for K=64 tiles (scores)
#define AFSTR  36   // float stride for raw-score staging
#define VSTR   68   // float stride for V tiles

// ---------------------------------------------------------------------------
// fp32 -> fp16 conversion (grid-stride over float4)
// ---------------------------------------------------------------------------
__global__ void conv_f2h(const float4* __restrict__ src, __half2* __restrict__ dst,
                         int n4) {
    int i = blockIdx.x * 256 + threadIdx.x;
    if (i < n4) {
        float4 v = src[i];
        dst[2 * i]     = __floats2half2_rn(v.x, v.y);
        dst[2 * i + 1] = __floats2half2_rn(v.z, v.w);
    }
}

// ===========================================================================
// GEMM NT (fp16 tensor core):  C[M,N] = A[M,K] @ W[N,K]^T + bias[N]
// A, W half; C half or float (template). Block 128x128, BK=32, 8 warps (4x2),
// warp tile 32x64.  Dyn smem: (As+Bs)[2][128][STRH] halves = 40960 B.
// ===========================================================================
template <bool HALF_OUT>
__global__ __launch_bounds__(256, 2)
void gemm_nt_h(const __half* __restrict__ A, const __half* __restrict__ W,
               const float* __restrict__ bias, void* __restrict__ Cv,
               int M, int N, int K) {
    extern __shared__ __half smh[];
    __half* As = smh;                    // [2][128][STRH]
    __half* Bs = smh + 2 * 128 * STRH;   // [2][128][STRH]

    const int tid = threadIdx.x;
    const int bm = blockIdx.y * 128;
    const int bn = blockIdx.x * 128;
    const int w = tid >> 5, lane = tid & 31;
    const int g = lane >> 2, tig = lane & 3;
    const int wm = (w & 3) * 32, wn = (w >> 2) * 64;

    float acc[2][8][4] = {};
    const int S = K >> 5;

    auto prefetch = [&](int s, int buf) {
        const int k0 = s * 32;
        __half* Ab = As + buf * 128 * STRH;
        __half* Bb = Bs + buf * 128 * STRH;
        #pragma unroll
        for (int i = 0; i < 2; i++) {
            int ch = tid + i * 256;       // 0..511
            int row = ch >> 2;            // 0..127
            int kc = (ch & 3) * 8;        // 0,8,16,24 halves
            cp16(Ab + row * STRH + kc, A + (size_t)(bm + row) * K + k0 + kc);
            cp16(Bb + row * STRH + kc, W + (size_t)(bn + row) * K + k0 + kc);
        }
    };

    prefetch(0, 0);
    cp_commit();

    for (int s = 0; s < S; s++) {
        const int buf = s & 1;
        if (s + 1 < S) { prefetch(s + 1, buf ^ 1); cp_commit(); cp_wait<1>(); }
        else           { cp_wait<0>(); }
        __syncthreads();

        const __half* Ab = As + buf * 128 * STRH;
        const __half* Bb = Bs + buf * 128 * STRH;
        #pragma unroll
        for (int kk = 0; kk < 32; kk += 16) {
            uint32_t af[2][4], bf[8][2];
            #pragma unroll
            for (int mf = 0; mf < 2; mf++) {
                int mb = wm + mf * 16;
                af[mf][0] = lds32h(Ab + (mb + g) * STRH + kk + 2 * tig);
                af[mf][1] = lds32h(Ab + (mb + g + 8) * STRH + kk + 2 * tig);
                af[mf][2] = lds32h(Ab + (mb + g) * STRH + kk + 2 * tig + 8);
                af[mf][3] = lds32h(Ab + (mb + g + 8) * STRH + kk + 2 * tig + 8);
            }
            #pragma unroll
            for (int nf = 0; nf < 8; nf++) {
                int nb = wn + nf * 8 + g;
                bf[nf][0] = lds32h(Bb + nb * STRH + kk + 2 * tig);
                bf[nf][1] = lds32h(Bb + nb * STRH + kk + 2 * tig + 8);
            }
            #pragma unroll
            for (int mf = 0; mf < 2; mf++)
                #pragma unroll
                for (int nf = 0; nf < 8; nf++)
                    mma_f16(acc[mf][nf], af[mf], bf[nf]);
        }
        __syncthreads();
    }

    #pragma unroll
    for (int mf = 0; mf < 2; mf++) {
        #pragma unroll
        for (int nf = 0; nf < 8; nf++) {
            int row = bm + wm + mf * 16 + g;
            int col = bn + wn + nf * 8 + tig * 2;
            float b0 = __ldg(bias + col);
            float b1 = __ldg(bias + col + 1);
            float c0 = acc[mf][nf][0] + b0, c1 = acc[mf][nf][1] + b1;
            float c2 = acc[mf][nf][2] + b0, c3 = acc[mf][nf][3] + b1;
            if (HALF_OUT) {
                __half* C = (__half*)Cv;
                *(__half2*)(C + (size_t)row * N + col) = __floats2half2_rn(c0, c1);
                *(__half2*)(C + (size_t)(row + 8) * N + col) = __floats2half2_rn(c2, c3);
            } else {
                float* C = (float*)Cv;
                *(float2*)(C + (size_t)row * N + col) = make_float2(c0, c1);
                *(float2*)(C + (size_t)(row + 8) * N + col) = make_float2(c2, c3);
            }
        }
    }
}

// ===========================================================================
// Scores (fp16): attn_raw = SCALE * q.k, plus per-(row,tile) max & sumexp.
// q,k half; K = HD = 64 in one shot (no slab loop).
// Dyn smem: 2 * 128 * STRH64 halves = 36864 B.
// Grid: (NTILES, LQ/128, BB*NH)
// ===========================================================================
__global__ __launch_bounds__(256, 2)
void scores_h(const __half* __restrict__ qm, const __half* __restrict__ km,
              float* __restrict__ attn, float* __restrict__ pm,
              float* __restrict__ ps) {
    extern __shared__ __half smh[];
    __half* As = smh;                      // [128][STRH64]
    __half* Bs = smh + 128 * STRH64;       // [128][STRH64]

    const int bh = blockIdx.z;
    const int b = bh >> 4, h = bh & 15;
    const __half* Aq = qm + (size_t)b * LQ * QD + h * HD;
    const __half* Ak = km + (size_t)b * LK * QD + h * HD;
    float* Cp = attn + (size_t)bh * LQ * LK;

    const int tid = threadIdx.x;
    const int bm = blockIdx.y * 128;
    const int bn = blockIdx.x * 128;
    const int w = tid >> 5, lane = tid & 31;
    const int g = lane >> 2, tig = lane & 3;
    const int wm = (w & 3) * 32, wn = (w >> 2) * 64;
    const int wcol = w >> 2;

    // one-shot load: 128 rows x 64 halves per matrix = 16 KB each
    #pragma unroll
    for (int i = 0; i < 4; i++) {
        int ch = tid + i * 256;        // 0..1023
        int row = ch >> 3;             // 0..127
        int kc = (ch & 7) * 8;         // 0..56 halves
        cp16(As + row * STRH64 + kc, Aq + (size_t)(bm + row) * QD + kc);
        cp16(Bs + row * STRH64 + kc, Ak + (size_t)(bn + row) * QD + kc);
    }
    cp_commit();
    cp_wait<0>();
    __syncthreads();

    float acc[2][8][4] = {};
    #pragma unroll
    for (int kk = 0; kk < 64; kk += 16) {
        uint32_t af[2][4], bf[8][2];
        #pragma unroll
        for (int mf = 0; mf < 2; mf++) {
            int mb = wm + mf * 16;
            af[mf][0] = lds32h(As + (mb + g) * STRH64 + kk + 2 * tig);
            af[mf][1] = lds32h(As + (mb + g + 8) * STRH64 + kk + 2 * tig);
            af[mf][2] = lds32h(As + (mb + g) * STRH64 + kk + 2 * tig + 8);
            af[mf][3] = lds32h(As + (mb + g + 8) * STRH64 + kk + 2 * tig + 8);
        }
        #pragma unroll
        for (int nf = 0; nf < 8; nf++) {
            int nb = wn + nf * 8 + g;
            bf[nf][0] = lds32h(Bs + nb * STRH64 + kk + 2 * tig);
            bf[nf][1] = lds32h(Bs + nb * STRH64 + kk + 2 * tig + 8);
        }
        #pragma unroll
        for (int mf = 0; mf < 2; mf++)
            #pragma unroll
            for (int nf = 0; nf < 8; nf++)
                mma_f16(acc[mf][nf], af[mf], bf[nf]);
    }

    // scale + write raw scores
    #pragma unroll
    for (int mf = 0; mf < 2; mf++)
        #pragma unroll
        for (int nf = 0; nf < 8; nf++)
            #pragma unroll
            for (int q = 0; q < 4; q++) acc[mf][nf][q] *= SCALE;

    #pragma unroll
    for (int mf = 0; mf < 2; mf++) {
        #pragma unroll
        for (int nf = 0; nf < 8; nf++) {
            int row = bm + wm + mf * 16 + g;
            int col = bn + wn + nf * 8 + tig * 2;
            *(float2*)(Cp + (size_t)row * LK + col) =
                make_float2(acc[mf][nf][0], acc[mf][nf][1]);
            *(float2*)(Cp + (size_t)(row + 8) * LK + col) =
                make_float2(acc[mf][nf][2], acc[mf][nf][3]);
        }
    }

    // per-row stats over this 128-col tile (reuse smem after all MMAs done)
    __syncthreads();
    float* sm_m = (float*)smh;          // [2][128]
    float* sm_s = (float*)smh + 256;    // [2][128]

    #pragma unroll
    for (int mf = 0; mf < 2; mf++) {
        float mA = -1e30f, mB = -1e30f;
        #pragma unroll
        for (int nf = 0; nf < 8; nf++) {
            mA = fmaxf(mA, fmaxf(acc[mf][nf][0], acc[mf][nf][1]));
            mB = fmaxf(mB, fmaxf(acc[mf][nf][2], acc[mf][nf][3]));
        }
        mA = fmaxf(mA, __shfl_xor_sync(0xFFFFFFFFu, mA, 1));
        mA = fmaxf(mA, __shfl_xor_sync(0xFFFFFFFFu, mA, 2));
        mB = fmaxf(mB, __shfl_xor_sync(0xFFFFFFFFu, mB, 1));
        mB = fmaxf(mB, __shfl_xor_sync(0xFFFFFFFFu, mB, 2));

        float sA = 0.f, sB = 0.f;
        #pragma unroll
        for (int nf = 0; nf < 8; nf++) {
            sA += __expf(acc[mf][nf][0] - mA) + __expf(acc[mf][nf][1] - mA);
            sB += __expf(acc[mf][nf][2] - mB) + __expf(acc[mf][nf][3] - mB);
        }
        sA += __shfl_xor_sync(0xFFFFFFFFu, sA, 1);
        sA += __shfl_xor_sync(0xFFFFFFFFu, sA, 2);
        sB += __shfl_xor_sync(0xFFFFFFFFu, sB, 1);
        sB += __shfl_xor_sync(0xFFFFFFFFu, sB, 2);

        if (tig == 0) {
            int rA = wm + mf * 16 + g;
            sm_m[wcol * 128 + rA] = mA; sm_s[wcol * 128 + rA] = sA;
            sm_m[wcol * 128 + rA + 8] = mB; sm_s[wcol * 128 + rA + 8] = sB;
        }
    }
    __syncthreads();

    if (tid < 128) {
        float m0 = sm_m[tid], m1 = sm_m[128 + tid];
        float s0 = sm_s[tid], s1 = sm_s[128 + tid];
        float m = fmaxf(m0, m1);
        float s = s0 * __expf(m0 - m) + s1 * __expf(m1 - m);
        size_t row = (size_t)bh * LQ + bm + tid;
        pm[row * NTILES + blockIdx.x] = m;
        ps[row * NTILES + blockIdx.x] = s;
    }
}

// ===========================================================================
// Combine per-tile stats -> per-row (max, 1/sumexp)
// ===========================================================================
__global__ void reduce_stats_k(const float* __restrict__ pm,
                               const float* __restrict__ ps,
                               float2* __restrict__ stat) {
    int row = blockIdx.x * 256 + threadIdx.x;
    if (row >= TOTROWS) return;
    const float* pmr = pm + (size_t)row * NTILES;
    const float* psr = ps + (size_t)row * NTILES;
    float m = -1e30f;
    #pragma unroll
    for (int t = 0; t < NTILES; t++) m = fmaxf(m, pmr[t]);
    float l = 0.f;
    #pragma unroll
    for (int t = 0; t < NTILES; t++) l += psr[t] * __expf(pmr[t] - m);
    stat[row] = make_float2(m, 1.0f / l);
}

// ===========================================================================
// Fused normalize + context (fp16 MMA).
// Reads raw fp32 scores, writes normalized fp32 attn in place, converts p to
// half for the P@V MMA (V fp32 -> half at fragment load). ctx written half.
// Dyn smem: Af[2][128][36]f + Vf[2][32][68]f + Ph[128][40]h = 64512 B.
// Grid: (LQ/128, BB*NH)
// ===========================================================================
__global__ __launch_bounds__(256, 2)
void ctx_fused_h(float* __restrict__ attn, const float* __restrict__ vm,
                 __half* __restrict__ ctx, const float2* __restrict__ stat) {
    extern __shared__ char smraw[];
    float* Af = (float*)smraw;                         // [2][128][AFSTR]
    float* Vf = (float*)(smraw + 2 * 128 * AFSTR * 4); // [2][32][VSTR]
    __half* Ph = (__half*)(smraw + 2 * 128 * AFSTR * 4 + 2 * 32 * VSTR * 4); // [128][STRH]
    __shared__ float2 st[128];

    const int bh = blockIdx.y;
    const int b = bh >> 4, h = bh & 15;
    float* Ap = attn + (size_t)bh * LQ * LK;
    const float* Vp = vm + (size_t)b * LK * QD + h * HD;

    const int tid = threadIdx.x;
    const int bm = blockIdx.x * 128;
    const int w = tid >> 5, lane = tid & 31;
    const int g = lane >> 2, tig = lane & 3;
    const int wm = (w & 3) * 32, wn = (w >> 2) * 32;

    if (tid < 128) st[tid] = stat[(size_t)bh * LQ + bm + tid];

    float acc[2][4][4] = {};

    auto prefetch = [&](int s, int buf) {
        const int k0 = s * 32;
        float* Ab = Af + buf * 128 * AFSTR;
        float* Vb = Vf + buf * 32 * VSTR;
        #pragma unroll
        for (int i = 0; i < 4; i++) {
            int ch = tid + i * 256;
            int row = ch >> 3;
            int kc = (ch & 7) * 4;
            cp16(Ab + row * AFSTR + kc, Ap + (size_t)(bm + row) * LK + k0 + kc);
        }
        #pragma unroll
        for (int i = 0; i < 2; i++) {
            int ch = tid + i * 256;
            int kr = ch >> 4;
            int nc = (ch & 15) * 4;
            cp16(Vb + kr * VSTR + nc, Vp + (size_t)(k0 + kr) * QD + nc);
        }
    };

    prefetch(0, 0);
    cp_commit();

    const int S = LK / 32;
    for (int s = 0; s < S; s++) {
        const int buf = s & 1;
        if (s + 1 < S) { prefetch(s + 1, buf ^ 1); cp_commit(); cp_wait<1>(); }
        else           { cp_wait<0>(); }
        __syncthreads();

        float* Ab = Af + buf * 128 * AFSTR;
        const float* Vb = Vf + buf * 32 * VSTR;
        const int k0 = s * 32;

        // Normalize: p = exp(s - m) * invl; write fp32 p to gmem, half p to Ph.
        #pragma unroll
        for (int i = 0; i < 4; i++) {
            int ch = tid + i * 256;
            int row = ch >> 3;
            int kc = (ch & 7) * 4;
            float2 ms = st[row];
            float4 v = *(float4*)(Ab + row * AFSTR + kc);
            v.x = __expf(v.x - ms.x) * ms.y;
            v.y = __expf(v.y - ms.x) * ms.y;
            v.z = __expf(v.z - ms.x) * ms.y;
            v.w = __expf(v.w - ms.x) * ms.y;
            *(float4*)(Ap + (size_t)(bm + row) * LK + k0 + kc) = v;
            __half2* ph = (__half2*)(Ph + row * STRH + kc);
            ph[0] = __floats2half2_rn(v.x, v.y);
            ph[1] = __floats2half2_rn(v.z, v.w);
        }
        __syncthreads();

        #pragma unroll
        for (int kk = 0; kk < 32; kk += 16) {
            uint32_t af[2][4], bf[4][2];
            #pragma unroll
            for (int mf = 0; mf < 2; mf++) {
                int mb = wm + mf * 16;
                af[mf][0] = lds32h(Ph + (mb + g) * STRH + kk + 2 * tig);
                af[mf][1] = lds32h(Ph + (mb + g + 8) * STRH + kk + 2 * tig);
                af[mf][2] = lds32h(Ph + (mb + g) * STRH + kk + 2 * tig + 8);
                af[mf][3] = lds32h(Ph + (mb + g + 8) * STRH + kk + 2 * tig + 8);
            }
            #pragma unroll
            for (int nf = 0; nf < 4; nf++) {
                int nb = wn + nf * 8 + g;
                bf[nf][0] = packh2(Vb[(kk + 2 * tig) * VSTR + nb],
                                   Vb[(kk + 2 * tig + 1) * VSTR + nb]);
                bf[nf][1] = packh2(Vb[(kk + 2 * tig + 8) * VSTR + nb],
                                   Vb[(kk + 2 * tig + 9) * VSTR + nb]);
            }
            #pragma unroll
            for (int mf = 0; mf < 2; mf++)
                #pragma unroll
                for (int nf = 0; nf < 4; nf++)
                    mma_f16(acc[mf][nf], af[mf], bf[nf]);
        }
        __syncthreads();
    }

    #pragma unroll
    for (int mf = 0; mf < 2; mf++) {
        #pragma unroll
        for (int nf = 0; nf < 4; nf++) {
            int row = bm + wm + mf * 16 + g;
            int col = h * HD + wn + nf * 8 + tig * 2;
            *(__half2*)(ctx + (size_t)(b * LQ + row) * QD + col) =
                __floats2half2_rn(acc[mf][nf][0], acc[mf][nf][1]);
            *(__half2*)(ctx + (size_t)(b * LQ + row + 8) * QD + col) =
                __floats2half2_rn(acc[mf][nf][2], acc[mf][nf][3]);
        }
    }
}

// ---------------------------------------------------------------------------
// kernel_launch
// ---------------------------------------------------------------------------
extern "C" void kernel_launch(void* const* d_in, const int* in_sizes, int n_in,
                              void* d_out, int out_size) {
    const float* query = (const float*)d_in[0];
    const float* key   = (const float*)d_in[1];
    const float* value = (const float*)d_in[2];
    const float* Wq = (const float*)d_in[3];
    const float* bq = (const float*)d_in[4];
    const float* Wk = (const float*)d_in[5];
    const float* bk = (const float*)d_in[6];
    const float* Wv = (const float*)d_in[7];
    const float* bv = (const float*)d_in[8];
    const float* Wo = (const float*)d_in[9];
    const float* bo = (const float*)d_in[10];

    float* out  = (float*)d_out;
    float* attn = out + (size_t)BB * LQ * QD;

    __half *inq, *ink, *inv, *wh, *qh, *kh, *ctxh;
    float *vs, *pm, *ps;
    float2* stat;
    cudaGetSymbolAddress((void**)&inq, g_inq);
    cudaGetSymbolAddress((void**)&ink, g_ink);
    cudaGetSymbolAddress((void**)&inv, g_inv);
    cudaGetSymbolAddress((void**)&wh,  g_wh);
    cudaGetSymbolAddress((void**)&qh,  g_qh);
    cudaGetSymbolAddress((void**)&kh,  g_kh);
    cudaGetSymbolAddress((void**)&vs,  g_v);
    cudaGetSymbolAddress((void**)&ctxh, g_ctxh);
    cudaGetSymbolAddress((void**)&pm, g_pm);
    cudaGetSymbolAddress((void**)&ps, g_ps);
    cudaGetSymbolAddress((void**)&stat, g_stat);

    const int SMEM_GEMM = 2 * 128 * STRH * 2 * 2;                     // 40960 B
    const int SMEM_SC   = 2 * 128 * STRH64 * 2;                       // 36864 B
    const int SMEM_CTX  = 2 * 128 * AFSTR * 4 + 2 * 32 * VSTR * 4 + 128 * STRH * 2; // 64512 B
    cudaFuncSetAttribute(gemm_nt_h<true>,  cudaFuncAttributeMaxDynamicSharedMemorySize, SMEM_GEMM);
    cudaFuncSetAttribute(gemm_nt_h<false>, cudaFuncAttributeMaxDynamicSharedMemorySize, SMEM_GEMM);
    cudaFuncSetAttribute(scores_h,    cudaFuncAttributeMaxDynamicSharedMemorySize, SMEM_SC);
    cudaFuncSetAttribute(ctx_fused_h, cudaFuncAttributeMaxDynamicSharedMemorySize, SMEM_CTX);

    // fp32 -> fp16 conversions (inputs + weights)
    conv_f2h<<<(BB * LQ * QD / 4 + 255) / 256, 256>>>((const float4*)query, (__half2*)inq, BB * LQ * QD / 4);
    conv_f2h<<<(BB * LK * KD / 4 + 255) / 256, 256>>>((const float4*)key,   (__half2*)ink, BB * LK * KD / 4);
    conv_f2h<<<(BB * LK * KD / 4 + 255) / 256, 256>>>((const float4*)value, (__half2*)inv, BB * LK * KD / 4);
    conv_f2h<<<(QD * QD / 4 + 255) / 256, 256>>>((const float4*)Wq, (__half2*)(wh + WQ_OFF), QD * QD / 4);
    conv_f2h<<<(QD * KD / 4 + 255) / 256, 256>>>((const float4*)Wk, (__half2*)(wh + WK_OFF), QD * KD / 4);
    conv_f2h<<<(QD * KD / 4 + 255) / 256, 256>>>((const float4*)Wv, (__half2*)(wh + WV_OFF), QD * KD / 4);
    conv_f2h<<<(QD * QD / 4 + 255) / 256, 256>>>((const float4*)Wo, (__half2*)(wh + WO_OFF), QD * QD / 4);

    // Projections (fp16 MMA)
    gemm_nt_h<true><<<dim3(QD / 128, (BB * LQ) / 128), 256, SMEM_GEMM>>>(inq, wh + WQ_OFF, bq, qh, BB * LQ, QD, QD);
    gemm_nt_h<true><<<dim3(QD / 128, (BB * LK) / 128), 256, SMEM_GEMM>>>(ink, wh + WK_OFF, bk, kh, BB * LK, QD, KD);
    gemm_nt_h<false><<<dim3(QD / 128, (BB * LK) / 128), 256, SMEM_GEMM>>>(inv, wh + WV_OFF, bv, vs, BB * LK, QD, KD);

    // Scores + stats, stat reduce, fused normalize + context
    scores_h<<<dim3(NTILES, LQ / 128, BB * NH), 256, SMEM_SC>>>(qh, kh, attn, pm, ps);
    reduce_stats_k<<<TOTROWS / 256, 256>>>(pm, ps, stat);
    ctx_fused_h<<<dim3(LQ / 128, BB * NH), 256, SMEM_CTX>>>(attn, vs, ctxh, stat);

    // Output projection (fp32 out + bias)
    gemm_nt_h<false><<<dim3(QD / 128, (BB * LQ) / 128), 256, SMEM_GEMM>>>(ctxh, wh + WO_OFF, bo, out, BB * LQ, QD, QD);
}

// round 6
// speedup vs baseline: 3.7216x; 1.0158x over previous
#include <cuda_runtime.h>
#include <cuda_fp16.h>
#include <cstdint>
#include <cstddef>

// Problem constants
#define BB   4
#define LQ   1024
#define LK   2048
#define NH   16
#define HD   64
#define QD   1024
#define KD   512
#define SCALE 0.125f   // 1/sqrt(64)

#define NSUB (LK / 64)           // 32 col-subtiles of 64 per attention row
#define TOTROWS (BB * NH * LQ)   // 65536 attention rows

// ---------------------------------------------------------------------------
// Scratch (device globals; allocation-free per harness rules).
// ---------------------------------------------------------------------------
__device__ __half g_inq [(size_t)BB * LQ * QD];      // 8 MB
__device__ __half g_ink [(size_t)BB * LK * KD];      // 8 MB
__device__ __half g_inv [(size_t)BB * LK * KD];      // 8 MB
__device__ __half g_wh  [(size_t)3 * 1024 * 1024];   // 6 MB  Wq|Wk|Wv|Wo
__device__ __half g_qh  [(size_t)BB * LQ * QD];      // 8 MB
__device__ __half g_kh  [(size_t)BB * LK * QD];      // 16 MB
__device__ __half g_vh  [(size_t)BB * LK * QD];      // 16 MB
__device__ __half g_ctxh[(size_t)BB * LQ * QD];      // 8 MB
__device__ __half g_ph  [(size_t)BB * NH * LQ * LK]; // 268 MB  p_tile (fp16)
__device__ float  g_pm  [(size_t)TOTROWS * NSUB];    // 8 MB  per-subtile row max
__device__ float  g_ps  [(size_t)TOTROWS * NSUB];    // 8 MB  per-subtile row sumexp
__device__ float  g_fac [(size_t)TOTROWS * NSUB];    // 8 MB  per-subtile factor

// weight offsets in g_wh (halves)
#define WQ_OFF 0
#define WK_OFF (1024 * 1024)
#define WV_OFF (1024 * 1024 + 512 * 1024)
#define WO_OFF (2 * 1024 * 1024)

// ---------------------------------------------------------------------------
// Helpers
// ---------------------------------------------------------------------------
__device__ __forceinline__ void mma_f16(float c[4],
                                        const uint32_t a[4],
                                        const uint32_t b[2]) {
    asm volatile(
        "mma.sync.aligned.m16n8k16.row.col.f32.f16.f16.f32 "
        "{%0,%1,%2,%3}, {%4,%5,%6,%7}, {%8,%9}, {%0,%1,%2,%3};\n"
        : "+f"(c[0]), "+f"(c[1]), "+f"(c[2]), "+f"(c[3])
        : "r"(a[0]), "r"(a[1]), "r"(a[2]), "r"(a[3]),
          "r"(b[0]), "r"(b[1]));
}

__device__ __forceinline__ uint32_t smem_u32(const void* p) {
    uint32_t r;
    asm("{ .reg .u64 t; cvta.to.shared.u64 t, %1; cvt.u32.u64 %0, t; }"
        : "=r"(r) : "l"(p));
    return r;
}
__device__ __forceinline__ void cp16(void* dst_smem, const void* src_gmem) {
    asm volatile("cp.async.cg.shared.global [%0], [%1], 16;\n"
                 :: "r"(smem_u32(dst_smem)), "l"(src_gmem));
}
__device__ __forceinline__ void cp_commit() {
    asm volatile("cp.async.commit_group;\n");
}
template <int N>
__device__ __forceinline__ void cp_wait() {
    asm volatile("cp.async.wait_group %0;\n" :: "n"(N));
}

__device__ __forceinline__ uint32_t lds32h(const __half* p) {
    return *(const uint32_t*)p;
}
__device__ __forceinline__ uint32_t h2scale(uint32_t a, __half2 f) {
    __half2 r = __hmul2(*(__half2*)&a, f);
    return *(uint32_t*)&r;
}

// smem strides (halves / floats)
#define STRH   40   // half stride, BK=32 tiles
#define STRH64 72   // half stride, K=64 tiles (scores)
#define VSTRH  72   // half stride, V tiles [32 k][64 d]

// ---------------------------------------------------------------------------
// fp32 -> fp16 conversion
// ---------------------------------------------------------------------------
__global__ void conv_f2h(const float4* __restrict__ src, __half2* __restrict__ dst,
                         int n4) {
    int i = blockIdx.x * 256 + threadIdx.x;
    if (i < n4) {
        float4 v = src[i];
        dst[2 * i]     = __floats2half2_rn(v.x, v.y);
        dst[2 * i + 1] = __floats2half2_rn(v.z, v.w);
    }
}

// ===========================================================================
// GEMM NT (fp16):  C[M,N] = A[M,K] @ W[N,K]^T + bias[N]
// Block 128x128, BK=32, 8 warps (4x2), warp tile 32x64.
// ===========================================================================
template <bool HALF_OUT>
__global__ __launch_bounds__(256, 2)
void gemm_nt_h(const __half* __restrict__ A, const __half* __restrict__ W,
               const float* __restrict__ bias, void* __restrict__ Cv,
               int M, int N, int K) {
    extern __shared__ __half smh[];
    __half* As = smh;                    // [2][128][STRH]
    __half* Bs = smh + 2 * 128 * STRH;   // [2][128][STRH]

    const int tid = threadIdx.x;
    const int bm = blockIdx.y * 128;
    const int bn = blockIdx.x * 128;
    const int w = tid >> 5, lane = tid & 31;
    const int g = lane >> 2, tig = lane & 3;
    const int wm = (w & 3) * 32, wn = (w >> 2) * 64;

    float acc[2][8][4] = {};
    const int S = K >> 5;

    auto prefetch = [&](int s, int buf) {
        const int k0 = s * 32;
        __half* Ab = As + buf * 128 * STRH;
        __half* Bb = Bs + buf * 128 * STRH;
        #pragma unroll
        for (int i = 0; i < 2; i++) {
            int ch = tid + i * 256;
            int row = ch >> 2;
            int kc = (ch & 3) * 8;
            cp16(Ab + row * STRH + kc, A + (size_t)(bm + row) * K + k0 + kc);
            cp16(Bb + row * STRH + kc, W + (size_t)(bn + row) * K + k0 + kc);
        }
    };

    prefetch(0, 0);
    cp_commit();

    for (int s = 0; s < S; s++) {
        const int buf = s & 1;
        if (s + 1 < S) { prefetch(s + 1, buf ^ 1); cp_commit(); cp_wait<1>(); }
        else           { cp_wait<0>(); }
        __syncthreads();

        const __half* Ab = As + buf * 128 * STRH;
        const __half* Bb = Bs + buf * 128 * STRH;
        #pragma unroll
        for (int kk = 0; kk < 32; kk += 16) {
            uint32_t af[2][4], bf[8][2];
            #pragma unroll
            for (int mf = 0; mf < 2; mf++) {
                int mb = wm + mf * 16;
                af[mf][0] = lds32h(Ab + (mb + g) * STRH + kk + 2 * tig);
                af[mf][1] = lds32h(Ab + (mb + g + 8) * STRH + kk + 2 * tig);
                af[mf][2] = lds32h(Ab + (mb + g) * STRH + kk + 2 * tig + 8);
                af[mf][3] = lds32h(Ab + (mb + g + 8) * STRH + kk + 2 * tig + 8);
            }
            #pragma unroll
            for (int nf = 0; nf < 8; nf++) {
                int nb = wn + nf * 8 + g;
                bf[nf][0] = lds32h(Bb + nb * STRH + kk + 2 * tig);
                bf[nf][1] = lds32h(Bb + nb * STRH + kk + 2 * tig + 8);
            }
            #pragma unroll
            for (int mf = 0; mf < 2; mf++)
                #pragma unroll
                for (int nf = 0; nf < 8; nf++)
                    mma_f16(acc[mf][nf], af[mf], bf[nf]);
        }
        __syncthreads();
    }

    #pragma unroll
    for (int mf = 0; mf < 2; mf++) {
        #pragma unroll
        for (int nf = 0; nf < 8; nf++) {
            int row = bm + wm + mf * 16 + g;
            int col = bn + wn + nf * 8 + tig * 2;
            float b0 = __ldg(bias + col);
            float b1 = __ldg(bias + col + 1);
            float c0 = acc[mf][nf][0] + b0, c1 = acc[mf][nf][1] + b1;
            float c2 = acc[mf][nf][2] + b0, c3 = acc[mf][nf][3] + b1;
            if (HALF_OUT) {
                __half* C = (__half*)Cv;
                *(__half2*)(C + (size_t)row * N + col) = __floats2half2_rn(c0, c1);
                *(__half2*)(C + (size_t)(row + 8) * N + col) = __floats2half2_rn(c2, c3);
            } else {
                float* C = (float*)Cv;
                *(float2*)(C + (size_t)row * N + col) = make_float2(c0, c1);
                *(float2*)(C + (size_t)(row + 8) * N + col) = make_float2(c2, c3);
            }
        }
    }
}

// ===========================================================================
// Scores: p_tile = exp(SCALE*q.k - m_subtile) written as fp16, plus
// per-(row, 64-col-subtile) stats (m, sumexp). No fp32 score write.
// Grid: (LK/128, LQ/128, BB*NH)
// ===========================================================================
__global__ __launch_bounds__(256, 2)
void scores_h(const __half* __restrict__ qm, const __half* __restrict__ km,
              __half* __restrict__ ph, float* __restrict__ pm,
              float* __restrict__ ps) {
    extern __shared__ __half smh[];
    __half* As = smh;                      // [128][STRH64]
    __half* Bs = smh + 128 * STRH64;       // [128][STRH64]

    const int bh = blockIdx.z;
    const int b = bh >> 4, h = bh & 15;
    const __half* Aq = qm + (size_t)b * LQ * QD + h * HD;
    const __half* Ak = km + (size_t)b * LK * QD + h * HD;
    __half* Pp = ph + (size_t)bh * LQ * LK;

    const int tid = threadIdx.x;
    const int bm = blockIdx.y * 128;
    const int bn = blockIdx.x * 128;
    const int w = tid >> 5, lane = tid & 31;
    const int g = lane >> 2, tig = lane & 3;
    const int wm = (w & 3) * 32, wn = (w >> 2) * 64;
    const int sub = blockIdx.x * 2 + (w >> 2);   // 64-col subtile index

    #pragma unroll
    for (int i = 0; i < 4; i++) {
        int ch = tid + i * 256;
        int row = ch >> 3;
        int kc = (ch & 7) * 8;
        cp16(As + row * STRH64 + kc, Aq + (size_t)(bm + row) * QD + kc);
        cp16(Bs + row * STRH64 + kc, Ak + (size_t)(bn + row) * QD + kc);
    }
    cp_commit();
    cp_wait<0>();
    __syncthreads();

    float acc[2][8][4] = {};
    #pragma unroll
    for (int kk = 0; kk < 64; kk += 16) {
        uint32_t af[2][4], bf[8][2];
        #pragma unroll
        for (int mf = 0; mf < 2; mf++) {
            int mb = wm + mf * 16;
            af[mf][0] = lds32h(As + (mb + g) * STRH64 + kk + 2 * tig);
            af[mf][1] = lds32h(As + (mb + g + 8) * STRH64 + kk + 2 * tig);
            af[mf][2] = lds32h(As + (mb + g) * STRH64 + kk + 2 * tig + 8);
            af[mf][3] = lds32h(As + (mb + g + 8) * STRH64 + kk + 2 * tig + 8);
        }
        #pragma unroll
        for (int nf = 0; nf < 8; nf++) {
            int nb = wn + nf * 8 + g;
            bf[nf][0] = lds32h(Bs + nb * STRH64 + kk + 2 * tig);
            bf[nf][1] = lds32h(Bs + nb * STRH64 + kk + 2 * tig + 8);
        }
        #pragma unroll
        for (int mf = 0; mf < 2; mf++)
            #pragma unroll
            for (int nf = 0; nf < 8; nf++)
                mma_f16(acc[mf][nf], af[mf], bf[nf]);
    }

    // per (mf): rows g (A) and g+8 (B). Scale, row max over the warp's 64 cols,
    // exponentiate in place, sum, write p as half + stats.
    #pragma unroll
    for (int mf = 0; mf < 2; mf++) {
        float mA = -1e30f, mB = -1e30f;
        #pragma unroll
        for (int nf = 0; nf < 8; nf++) {
            #pragma unroll
            for (int q = 0; q < 4; q++) acc[mf][nf][q] *= SCALE;
            mA = fmaxf(mA, fmaxf(acc[mf][nf][0], acc[mf][nf][1]));
            mB = fmaxf(mB, fmaxf(acc[mf][nf][2], acc[mf][nf][3]));
        }
        mA = fmaxf(mA, __shfl_xor_sync(0xFFFFFFFFu, mA, 1));
        mA = fmaxf(mA, __shfl_xor_sync(0xFFFFFFFFu, mA, 2));
        mB = fmaxf(mB, __shfl_xor_sync(0xFFFFFFFFu, mB, 1));
        mB = fmaxf(mB, __shfl_xor_sync(0xFFFFFFFFu, mB, 2));

        float sA = 0.f, sB = 0.f;
        #pragma unroll
        for (int nf = 0; nf < 8; nf++) {
            acc[mf][nf][0] = __expf(acc[mf][nf][0] - mA);
            acc[mf][nf][1] = __expf(acc[mf][nf][1] - mA);
            acc[mf][nf][2] = __expf(acc[mf][nf][2] - mB);
            acc[mf][nf][3] = __expf(acc[mf][nf][3] - mB);
            sA += acc[mf][nf][0] + acc[mf][nf][1];
            sB += acc[mf][nf][2] + acc[mf][nf][3];
        }
        sA += __shfl_xor_sync(0xFFFFFFFFu, sA, 1);
        sA += __shfl_xor_sync(0xFFFFFFFFu, sA, 2);
        sB += __shfl_xor_sync(0xFFFFFFFFu, sB, 1);
        sB += __shfl_xor_sync(0xFFFFFFFFu, sB, 2);

        int rowA = bm + wm + mf * 16 + g;
        #pragma unroll
        for (int nf = 0; nf < 8; nf++) {
            int col = bn + wn + nf * 8 + tig * 2;
            *(__half2*)(Pp + (size_t)rowA * LK + col) =
                __floats2half2_rn(acc[mf][nf][0], acc[mf][nf][1]);
            *(__half2*)(Pp + (size_t)(rowA + 8) * LK + col) =
                __floats2half2_rn(acc[mf][nf][2], acc[mf][nf][3]);
        }
        if (tig == 0) {
            size_t rA = (size_t)bh * LQ + rowA;
            pm[rA * NSUB + sub] = mA; ps[rA * NSUB + sub] = sA;
            pm[(rA + 8) * NSUB + sub] = mB; ps[(rA + 8) * NSUB + sub] = sB;
        }
    }
}

// ===========================================================================
// Per-row: m = max_t m_t; l = sum_t s_t*exp(m_t-m); fac_t = exp(m_t-m)/l
// ===========================================================================
__global__ void reduce_stats_k(const float* __restrict__ pm,
                               const float* __restrict__ ps,
                               float* __restrict__ fac) {
    int row = blockIdx.x * 256 + threadIdx.x;
    if (row >= TOTROWS) return;
    const float* pmr = pm + (size_t)row * NSUB;
    const float* psr = ps + (size_t)row * NSUB;
    float m = -1e30f;
    #pragma unroll
    for (int t = 0; t < NSUB; t++) m = fmaxf(m, pmr[t]);
    float l = 0.f;
    float e[NSUB];
    #pragma unroll
    for (int t = 0; t < NSUB; t++) { e[t] = __expf(pmr[t] - m); l += psr[t] * e[t]; }
    float invl = 1.0f / l;
    float* fr = fac + (size_t)row * NSUB;
    #pragma unroll
    for (int t = 0; t < NSUB; t++) fr[t] = e[t] * invl;
}

// ===========================================================================
// Context: reads p fp16 + per-subtile factors; writes attn fp32 = p*fac and
// ctx(half) = (p*fac) @ V  (factor applied to A-fragments via HMUL2).
// Grid: (LQ/128, BB*NH). Block 128 rows x 64 d, BK=32, warp tile 32x32.
// ===========================================================================
__global__ __launch_bounds__(256, 2)
void ctx_h(const __half* __restrict__ ph, const __half* __restrict__ vh,
           float* __restrict__ attn, __half* __restrict__ ctx,
           const float* __restrict__ fac) {
    extern __shared__ char smraw[];
    __half* Ps = (__half*)smraw;                            // [2][128][STRH]
    __half* Vs = (__half*)(smraw + 2 * 128 * STRH * 2);     // [2][32][VSTRH]
    float* facs = (float*)(smraw + 2 * 128 * STRH * 2 + 2 * 32 * VSTRH * 2); // [128][NSUB]

    const int bh = blockIdx.y;
    const int b = bh >> 4, h = bh & 15;
    const __half* Pp = ph + (size_t)bh * LQ * LK;
    const __half* Vp = vh + (size_t)b * LK * QD + h * HD;
    float* Ap = attn + (size_t)bh * LQ * LK;

    const int tid = threadIdx.x;
    const int bm = blockIdx.x * 128;
    const int w = tid >> 5, lane = tid & 31;
    const int g = lane >> 2, tig = lane & 3;
    const int wm = (w & 3) * 32, wn = (w >> 2) * 32;

    // factors for this row block: 128*NSUB contiguous floats
    {
        const float* fsrc = fac + ((size_t)bh * LQ + bm) * NSUB;
        #pragma unroll
        for (int i = 0; i < (128 * NSUB) / 256; i++)
            facs[i * 256 + tid] = fsrc[i * 256 + tid];
    }

    float acc[2][4][4] = {};

    auto prefetch = [&](int s, int buf) {
        const int k0 = s * 32;
        __half* Pb = Ps + buf * 128 * STRH;
        __half* Vb = Vs + buf * 32 * VSTRH;
        #pragma unroll
        for (int i = 0; i < 2; i++) {
            int ch = tid + i * 256;
            int row = ch >> 2;
            int kc = (ch & 3) * 8;
            cp16(Pb + row * STRH + kc, Pp + (size_t)(bm + row) * LK + k0 + kc);
        }
        {
            int kr = tid >> 3;           // 0..31
            int nc = (tid & 7) * 8;      // 0..56
            cp16(Vb + kr * VSTRH + nc, Vp + (size_t)(k0 + kr) * QD + nc);
        }
    };

    prefetch(0, 0);
    cp_commit();

    const int S = LK / 32;
    for (int s = 0; s < S; s++) {
        const int buf = s & 1;
        if (s + 1 < S) { prefetch(s + 1, buf ^ 1); cp_commit(); cp_wait<1>(); }
        else           { cp_wait<0>(); }
        __syncthreads();

        const __half* Pb = Ps + buf * 128 * STRH;
        const __half* Vb = Vs + buf * 32 * VSTRH;
        const int k0 = s * 32;
        const int sub = s >> 1;

        // attn write: p_fp32 = half(p) * factor
        #pragma unroll
        for (int i = 0; i < 4; i++) {
            int ch = tid + i * 256;
            int row = ch >> 3;
            int kc = (ch & 7) * 4;
            float f = facs[row * NSUB + sub];
            __half2 h0 = *(const __half2*)(Pb + row * STRH + kc);
            __half2 h1 = *(const __half2*)(Pb + row * STRH + kc + 2);
            float4 o;
            o.x = __low2float(h0) * f;  o.y = __high2float(h0) * f;
            o.z = __low2float(h1) * f;  o.w = __high2float(h1) * f;
            *(float4*)(Ap + (size_t)(bm + row) * LK + k0 + kc) = o;
        }

        #pragma unroll
        for (int kk = 0; kk < 32; kk += 16) {
            uint32_t af[2][4], bf[4][2];
            #pragma unroll
            for (int mf = 0; mf < 2; mf++) {
                int mb = wm + mf * 16;
                __half2 fg = __float2half2_rn(facs[(mb + g) * NSUB + sub]);
                __half2 f8 = __float2half2_rn(facs[(mb + g + 8) * NSUB + sub]);
                af[mf][0] = h2scale(lds32h(Pb + (mb + g) * STRH + kk + 2 * tig), fg);
                af[mf][1] = h2scale(lds32h(Pb + (mb + g + 8) * STRH + kk + 2 * tig), f8);
                af[mf][2] = h2scale(lds32h(Pb + (mb + g) * STRH + kk + 2 * tig + 8), fg);
                af[mf][3] = h2scale(lds32h(Pb + (mb + g + 8) * STRH + kk + 2 * tig + 8), f8);
            }
            #pragma unroll
            for (int nf = 0; nf < 4; nf++) {
                int nb = wn + nf * 8 + g;
                __half2 b0 = __halves2half2(Vb[(kk + 2 * tig) * VSTRH + nb],
                                            Vb[(kk + 2 * tig + 1) * VSTRH + nb]);
                __half2 b1 = __halves2half2(Vb[(kk + 2 * tig + 8) * VSTRH + nb],
                                            Vb[(kk + 2 * tig + 9) * VSTRH + nb]);
                bf[nf][0] = *(uint32_t*)&b0;
                bf[nf][1] = *(uint32_t*)&b1;
            }
            #pragma unroll
            for (int mf = 0; mf < 2; mf++)
                #pragma unroll
                for (int nf = 0; nf < 4; nf++)
                    mma_f16(acc[mf][nf], af[mf], bf[nf]);
        }
        __syncthreads();
    }

    #pragma unroll
    for (int mf = 0; mf < 2; mf++) {
        #pragma unroll
        for (int nf = 0; nf < 4; nf++) {
            int row = bm + wm + mf * 16 + g;
            int col = h * HD + wn + nf * 8 + tig * 2;
            *(__half2*)(ctx + (size_t)(b * LQ + row) * QD + col) =
                __floats2half2_rn(acc[mf][nf][0], acc[mf][nf][1]);
            *(__half2*)(ctx + (size_t)(b * LQ + row + 8) * QD + col) =
                __floats2half2_rn(acc[mf][nf][2], acc[mf][nf][3]);
        }
    }
}

// ---------------------------------------------------------------------------
// kernel_launch
// ---------------------------------------------------------------------------
extern "C" void kernel_launch(void* const* d_in, const int* in_sizes, int n_in,
                              void* d_out, int out_size) {
    const float* query = (const float*)d_in[0];
    const float* key   = (const float*)d_in[1];
    const float* value = (const float*)d_in[2];
    const float* Wq = (const float*)d_in[3];
    const float* bq = (const float*)d_in[4];
    const float* Wk = (const float*)d_in[5];
    const float* bk = (const float*)d_in[6];
    const float* Wv = (const float*)d_in[7];
    const float* bv = (const float*)d_in[8];
    const float* Wo = (const float*)d_in[9];
    const float* bo = (const float*)d_in[10];

    float* out  = (float*)d_out;
    float* attn = out + (size_t)BB * LQ * QD;

    __half *inq, *ink, *inv, *wh, *qh, *kh, *vhp, *ctxh, *php;
    float *pm, *ps, *facp;
    cudaGetSymbolAddress((void**)&inq, g_inq);
    cudaGetSymbolAddress((void**)&ink, g_ink);
    cudaGetSymbolAddress((void**)&inv, g_inv);
    cudaGetSymbolAddress((void**)&wh,  g_wh);
    cudaGetSymbolAddress((void**)&qh,  g_qh);
    cudaGetSymbolAddress((void**)&kh,  g_kh);
    cudaGetSymbolAddress((void**)&vhp, g_vh);
    cudaGetSymbolAddress((void**)&ctxh, g_ctxh);
    cudaGetSymbolAddress((void**)&php, g_ph);
    cudaGetSymbolAddress((void**)&pm, g_pm);
    cudaGetSymbolAddress((void**)&ps, g_ps);
    cudaGetSymbolAddress((void**)&facp, g_fac);

    const int SMEM_GEMM = 2 * 128 * STRH * 2 * 2;                  // 40960 B
    const int SMEM_SC   = 2 * 128 * STRH64 * 2;                    // 36864 B
    const int SMEM_CTX  = 2 * 128 * STRH * 2 + 2 * 32 * VSTRH * 2 + 128 * NSUB * 4; // 46080 B
    cudaFuncSetAttribute(gemm_nt_h<true>,  cudaFuncAttributeMaxDynamicSharedMemorySize, SMEM_GEMM);
    cudaFuncSetAttribute(gemm_nt_h<false>, cudaFuncAttributeMaxDynamicSharedMemorySize, SMEM_GEMM);
    cudaFuncSetAttribute(scores_h, cudaFuncAttributeMaxDynamicSharedMemorySize, SMEM_SC);
    cudaFuncSetAttribute(ctx_h,    cudaFuncAttributeMaxDynamicSharedMemorySize, SMEM_CTX);

    // fp32 -> fp16 conversions
    conv_f2h<<<(BB * LQ * QD / 4 + 255) / 256, 256>>>((const float4*)query, (__half2*)inq, BB * LQ * QD / 4);
    conv_f2h<<<(BB * LK * KD / 4 + 255) / 256, 256>>>((const float4*)key,   (__half2*)ink, BB * LK * KD / 4);
    conv_f2h<<<(BB * LK * KD / 4 + 255) / 256, 256>>>((const float4*)value, (__half2*)inv, BB * LK * KD / 4);
    conv_f2h<<<(QD * QD / 4 + 255) / 256, 256>>>((const float4*)Wq, (__half2*)(wh + WQ_OFF), QD * QD / 4);
    conv_f2h<<<(QD * KD / 4 + 255) / 256, 256>>>((const float4*)Wk, (__half2*)(wh + WK_OFF), QD * KD / 4);
    conv_f2h<<<(QD * KD / 4 + 255) / 256, 256>>>((const float4*)Wv, (__half2*)(wh + WV_OFF), QD * KD / 4);
    conv_f2h<<<(QD * QD / 4 + 255) / 256, 256>>>((const float4*)Wo, (__half2*)(wh + WO_OFF), QD * QD / 4);

    // Projections (fp16 MMA, half outputs)
    gemm_nt_h<true><<<dim3(QD / 128, (BB * LQ) / 128), 256, SMEM_GEMM>>>(inq, wh + WQ_OFF, bq, qh, BB * LQ, QD, QD);
    gemm_nt_h<true><<<dim3(QD / 128, (BB * LK) / 128), 256, SMEM_GEMM>>>(ink, wh + WK_OFF, bk, kh, BB * LK, QD, KD);
    gemm_nt_h<true><<<dim3(QD / 128, (BB * LK) / 128), 256, SMEM_GEMM>>>(inv, wh + WV_OFF, bv, vhp, BB * LK, QD, KD);

    // Attention: p-tiles + stats -> factors -> fused normalize/context
    scores_h<<<dim3(LK / 128, LQ / 128, BB * NH), 256, SMEM_SC>>>(qh, kh, php, pm, ps);
    reduce_stats_k<<<TOTROWS / 256, 256>>>(pm, ps, facp);
    ctx_h<<<dim3(LQ / 128, BB * NH), 256, SMEM_CTX>>>(php, vhp, attn, ctxh, facp);

    // Output projection (fp32 out)
    gemm_nt_h<false><<<dim3(QD / 128, (BB * LQ) / 128), 256, SMEM_GEMM>>>(ctxh, wh + WO_OFF, bo, out, BB * LQ, QD, QD);
}

// round 9
// speedup vs baseline: 4.3470x; 1.1680x over previous
#include <cuda_runtime.h>
#include <cuda_fp16.h>
#include <cstdint>
#include <cstddef>

// Problem constants
#define BB   4
#define LQ   1024
#define LK   2048
#define NH   16
#define HD   64
#define QD   1024
#define KD   512
#define SCALE 0.125f   // 1/sqrt(64)

#define NSUB (LK / 64)           // 32 col-subtiles of 64 per attention row
#define TOTROWS (BB * NH * LQ)   // 65536 attention rows

// ---------------------------------------------------------------------------
// Scratch (device globals; allocation-free per harness rules).
// ---------------------------------------------------------------------------
__device__ __half g_inq [(size_t)BB * LQ * QD];      // 8 MB
__device__ __half g_ink [(size_t)BB * LK * KD];      // 8 MB
__device__ __half g_inv [(size_t)BB * LK * KD];      // 8 MB
__device__ __half g_wh  [(size_t)3 * 1024 * 1024];   // 6 MB  Wq|Wk|Wv|Wo
__device__ __half g_qh  [(size_t)BB * LQ * QD];      // 8 MB
__device__ __half g_kh  [(size_t)BB * LK * QD];      // 16 MB
__device__ __half g_vh  [(size_t)BB * LK * QD];      // 16 MB
__device__ __half g_ctxh[(size_t)BB * LQ * QD];      // 8 MB
__device__ __half g_ph  [(size_t)BB * NH * LQ * LK]; // 268 MB  p_tile (fp16)
__device__ float  g_pm  [(size_t)TOTROWS * NSUB];    // 8 MB
__device__ float  g_ps  [(size_t)TOTROWS * NSUB];    // 8 MB
__device__ float  g_fac [(size_t)TOTROWS * NSUB];    // 8 MB

// weight offsets in g_wh (halves)
#define WQ_OFF 0
#define WK_OFF (1024 * 1024)
#define WV_OFF (1024 * 1024 + 512 * 1024)
#define WO_OFF (2 * 1024 * 1024)

// ---------------------------------------------------------------------------
// Helpers
// ---------------------------------------------------------------------------
__device__ __forceinline__ void mma_f16(float c[4],
                                        const uint32_t a[4],
                                        const uint32_t b[2]) {
    asm volatile(
        "mma.sync.aligned.m16n8k16.row.col.f32.f16.f16.f32 "
        "{%0,%1,%2,%3}, {%4,%5,%6,%7}, {%8,%9}, {%0,%1,%2,%3};\n"
        : "+f"(c[0]), "+f"(c[1]), "+f"(c[2]), "+f"(c[3])
        : "r"(a[0]), "r"(a[1]), "r"(a[2]), "r"(a[3]),
          "r"(b[0]), "r"(b[1]));
}

__device__ __forceinline__ uint32_t smem_u32(const void* p) {
    uint32_t r;
    asm("{ .reg .u64 t; cvta.to.shared.u64 t, %1; cvt.u32.u64 %0, t; }"
        : "=r"(r) : "l"(p));
    return r;
}
__device__ __forceinline__ void cp16(void* dst_smem, const void* src_gmem) {
    asm volatile("cp.async.cg.shared.global [%0], [%1], 16;\n"
                 :: "r"(smem_u32(dst_smem)), "l"(src_gmem));
}
__device__ __forceinline__ void cp_commit() {
    asm volatile("cp.async.commit_group;\n");
}
template <int N>
__device__ __forceinline__ void cp_wait() {
    asm volatile("cp.async.wait_group %0;\n" :: "n"(N));
}

__device__ __forceinline__ uint32_t lds32h(const __half* p) {
    return *(const uint32_t*)p;
}
__device__ __forceinline__ uint32_t h2scale(uint32_t a, __half2 f) {
    __half2 r = __hmul2(*(__half2*)&a, f);
    return *(uint32_t*)&r;
}

// smem stride (halves): rows are 144 B (odd multiple of 16B -> conflict-free)
#define STRH64 72

// ---------------------------------------------------------------------------
// Merged fp32 -> fp16 conversion for all 7 buffers (compile-time boundaries)
// ---------------------------------------------------------------------------
#define C_N1 1048576u            // query float4s
#define C_N2 2097152u            // + key
#define C_N3 3145728u            // + value
#define C_N4 3407872u            // + Wq
#define C_N5 3538944u            // + Wk
#define C_N6 3670016u            // + Wv
#define C_NT 3932160u            // + Wo

__global__ void conv_all(const float4* __restrict__ q, const float4* __restrict__ k,
                         const float4* __restrict__ v, const float4* __restrict__ wq,
                         const float4* __restrict__ wk, const float4* __restrict__ wv,
                         const float4* __restrict__ wo,
                         __half2* dq, __half2* dk, __half2* dv, __half2* dwq,
                         __half2* dwk, __half2* dwv, __half2* dwo) {
    unsigned i = blockIdx.x * 256 + threadIdx.x;
    if (i >= C_NT) return;
    const float4* s; __half2* d; unsigned off;
    if (i < C_N3) {
        if (i < C_N1)      { s = q; d = dq; off = i; }
        else if (i < C_N2) { s = k; d = dk; off = i - C_N1; }
        else               { s = v; d = dv; off = i - C_N2; }
    } else {
        if (i < C_N4)      { s = wq; d = dwq; off = i - C_N3; }
        else if (i < C_N5) { s = wk; d = dwk; off = i - C_N4; }
        else if (i < C_N6) { s = wv; d = dwv; off = i - C_N5; }
        else               { s = wo; d = dwo; off = i - C_N6; }
    }
    float4 vv = s[off];
    d[2 * off]     = __floats2half2_rn(vv.x, vv.y);
    d[2 * off + 1] = __floats2half2_rn(vv.z, vv.w);
}

// ===========================================================================
// GEMM NT (fp16 mma.sync, BK=64):  C[M,N] = A[M,K] @ W[N,K]^T + bias[N]
// Block 128x128, 8 warps (4x2), warp tile 32x64. K%64==0 at all call sites.
// Dyn smem: (As+Bs)[2][128][STRH64] halves = 73728 B.
// ===========================================================================
template <bool HALF_OUT>
__global__ __launch_bounds__(256, 2)
void gemm_nt_h(const __half* __restrict__ A, const __half* __restrict__ W,
               const float* __restrict__ bias, void* __restrict__ Cv,
               int M, int N, int K) {
    extern __shared__ __half smh[];
    __half* As = smh;                      // [2][128][STRH64]
    __half* Bs = smh + 2 * 128 * STRH64;   // [2][128][STRH64]

    const int tid = threadIdx.x;
    const int bm = blockIdx.y * 128;
    const int bn = blockIdx.x * 128;
    const int w = tid >> 5, lane = tid & 31;
    const int g = lane >> 2, tig = lane & 3;
    const int wm = (w & 3) * 32, wn = (w >> 2) * 64;

    float acc[2][8][4] = {};
    const int S = K >> 6;

    auto prefetch = [&](int s, int buf) {
        const int k0 = s * 64;
        __half* Ab = As + buf * 128 * STRH64;
        __half* Bb = Bs + buf * 128 * STRH64;
        #pragma unroll
        for (int i = 0; i < 4; i++) {
            int ch = tid + i * 256;       // 0..1023
            int row = ch >> 3;            // 0..127
            int kc = (ch & 7) * 8;        // 0..56 halves
            cp16(Ab + row * STRH64 + kc, A + (size_t)(bm + row) * K + k0 + kc);
            cp16(Bb + row * STRH64 + kc, W + (size_t)(bn + row) * K + k0 + kc);
        }
    };

    prefetch(0, 0);
    cp_commit();

    for (int s = 0; s < S; s++) {
        const int buf = s & 1;
        if (s + 1 < S) { prefetch(s + 1, buf ^ 1); cp_commit(); cp_wait<1>(); }
        else           { cp_wait<0>(); }
        __syncthreads();

        const __half* Ab = As + buf * 128 * STRH64;
        const __half* Bb = Bs + buf * 128 * STRH64;
        #pragma unroll
        for (int kk = 0; kk < 64; kk += 16) {
            uint32_t af[2][4], bf[8][2];
            #pragma unroll
            for (int mf = 0; mf < 2; mf++) {
                int mb = wm + mf * 16;
                af[mf][0] = lds32h(Ab + (mb + g) * STRH64 + kk + 2 * tig);
                af[mf][1] = lds32h(Ab + (mb + g + 8) * STRH64 + kk + 2 * tig);
                af[mf][2] = lds32h(Ab + (mb + g) * STRH64 + kk + 2 * tig + 8);
                af[mf][3] = lds32h(Ab + (mb + g + 8) * STRH64 + kk + 2 * tig + 8);
            }
            #pragma unroll
            for (int nf = 0; nf < 8; nf++) {
                int nb = wn + nf * 8 + g;
                bf[nf][0] = lds32h(Bb + nb * STRH64 + kk + 2 * tig);
                bf[nf][1] = lds32h(Bb + nb * STRH64 + kk + 2 * tig + 8);
            }
            #pragma unroll
            for (int mf = 0; mf < 2; mf++)
                #pragma unroll
                for (int nf = 0; nf < 8; nf++)
                    mma_f16(acc[mf][nf], af[mf], bf[nf]);
        }
        __syncthreads();
    }

    #pragma unroll
    for (int mf = 0; mf < 2; mf++) {
        #pragma unroll
        for (int nf = 0; nf < 8; nf++) {
            int row = bm + wm + mf * 16 + g;
            int col = bn + wn + nf * 8 + tig * 2;
            float b0 = __ldg(bias + col);
            float b1 = __ldg(bias + col + 1);
            float c0 = acc[mf][nf][0] + b0, c1 = acc[mf][nf][1] + b1;
            float c2 = acc[mf][nf][2] + b0, c3 = acc[mf][nf][3] + b1;
            if (HALF_OUT) {
                __half* C = (__half*)Cv;
                *(__half2*)(C + (size_t)row * N + col) = __floats2half2_rn(c0, c1);
                *(__half2*)(C + (size_t)(row + 8) * N + col) = __floats2half2_rn(c2, c3);
            } else {
                float* C = (float*)Cv;
                *(float2*)(C + (size_t)row * N + col) = make_float2(c0, c1);
                *(float2*)(C + (size_t)(row + 8) * N + col) = make_float2(c2, c3);
            }
        }
    }
}

// ===========================================================================
// Scores: p_tile = exp(SCALE*q.k - m_sub) fp16 + per-(row, 64-col) stats.
// Grid: (LK/128, LQ/128, BB*NH)
// ===========================================================================
__global__ __launch_bounds__(256, 2)
void scores_h(const __half* __restrict__ qm, const __half* __restrict__ km,
              __half* __restrict__ ph, float* __restrict__ pm,
              float* __restrict__ ps) {
    extern __shared__ __half smh[];
    __half* As = smh;                      // [128][STRH64]
    __half* Bs = smh + 128 * STRH64;       // [128][STRH64]

    const int bh = blockIdx.z;
    const int b = bh >> 4, h = bh & 15;
    const __half* Aq = qm + (size_t)b * LQ * QD + h * HD;
    const __half* Ak = km + (size_t)b * LK * QD + h * HD;
    __half* Pp = ph + (size_t)bh * LQ * LK;

    const int tid = threadIdx.x;
    const int bm = blockIdx.y * 128;
    const int bn = blockIdx.x * 128;
    const int w = tid >> 5, lane = tid & 31;
    const int g = lane >> 2, tig = lane & 3;
    const int wm = (w & 3) * 32, wn = (w >> 2) * 64;
    const int sub = blockIdx.x * 2 + (w >> 2);

    #pragma unroll
    for (int i = 0; i < 4; i++) {
        int ch = tid + i * 256;
        int row = ch >> 3;
        int kc = (ch & 7) * 8;
        cp16(As + row * STRH64 + kc, Aq + (size_t)(bm + row) * QD + kc);
        cp16(Bs + row * STRH64 + kc, Ak + (size_t)(bn + row) * QD + kc);
    }
    cp_commit();
    cp_wait<0>();
    __syncthreads();

    float acc[2][8][4] = {};
    #pragma unroll
    for (int kk = 0; kk < 64; kk += 16) {
        uint32_t af[2][4], bf[8][2];
        #pragma unroll
        for (int mf = 0; mf < 2; mf++) {
            int mb = wm + mf * 16;
            af[mf][0] = lds32h(As + (mb + g) * STRH64 + kk + 2 * tig);
            af[mf][1] = lds32h(As + (mb + g + 8) * STRH64 + kk + 2 * tig);
            af[mf][2] = lds32h(As + (mb + g) * STRH64 + kk + 2 * tig + 8);
            af[mf][3] = lds32h(As + (mb + g + 8) * STRH64 + kk + 2 * tig + 8);
        }
        #pragma unroll
        for (int nf = 0; nf < 8; nf++) {
            int nb = wn + nf * 8 + g;
            bf[nf][0] = lds32h(Bs + nb * STRH64 + kk + 2 * tig);
            bf[nf][1] = lds32h(Bs + nb * STRH64 + kk + 2 * tig + 8);
        }
        #pragma unroll
        for (int mf = 0; mf < 2; mf++)
            #pragma unroll
            for (int nf = 0; nf < 8; nf++)
                mma_f16(acc[mf][nf], af[mf], bf[nf]);
    }

    #pragma unroll
    for (int mf = 0; mf < 2; mf++) {
        float mA = -1e30f, mB = -1e30f;
        #pragma unroll
        for (int nf = 0; nf < 8; nf++) {
            #pragma unroll
            for (int q = 0; q < 4; q++) acc[mf][nf][q] *= SCALE;
            mA = fmaxf(mA, fmaxf(acc[mf][nf][0], acc[mf][nf][1]));
            mB = fmaxf(mB, fmaxf(acc[mf][nf][2], acc[mf][nf][3]));
        }
        mA = fmaxf(mA, __shfl_xor_sync(0xFFFFFFFFu, mA, 1));
        mA = fmaxf(mA, __shfl_xor_sync(0xFFFFFFFFu, mA, 2));
        mB = fmaxf(mB, __shfl_xor_sync(0xFFFFFFFFu, mB, 1));
        mB = fmaxf(mB, __shfl_xor_sync(0xFFFFFFFFu, mB, 2));

        float sA = 0.f, sB = 0.f;
        #pragma unroll
        for (int nf = 0; nf < 8; nf++) {
            acc[mf][nf][0] = __expf(acc[mf][nf][0] - mA);
            acc[mf][nf][1] = __expf(acc[mf][nf][1] - mA);
            acc[mf][nf][2] = __expf(acc[mf][nf][2] - mB);
            acc[mf][nf][3] = __expf(acc[mf][nf][3] - mB);
            sA += acc[mf][nf][0] + acc[mf][nf][1];
            sB += acc[mf][nf][2] + acc[mf][nf][3];
        }
        sA += __shfl_xor_sync(0xFFFFFFFFu, sA, 1);
        sA += __shfl_xor_sync(0xFFFFFFFFu, sA, 2);
        sB += __shfl_xor_sync(0xFFFFFFFFu, sB, 1);
        sB += __shfl_xor_sync(0xFFFFFFFFu, sB, 2);

        int rowA = bm + wm + mf * 16 + g;
        #pragma unroll
        for (int nf = 0; nf < 8; nf++) {
            int col = bn + wn + nf * 8 + tig * 2;
            *(__half2*)(Pp + (size_t)rowA * LK + col) =
                __floats2half2_rn(acc[mf][nf][0], acc[mf][nf][1]);
            *(__half2*)(Pp + (size_t)(rowA + 8) * LK + col) =
                __floats2half2_rn(acc[mf][nf][2], acc[mf][nf][3]);
        }
        if (tig == 0) {
            size_t rA = (size_t)bh * LQ + rowA;
            pm[rA * NSUB + sub] = mA; ps[rA * NSUB + sub] = sA;
            pm[(rA + 8) * NSUB + sub] = mB; ps[(rA + 8) * NSUB + sub] = sB;
        }
    }
}

// ===========================================================================
// Per-row factors
// ===========================================================================
__global__ void reduce_stats_k(const float* __restrict__ pm,
                               const float* __restrict__ ps,
                               float* __restrict__ fac) {
    int row = blockIdx.x * 256 + threadIdx.x;
    if (row >= TOTROWS) return;
    const float* pmr = pm + (size_t)row * NSUB;
    const float* psr = ps + (size_t)row * NSUB;
    float m = -1e30f;
    #pragma unroll
    for (int t = 0; t < NSUB; t++) m = fmaxf(m, pmr[t]);
    float l = 0.f;
    float e[NSUB];
    #pragma unroll
    for (int t = 0; t < NSUB; t++) { e[t] = __expf(pmr[t] - m); l += psr[t] * e[t]; }
    float invl = 1.0f / l;
    float* fr = fac + (size_t)row * NSUB;
    #pragma unroll
    for (int t = 0; t < NSUB; t++) fr[t] = e[t] * invl;
}

// ===========================================================================
// Context (BK=64): attn fp32 = p*fac (streaming store); ctx = (p*fac) @ V.
// Grid: (LQ/128, BB*NH). Slab s == stat subtile s.
// Dyn smem: Ps[2][128][72] + Vs[2][64][72] + facs[128][32]f = 71680 B.
// ===========================================================================
__global__ __launch_bounds__(256, 2)
void ctx_h(const __half* __restrict__ ph, const __half* __restrict__ vh,
           float* __restrict__ attn, __half* __restrict__ ctx,
           const float* __restrict__ fac) {
    extern __shared__ char smraw2[];
    __half* Ps = (__half*)smraw2;                              // [2][128][STRH64]
    __half* Vs = (__half*)(smraw2 + 2 * 128 * STRH64 * 2);     // [2][64][STRH64]
    float* facs = (float*)(smraw2 + 2 * 128 * STRH64 * 2 + 2 * 64 * STRH64 * 2);

    const int bh = blockIdx.y;
    const int b = bh >> 4, h = bh & 15;
    const __half* Pp = ph + (size_t)bh * LQ * LK;
    const __half* Vp = vh + (size_t)b * LK * QD + h * HD;
    float* Ap = attn + (size_t)bh * LQ * LK;

    const int tid = threadIdx.x;
    const int bm = blockIdx.x * 128;
    const int w = tid >> 5, lane = tid & 31;
    const int g = lane >> 2, tig = lane & 3;
    const int wm = (w & 3) * 32, wn = (w >> 2) * 32;

    {
        const float* fsrc = fac + ((size_t)bh * LQ + bm) * NSUB;
        #pragma unroll
        for (int i = 0; i < (128 * NSUB) / 256; i++)
            facs[i * 256 + tid] = fsrc[i * 256 + tid];
    }

    float acc[2][4][4] = {};

    auto prefetch = [&](int s, int buf) {
        const int k0 = s * 64;
        __half* Pb = Ps + buf * 128 * STRH64;
        __half* Vb = Vs + buf * 64 * STRH64;
        #pragma unroll
        for (int i = 0; i < 4; i++) {
            int ch = tid + i * 256;       // 0..1023
            int row = ch >> 3;            // 0..127
            int kc = (ch & 7) * 8;        // 0..56
            cp16(Pb + row * STRH64 + kc, Pp + (size_t)(bm + row) * LK + k0 + kc);
        }
        #pragma unroll
        for (int i = 0; i < 2; i++) {
            int ch = tid + i * 256;       // 0..511
            int kr = ch >> 3;             // 0..63
            int nc = (ch & 7) * 8;        // 0..56
            cp16(Vb + kr * STRH64 + nc, Vp + (size_t)(k0 + kr) * QD + nc);
        }
    };

    prefetch(0, 0);
    cp_commit();

    const int S = LK / 64;   // 32 slabs; slab s == subtile s
    for (int s = 0; s < S; s++) {
        const int buf = s & 1;
        if (s + 1 < S) { prefetch(s + 1, buf ^ 1); cp_commit(); cp_wait<1>(); }
        else           { cp_wait<0>(); }
        __syncthreads();

        const __half* Pb = Ps + buf * 128 * STRH64;
        const __half* Vb = Vs + buf * 64 * STRH64;
        const int k0 = s * 64;

        // attn write: p_fp32 = half(p) * factor (streaming store, no reuse)
        #pragma unroll
        for (int i = 0; i < 8; i++) {
            int ch = tid + i * 256;       // 0..2047
            int row = ch >> 4;            // 0..127
            int kc = (ch & 15) * 4;       // 0..60
            float f = facs[row * NSUB + s];
            __half2 h0 = *(const __half2*)(Pb + row * STRH64 + kc);
            __half2 h1 = *(const __half2*)(Pb + row * STRH64 + kc + 2);
            float4 o;
            o.x = __low2float(h0) * f;  o.y = __high2float(h0) * f;
            o.z = __low2float(h1) * f;  o.w = __high2float(h1) * f;
            __stcs((float4*)(Ap + (size_t)(bm + row) * LK + k0 + kc), o);
        }

        #pragma unroll
        for (int kk = 0; kk < 64; kk += 16) {
            uint32_t af[2][4], bf[4][2];
            #pragma unroll
            for (int mf = 0; mf < 2; mf++) {
                int mb = wm + mf * 16;
                __half2 fg = __float2half2_rn(facs[(mb + g) * NSUB + s]);
                __half2 f8 = __float2half2_rn(facs[(mb + g + 8) * NSUB + s]);
                af[mf][0] = h2scale(lds32h(Pb + (mb + g) * STRH64 + kk + 2 * tig), fg);
                af[mf][1] = h2scale(lds32h(Pb + (mb + g + 8) * STRH64 + kk + 2 * tig), f8);
                af[mf][2] = h2scale(lds32h(Pb + (mb + g) * STRH64 + kk + 2 * tig + 8), fg);
                af[mf][3] = h2scale(lds32h(Pb + (mb + g + 8) * STRH64 + kk + 2 * tig + 8), f8);
            }
            #pragma unroll
            for (int nf = 0; nf < 4; nf++) {
                int nb = wn + nf * 8 + g;
                __half2 b0 = __halves2half2(Vb[(kk + 2 * tig) * STRH64 + nb],
                                            Vb[(kk + 2 * tig + 1) * STRH64 + nb]);
                __half2 b1 = __halves2half2(Vb[(kk + 2 * tig + 8) * STRH64 + nb],
                                            Vb[(kk + 2 * tig + 9) * STRH64 + nb]);
                bf[nf][0] = *(uint32_t*)&b0;
                bf[nf][1] = *(uint32_t*)&b1;
            }
            #pragma unroll
            for (int mf = 0; mf < 2; mf++)
                #pragma unroll
                for (int nf = 0; nf < 4; nf++)
                    mma_f16(acc[mf][nf], af[mf], bf[nf]);
        }
        __syncthreads();
    }

    #pragma unroll
    for (int mf = 0; mf < 2; mf++) {
        #pragma unroll
        for (int nf = 0; nf < 4; nf++) {
            int row = bm + wm + mf * 16 + g;
            int col = h * HD + wn + nf * 8 + tig * 2;
            *(__half2*)(ctx + (size_t)(b * LQ + row) * QD + col) =
                __floats2half2_rn(acc[mf][nf][0], acc[mf][nf][1]);
            *(__half2*)(ctx + (size_t)(b * LQ + row + 8) * QD + col) =
                __floats2half2_rn(acc[mf][nf][2], acc[mf][nf][3]);
        }
    }
}

// ---------------------------------------------------------------------------
// kernel_launch
// ---------------------------------------------------------------------------
extern "C" void kernel_launch(void* const* d_in, const int* in_sizes, int n_in,
                              void* d_out, int out_size) {
    const float* query = (const float*)d_in[0];
    const float* key   = (const float*)d_in[1];
    const float* value = (const float*)d_in[2];
    const float* Wq = (const float*)d_in[3];
    const float* bq = (const float*)d_in[4];
    const float* Wk = (const float*)d_in[5];
    const float* bk = (const float*)d_in[6];
    const float* Wv = (const float*)d_in[7];
    const float* bv = (const float*)d_in[8];
    const float* Wo = (const float*)d_in[9];
    const float* bo = (const float*)d_in[10];

    float* out  = (float*)d_out;
    float* attn = out + (size_t)BB * LQ * QD;

    __half *inq, *ink, *inv, *wh, *qh, *kh, *vhp, *ctxh, *php;
    float *pm, *ps, *facp;
    cudaGetSymbolAddress((void**)&inq, g_inq);
    cudaGetSymbolAddress((void**)&ink, g_ink);
    cudaGetSymbolAddress((void**)&inv, g_inv);
    cudaGetSymbolAddress((void**)&wh,  g_wh);
    cudaGetSymbolAddress((void**)&qh,  g_qh);
    cudaGetSymbolAddress((void**)&kh,  g_kh);
    cudaGetSymbolAddress((void**)&vhp, g_vh);
    cudaGetSymbolAddress((void**)&ctxh, g_ctxh);
    cudaGetSymbolAddress((void**)&php, g_ph);
    cudaGetSymbolAddress((void**)&pm, g_pm);
    cudaGetSymbolAddress((void**)&ps, g_ps);
    cudaGetSymbolAddress((void**)&facp, g_fac);

    const int SMEM_GEMM = 2 * 2 * 128 * STRH64 * 2;                      // 73728 B
    const int SMEM_SC   = 2 * 128 * STRH64 * 2;                          // 36864 B
    const int SMEM_CTX  = 2 * 128 * STRH64 * 2 + 2 * 64 * STRH64 * 2
                        + 128 * NSUB * 4;                                // 71680 B
    cudaFuncSetAttribute(gemm_nt_h<true>,  cudaFuncAttributeMaxDynamicSharedMemorySize, SMEM_GEMM);
    cudaFuncSetAttribute(gemm_nt_h<false>, cudaFuncAttributeMaxDynamicSharedMemorySize, SMEM_GEMM);
    cudaFuncSetAttribute(scores_h, cudaFuncAttributeMaxDynamicSharedMemorySize, SMEM_SC);
    cudaFuncSetAttribute(ctx_h,    cudaFuncAttributeMaxDynamicSharedMemorySize, SMEM_CTX);

    // fp32 -> fp16 conversions (single merged launch)
    conv_all<<<C_NT / 256, 256>>>(
        (const float4*)query, (const float4*)key, (const float4*)value,
        (const float4*)Wq, (const float4*)Wk, (const float4*)Wv, (const float4*)Wo,
        (__half2*)inq, (__half2*)ink, (__half2*)inv,
        (__half2*)(wh + WQ_OFF), (__half2*)(wh + WK_OFF),
        (__half2*)(wh + WV_OFF), (__half2*)(wh + WO_OFF));

    // Projections (fp16 MMA, BK=64)
    gemm_nt_h<true><<<dim3(QD / 128, (BB * LQ) / 128), 256, SMEM_GEMM>>>(inq, wh + WQ_OFF, bq, qh, BB * LQ, QD, QD);
    gemm_nt_h<true><<<dim3(QD / 128, (BB * LK) / 128), 256, SMEM_GEMM>>>(ink, wh + WK_OFF, bk, kh, BB * LK, QD, KD);
    gemm_nt_h<true><<<dim3(QD / 128, (BB * LK) / 128), 256, SMEM_GEMM>>>(inv, wh + WV_OFF, bv, vhp, BB * LK, QD, KD);

    // Attention
    scores_h<<<dim3(LK / 128, LQ / 128, BB * NH), 256, SMEM_SC>>>(qh, kh, php, pm, ps);
    reduce_stats_k<<<TOTROWS / 256, 256>>>(pm, ps, facp);
    ctx_h<<<dim3(LQ / 128, BB * NH), 256, SMEM_CTX>>>(php, vhp, attn, ctxh, facp);

    // Output projection (fp32 out)
    gemm_nt_h<false><<<dim3(QD / 128, (BB * LQ) / 128), 256, SMEM_GEMM>>>(ctxh, wh + WO_OFF, bo, out, BB * LQ, QD, QD);
}

// round 10
// speedup vs baseline: 4.4656x; 1.0273x over previous
#include <cuda_runtime.h>
#include <cuda_fp16.h>
#include <cstdint>
#include <cstddef>

// Problem constants
#define BB   4
#define LQ   1024
#define LK   2048
#define NH   16
#define HD   64
#define QD   1024
#define KD   512
#define SCALE 0.125f   // 1/sqrt(64)

#define NSUB (LK / 64)           // 32 col-subtiles of 64 per attention row
#define TOTROWS (BB * NH * LQ)   // 65536 attention rows

// ---------------------------------------------------------------------------
// Scratch (device globals; allocation-free per harness rules).
// ---------------------------------------------------------------------------
__device__ __half g_inq [(size_t)BB * LQ * QD];      // 8 MB
__device__ __half g_ink [(size_t)BB * LK * KD];      // 8 MB
__device__ __half g_inv [(size_t)BB * LK * KD];      // 8 MB
__device__ __half g_wh  [(size_t)3 * 1024 * 1024];   // 6 MB  Wq|Wk|Wv|Wo
__device__ __half g_qh  [(size_t)BB * LQ * QD];      // 8 MB
__device__ __half g_kh  [(size_t)BB * LK * QD];      // 16 MB
__device__ __half g_vh  [(size_t)BB * LK * QD];      // 16 MB
__device__ __half g_ctxh[(size_t)BB * LQ * QD];      // 8 MB
__device__ __half g_ph  [(size_t)BB * NH * LQ * LK]; // 268 MB  p_tile (fp16)
__device__ float  g_pm  [(size_t)TOTROWS * NSUB];    // 8 MB
__device__ float  g_ps  [(size_t)TOTROWS * NSUB];    // 8 MB
__device__ float  g_fac [(size_t)TOTROWS * NSUB];    // 8 MB

// weight offsets in g_wh (halves)
#define WQ_OFF 0
#define WK_OFF (1024 * 1024)
#define WV_OFF (1024 * 1024 + 512 * 1024)
#define WO_OFF (2 * 1024 * 1024)

// ---------------------------------------------------------------------------
// Helpers
// ---------------------------------------------------------------------------
__device__ __forceinline__ void mma_f16(float c[4],
                                        const uint32_t a[4],
                                        const uint32_t b[2]) {
    asm volatile(
        "mma.sync.aligned.m16n8k16.row.col.f32.f16.f16.f32 "
        "{%0,%1,%2,%3}, {%4,%5,%6,%7}, {%8,%9}, {%0,%1,%2,%3};\n"
        : "+f"(c[0]), "+f"(c[1]), "+f"(c[2]), "+f"(c[3])
        : "r"(a[0]), "r"(a[1]), "r"(a[2]), "r"(a[3]),
          "r"(b[0]), "r"(b[1]));
}

__device__ __forceinline__ uint32_t smem_u32(const void* p) {
    uint32_t r;
    asm("{ .reg .u64 t; cvta.to.shared.u64 t, %1; cvt.u32.u64 %0, t; }"
        : "=r"(r) : "l"(p));
    return r;
}
__device__ __forceinline__ void cp16(void* dst_smem, const void* src_gmem) {
    asm volatile("cp.async.cg.shared.global [%0], [%1], 16;\n"
                 :: "r"(smem_u32(dst_smem)), "l"(src_gmem));
}
__device__ __forceinline__ void cp_commit() {
    asm volatile("cp.async.commit_group;\n");
}
template <int N>
__device__ __forceinline__ void cp_wait() {
    asm volatile("cp.async.wait_group %0;\n" :: "n"(N));
}

__device__ __forceinline__ uint32_t lds32h(const __half* p) {
    return *(const uint32_t*)p;
}
__device__ __forceinline__ uint32_t h2scale(uint32_t a, __half2 f) {
    __half2 r = __hmul2(*(__half2*)&a, f);
    return *(uint32_t*)&r;
}

// smem stride (halves): rows are 144 B (odd multiple of 16B -> conflict-free)
#define STRH64 72

// ---------------------------------------------------------------------------
// Merged fp32 -> fp16 conversion for all 7 buffers (compile-time boundaries)
// ---------------------------------------------------------------------------
#define C_N1 1048576u            // query float4s
#define C_N2 2097152u            // + key
#define C_N3 3145728u            // + value
#define C_N4 3407872u            // + Wq
#define C_N5 3538944u            // + Wk
#define C_N6 3670016u            // + Wv
#define C_NT 3932160u            // + Wo

__global__ void conv_all(const float4* __restrict__ q, const float4* __restrict__ k,
                         const float4* __restrict__ v, const float4* __restrict__ wq,
                         const float4* __restrict__ wk, const float4* __restrict__ wv,
                         const float4* __restrict__ wo,
                         __half2* dq, __half2* dk, __half2* dv, __half2* dwq,
                         __half2* dwk, __half2* dwv, __half2* dwo) {
    unsigned i = blockIdx.x * 256 + threadIdx.x;
    if (i >= C_NT) return;
    const float4* s; __half2* d; unsigned off;
    if (i < C_N3) {
        if (i < C_N1)      { s = q; d = dq; off = i; }
        else if (i < C_N2) { s = k; d = dk; off = i - C_N1; }
        else               { s = v; d = dv; off = i - C_N2; }
    } else {
        if (i < C_N4)      { s = wq; d = dwq; off = i - C_N3; }
        else if (i < C_N5) { s = wk; d = dwk; off = i - C_N4; }
        else if (i < C_N6) { s = wv; d = dwv; off = i - C_N5; }
        else               { s = wo; d = dwo; off = i - C_N6; }
    }
    float4 vv = s[off];
    d[2 * off]     = __floats2half2_rn(vv.x, vv.y);
    d[2 * off + 1] = __floats2half2_rn(vv.z, vv.w);
}

// ===========================================================================
// GEMM core (BK=64, block 128x128, 8 warps 4x2, warp tile 32x64).
// Shared by the merged-QKV kernel and the O-projection kernel.
// ===========================================================================
template <bool HALF_OUT>
__device__ __forceinline__
void gemm_body(const __half* __restrict__ A, const __half* __restrict__ W,
               const float* __restrict__ bias, void* __restrict__ Cv,
               int N, int K, int bm, int bn, __half* smh) {
    __half* As = smh;                      // [2][128][STRH64]
    __half* Bs = smh + 2 * 128 * STRH64;   // [2][128][STRH64]

    const int tid = threadIdx.x;
    const int w = tid >> 5, lane = tid & 31;
    const int g = lane >> 2, tig = lane & 3;
    const int wm = (w & 3) * 32, wn = (w >> 2) * 64;

    float acc[2][8][4] = {};
    const int S = K >> 6;

    auto prefetch = [&](int s, int buf) {
        const int k0 = s * 64;
        __half* Ab = As + buf * 128 * STRH64;
        __half* Bb = Bs + buf * 128 * STRH64;
        #pragma unroll
        for (int i = 0; i < 4; i++) {
            int ch = tid + i * 256;       // 0..1023
            int row = ch >> 3;            // 0..127
            int kc = (ch & 7) * 8;        // 0..56 halves
            cp16(Ab + row * STRH64 + kc, A + (size_t)(bm + row) * K + k0 + kc);
            cp16(Bb + row * STRH64 + kc, W + (size_t)(bn + row) * K + k0 + kc);
        }
    };

    prefetch(0, 0);
    cp_commit();

    for (int s = 0; s < S; s++) {
        const int buf = s & 1;
        if (s + 1 < S) { prefetch(s + 1, buf ^ 1); cp_commit(); cp_wait<1>(); }
        else           { cp_wait<0>(); }
        __syncthreads();

        const __half* Ab = As + buf * 128 * STRH64;
        const __half* Bb = Bs + buf * 128 * STRH64;
        #pragma unroll
        for (int kk = 0; kk < 64; kk += 16) {
            uint32_t af[2][4], bf[8][2];
            #pragma unroll
            for (int mf = 0; mf < 2; mf++) {
                int mb = wm + mf * 16;
                af[mf][0] = lds32h(Ab + (mb + g) * STRH64 + kk + 2 * tig);
                af[mf][1] = lds32h(Ab + (mb + g + 8) * STRH64 + kk + 2 * tig);
                af[mf][2] = lds32h(Ab + (mb + g) * STRH64 + kk + 2 * tig + 8);
                af[mf][3] = lds32h(Ab + (mb + g + 8) * STRH64 + kk + 2 * tig + 8);
            }
            #pragma unroll
            for (int nf = 0; nf < 8; nf++) {
                int nb = wn + nf * 8 + g;
                bf[nf][0] = lds32h(Bb + nb * STRH64 + kk + 2 * tig);
                bf[nf][1] = lds32h(Bb + nb * STRH64 + kk + 2 * tig + 8);
            }
            #pragma unroll
            for (int mf = 0; mf < 2; mf++)
                #pragma unroll
                for (int nf = 0; nf < 8; nf++)
                    mma_f16(acc[mf][nf], af[mf], bf[nf]);
        }
        __syncthreads();
    }

    #pragma unroll
    for (int mf = 0; mf < 2; mf++) {
        #pragma unroll
        for (int nf = 0; nf < 8; nf++) {
            int row = bm + wm + mf * 16 + g;
            int col = bn + wn + nf * 8 + tig * 2;
            float b0 = __ldg(bias + col);
            float b1 = __ldg(bias + col + 1);
            float c0 = acc[mf][nf][0] + b0, c1 = acc[mf][nf][1] + b1;
            float c2 = acc[mf][nf][2] + b0, c3 = acc[mf][nf][3] + b1;
            if (HALF_OUT) {
                __half* C = (__half*)Cv;
                *(__half2*)(C + (size_t)row * N + col) = __floats2half2_rn(c0, c1);
                *(__half2*)(C + (size_t)(row + 8) * N + col) = __floats2half2_rn(c2, c3);
            } else {
                float* C = (float*)Cv;
                *(float2*)(C + (size_t)row * N + col) = make_float2(c0, c1);
                *(float2*)(C + (size_t)(row + 8) * N + col) = make_float2(c2, c3);
            }
        }
    }
}

// ===========================================================================
// Merged Q/K/V projection: one launch, 1280 blocks.
//   blocks [0,256):    Q = inq @ Wq^T + bq   (M=4096,  K=1024)
//   blocks [256,768):  K = ink @ Wk^T + bk   (M=8192,  K=512)
//   blocks [768,1280): V = inv @ Wv^T + bv   (M=8192,  K=512)
// All N = 1024, half outputs.
// ===========================================================================
__global__ __launch_bounds__(256, 2)
void gemm_qkv(const __half* __restrict__ inq, const __half* __restrict__ ink,
              const __half* __restrict__ inv, const __half* __restrict__ wh,
              const float* __restrict__ bq, const float* __restrict__ bk,
              const float* __restrict__ bv,
              __half* __restrict__ qh, __half* __restrict__ kh,
              __half* __restrict__ vh) {
    extern __shared__ __half smh[];
    int blk = blockIdx.x;
    const __half *A, *W;
    const float* bias;
    __half* C;
    int K;
    if (blk < 256) {
        A = inq; W = wh + WQ_OFF; bias = bq; C = qh; K = QD;
    } else if (blk < 768) {
        blk -= 256;
        A = ink; W = wh + WK_OFF; bias = bk; C = kh; K = KD;
    } else {
        blk -= 768;
        A = inv; W = wh + WV_OFF; bias = bv; C = vh; K = KD;
    }
    const int bn = (blk & 7) * 128;
    const int bm = (blk >> 3) * 128;
    gemm_body<true>(A, W, bias, C, QD, K, bm, bn, smh);
}

// ===========================================================================
// O projection (fp32 out): grid (QD/128, BB*LQ/128)
// ===========================================================================
__global__ __launch_bounds__(256, 2)
void gemm_o(const __half* __restrict__ ctxh, const __half* __restrict__ wo,
            const float* __restrict__ bo, float* __restrict__ out) {
    extern __shared__ __half smh[];
    gemm_body<false>(ctxh, wo, bo, out, QD, QD,
                     blockIdx.y * 128, blockIdx.x * 128, smh);
}

// ===========================================================================
// Scores: p_tile = exp(SCALE*q.k - m_sub) fp16 + per-(row, 64-col) stats.
// Grid: (LK/128, LQ/128, BB*NH)
// ===========================================================================
__global__ __launch_bounds__(256, 2)
void scores_h(const __half* __restrict__ qm, const __half* __restrict__ km,
              __half* __restrict__ ph, float* __restrict__ pm,
              float* __restrict__ ps) {
    extern __shared__ __half smh[];
    __half* As = smh;                      // [128][STRH64]
    __half* Bs = smh + 128 * STRH64;       // [128][STRH64]

    const int bh = blockIdx.z;
    const int b = bh >> 4, h = bh & 15;
    const __half* Aq = qm + (size_t)b * LQ * QD + h * HD;
    const __half* Ak = km + (size_t)b * LK * QD + h * HD;
    __half* Pp = ph + (size_t)bh * LQ * LK;

    const int tid = threadIdx.x;
    const int bm = blockIdx.y * 128;
    const int bn = blockIdx.x * 128;
    const int w = tid >> 5, lane = tid & 31;
    const int g = lane >> 2, tig = lane & 3;
    const int wm = (w & 3) * 32, wn = (w >> 2) * 64;
    const int sub = blockIdx.x * 2 + (w >> 2);

    #pragma unroll
    for (int i = 0; i < 4; i++) {
        int ch = tid + i * 256;
        int row = ch >> 3;
        int kc = (ch & 7) * 8;
        cp16(As + row * STRH64 + kc, Aq + (size_t)(bm + row) * QD + kc);
        cp16(Bs + row * STRH64 + kc, Ak + (size_t)(bn + row) * QD + kc);
    }
    cp_commit();
    cp_wait<0>();
    __syncthreads();

    float acc[2][8][4] = {};
    #pragma unroll
    for (int kk = 0; kk < 64; kk += 16) {
        uint32_t af[2][4], bf[8][2];
        #pragma unroll
        for (int mf = 0; mf < 2; mf++) {
            int mb = wm + mf * 16;
            af[mf][0] = lds32h(As + (mb + g) * STRH64 + kk + 2 * tig);
            af[mf][1] = lds32h(As + (mb + g + 8) * STRH64 + kk + 2 * tig);
            af[mf][2] = lds32h(As + (mb + g) * STRH64 + kk + 2 * tig + 8);
            af[mf][3] = lds32h(As + (mb + g + 8) * STRH64 + kk + 2 * tig + 8);
        }
        #pragma unroll
        for (int nf = 0; nf < 8; nf++) {
            int nb = wn + nf * 8 + g;
            bf[nf][0] = lds32h(Bs + nb * STRH64 + kk + 2 * tig);
            bf[nf][1] = lds32h(Bs + nb * STRH64 + kk + 2 * tig + 8);
        }
        #pragma unroll
        for (int mf = 0; mf < 2; mf++)
            #pragma unroll
            for (int nf = 0; nf < 8; nf++)
                mma_f16(acc[mf][nf], af[mf], bf[nf]);
    }

    #pragma unroll
    for (int mf = 0; mf < 2; mf++) {
        float mA = -1e30f, mB = -1e30f;
        #pragma unroll
        for (int nf = 0; nf < 8; nf++) {
            #pragma unroll
            for (int q = 0; q < 4; q++) acc[mf][nf][q] *= SCALE;
            mA = fmaxf(mA, fmaxf(acc[mf][nf][0], acc[mf][nf][1]));
            mB = fmaxf(mB, fmaxf(acc[mf][nf][2], acc[mf][nf][3]));
        }
        mA = fmaxf(mA, __shfl_xor_sync(0xFFFFFFFFu, mA, 1));
        mA = fmaxf(mA, __shfl_xor_sync(0xFFFFFFFFu, mA, 2));
        mB = fmaxf(mB, __shfl_xor_sync(0xFFFFFFFFu, mB, 1));
        mB = fmaxf(mB, __shfl_xor_sync(0xFFFFFFFFu, mB, 2));

        float sA = 0.f, sB = 0.f;
        #pragma unroll
        for (int nf = 0; nf < 8; nf++) {
            acc[mf][nf][0] = __expf(acc[mf][nf][0] - mA);
            acc[mf][nf][1] = __expf(acc[mf][nf][1] - mA);
            acc[mf][nf][2] = __expf(acc[mf][nf][2] - mB);
            acc[mf][nf][3] = __expf(acc[mf][nf][3] - mB);
            sA += acc[mf][nf][0] + acc[mf][nf][1];
            sB += acc[mf][nf][2] + acc[mf][nf][3];
        }
        sA += __shfl_xor_sync(0xFFFFFFFFu, sA, 1);
        sA += __shfl_xor_sync(0xFFFFFFFFu, sA, 2);
        sB += __shfl_xor_sync(0xFFFFFFFFu, sB, 1);
        sB += __shfl_xor_sync(0xFFFFFFFFu, sB, 2);

        int rowA = bm + wm + mf * 16 + g;
        #pragma unroll
        for (int nf = 0; nf < 8; nf++) {
            int col = bn + wn + nf * 8 + tig * 2;
            *(__half2*)(Pp + (size_t)rowA * LK + col) =
                __floats2half2_rn(acc[mf][nf][0], acc[mf][nf][1]);
            *(__half2*)(Pp + (size_t)(rowA + 8) * LK + col) =
                __floats2half2_rn(acc[mf][nf][2], acc[mf][nf][3]);
        }
        if (tig == 0) {
            size_t rA = (size_t)bh * LQ + rowA;
            pm[rA * NSUB + sub] = mA; ps[rA * NSUB + sub] = sA;
            pm[(rA + 8) * NSUB + sub] = mB; ps[(rA + 8) * NSUB + sub] = sB;
        }
    }
}

// ===========================================================================
// Per-row factors
// ===========================================================================
__global__ void reduce_stats_k(const float* __restrict__ pm,
                               const float* __restrict__ ps,
                               float* __restrict__ fac) {
    int row = blockIdx.x * 256 + threadIdx.x;
    if (row >= TOTROWS) return;
    const float* pmr = pm + (size_t)row * NSUB;
    const float* psr = ps + (size_t)row * NSUB;
    float m = -1e30f;
    #pragma unroll
    for (int t = 0; t < NSUB; t++) m = fmaxf(m, pmr[t]);
    float l = 0.f;
    float e[NSUB];
    #pragma unroll
    for (int t = 0; t < NSUB; t++) { e[t] = __expf(pmr[t] - m); l += psr[t] * e[t]; }
    float invl = 1.0f / l;
    float* fr = fac + (size_t)row * NSUB;
    #pragma unroll
    for (int t = 0; t < NSUB; t++) fr[t] = e[t] * invl;
}

// ===========================================================================
// Context (BK=64): attn fp32 = p*fac (streaming store); ctx = (p*fac) @ V.
// Grid: (LQ/128, BB*NH). Slab s == stat subtile s.
// ===========================================================================
__global__ __launch_bounds__(256, 2)
void ctx_h(const __half* __restrict__ ph, const __half* __restrict__ vh,
           float* __restrict__ attn, __half* __restrict__ ctx,
           const float* __restrict__ fac) {
    extern __shared__ char smraw2[];
    __half* Ps = (__half*)smraw2;                              // [2][128][STRH64]
    __half* Vs = (__half*)(smraw2 + 2 * 128 * STRH64 * 2);     // [2][64][STRH64]
    float* facs = (float*)(smraw2 + 2 * 128 * STRH64 * 2 + 2 * 64 * STRH64 * 2);

    const int bh = blockIdx.y;
    const int b = bh >> 4, h = bh & 15;
    const __half* Pp = ph + (size_t)bh * LQ * LK;
    const __half* Vp = vh + (size_t)b * LK * QD + h * HD;
    float* Ap = attn + (size_t)bh * LQ * LK;

    const int tid = threadIdx.x;
    const int bm = blockIdx.x * 128;
    const int w = tid >> 5, lane = tid & 31;
    const int g = lane >> 2, tig = lane & 3;
    const int wm = (w & 3) * 32, wn = (w >> 2) * 32;

    {
        const float* fsrc = fac + ((size_t)bh * LQ + bm) * NSUB;
        #pragma unroll
        for (int i = 0; i < (128 * NSUB) / 256; i++)
            facs[i * 256 + tid] = fsrc[i * 256 + tid];
    }

    float acc[2][4][4] = {};

    auto prefetch = [&](int s, int buf) {
        const int k0 = s * 64;
        __half* Pb = Ps + buf * 128 * STRH64;
        __half* Vb = Vs + buf * 64 * STRH64;
        #pragma unroll
        for (int i = 0; i < 4; i++) {
            int ch = tid + i * 256;       // 0..1023
            int row = ch >> 3;            // 0..127
            int kc = (ch & 7) * 8;        // 0..56
            cp16(Pb + row * STRH64 + kc, Pp + (size_t)(bm + row) * LK + k0 + kc);
        }
        #pragma unroll
        for (int i = 0; i < 2; i++) {
            int ch = tid + i * 256;       // 0..511
            int kr = ch >> 3;             // 0..63
            int nc = (ch & 7) * 8;        // 0..56
            cp16(Vb + kr * STRH64 + nc, Vp + (size_t)(k0 + kr) * QD + nc);
        }
    };

    prefetch(0, 0);
    cp_commit();

    const int S = LK / 64;   // 32 slabs; slab s == subtile s
    for (int s = 0; s < S; s++) {
        const int buf = s & 1;
        if (s + 1 < S) { prefetch(s + 1, buf ^ 1); cp_commit(); cp_wait<1>(); }
        else           { cp_wait<0>(); }
        __syncthreads();

        const __half* Pb = Ps + buf * 128 * STRH64;
        const __half* Vb = Vs + buf * 64 * STRH64;
        const int k0 = s * 64;

        // attn write: p_fp32 = half(p) * factor (streaming store, no reuse)
        #pragma unroll
        for (int i = 0; i < 8; i++) {
            int ch = tid + i * 256;       // 0..2047
            int row = ch >> 4;            // 0..127
            int kc = (ch & 15) * 4;       // 0..60
            float f = facs[row * NSUB + s];
            __half2 h0 = *(const __half2*)(Pb + row * STRH64 + kc);
            __half2 h1 = *(const __half2*)(Pb + row * STRH64 + kc + 2);
            float4 o;
            o.x = __low2float(h0) * f;  o.y = __high2float(h0) * f;
            o.z = __low2float(h1) * f;  o.w = __high2float(h1) * f;
            __stcs((float4*)(Ap + (size_t)(bm + row) * LK + k0 + kc), o);
        }

        #pragma unroll
        for (int kk = 0; kk < 64; kk += 16) {
            uint32_t af[2][4], bf[4][2];
            #pragma unroll
            for (int mf = 0; mf < 2; mf++) {
                int mb = wm + mf * 16;
                __half2 fg = __float2half2_rn(facs[(mb + g) * NSUB + s]);
                __half2 f8 = __float2half2_rn(facs[(mb + g + 8) * NSUB + s]);
                af[mf][0] = h2scale(lds32h(Pb + (mb + g) * STRH64 + kk + 2 * tig), fg);
                af[mf][1] = h2scale(lds32h(Pb + (mb + g + 8) * STRH64 + kk + 2 * tig), f8);
                af[mf][2] = h2scale(lds32h(Pb + (mb + g) * STRH64 + kk + 2 * tig + 8), fg);
                af[mf][3] = h2scale(lds32h(Pb + (mb + g + 8) * STRH64 + kk + 2 * tig + 8), f8);
            }
            #pragma unroll
            for (int nf = 0; nf < 4; nf++) {
                int nb = wn + nf * 8 + g;
                __half2 b0 = __halves2half2(Vb[(kk + 2 * tig) * STRH64 + nb],
                                            Vb[(kk + 2 * tig + 1) * STRH64 + nb]);
                __half2 b1 = __halves2half2(Vb[(kk + 2 * tig + 8) * STRH64 + nb],
                                            Vb[(kk + 2 * tig + 9) * STRH64 + nb]);
                bf[nf][0] = *(uint32_t*)&b0;
                bf[nf][1] = *(uint32_t*)&b1;
            }
            #pragma unroll
            for (int mf = 0; mf < 2; mf++)
                #pragma unroll
                for (int nf = 0; nf < 4; nf++)
                    mma_f16(acc[mf][nf], af[mf], bf[nf]);
        }
        __syncthreads();
    }

    #pragma unroll
    for (int mf = 0; mf < 2; mf++) {
        #pragma unroll
        for (int nf = 0; nf < 4; nf++) {
            int row = bm + wm + mf * 16 + g;
            int col = h * HD + wn + nf * 8 + tig * 2;
            *(__half2*)(ctx + (size_t)(b * LQ + row) * QD + col) =
                __floats2half2_rn(acc[mf][nf][0], acc[mf][nf][1]);
            *(__half2*)(ctx + (size_t)(b * LQ + row + 8) * QD + col) =
                __floats2half2_rn(acc[mf][nf][2], acc[mf][nf][3]);
        }
    }
}

// ---------------------------------------------------------------------------
// kernel_launch
// ---------------------------------------------------------------------------
extern "C" void kernel_launch(void* const* d_in, const int* in_sizes, int n_in,
                              void* d_out, int out_size) {
    const float* query = (const float*)d_in[0];
    const float* key   = (const float*)d_in[1];
    const float* value = (const float*)d_in[2];
    const float* Wq = (const float*)d_in[3];
    const float* bq = (const float*)d_in[4];
    const float* Wk = (const float*)d_in[5];
    const float* bk = (const float*)d_in[6];
    const float* Wv = (const float*)d_in[7];
    const float* bv = (const float*)d_in[8];
    const float* Wo = (const float*)d_in[9];
    const float* bo = (const float*)d_in[10];

    float* out  = (float*)d_out;
    float* attn = out + (size_t)BB * LQ * QD;

    __half *inq, *ink, *inv, *wh, *qh, *kh, *vhp, *ctxh, *php;
    float *pm, *ps, *facp;
    cudaGetSymbolAddress((void**)&inq, g_inq);
    cudaGetSymbolAddress((void**)&ink, g_ink);
    cudaGetSymbolAddress((void**)&inv, g_inv);
    cudaGetSymbolAddress((void**)&wh,  g_wh);
    cudaGetSymbolAddress((void**)&qh,  g_qh);
    cudaGetSymbolAddress((void**)&kh,  g_kh);
    cudaGetSymbolAddress((void**)&vhp, g_vh);
    cudaGetSymbolAddress((void**)&ctxh, g_ctxh);
    cudaGetSymbolAddress((void**)&php, g_ph);
    cudaGetSymbolAddress((void**)&pm, g_pm);
    cudaGetSymbolAddress((void**)&ps, g_ps);
    cudaGetSymbolAddress((void**)&facp, g_fac);

    const int SMEM_GEMM = 2 * 2 * 128 * STRH64 * 2;                      // 73728 B
    const int SMEM_SC   = 2 * 128 * STRH64 * 2;                          // 36864 B
    const int SMEM_CTX  = 2 * 128 * STRH64 * 2 + 2 * 64 * STRH64 * 2
                        + 128 * NSUB * 4;                                // 71680 B
    cudaFuncSetAttribute(gemm_qkv, cudaFuncAttributeMaxDynamicSharedMemorySize, SMEM_GEMM);
    cudaFuncSetAttribute(gemm_o,   cudaFuncAttributeMaxDynamicSharedMemorySize, SMEM_GEMM);
    cudaFuncSetAttribute(scores_h, cudaFuncAttributeMaxDynamicSharedMemorySize, SMEM_SC);
    cudaFuncSetAttribute(ctx_h,    cudaFuncAttributeMaxDynamicSharedMemorySize, SMEM_CTX);

    // fp32 -> fp16 conversions (single merged launch)
    conv_all<<<C_NT / 256, 256>>>(
        (const float4*)query, (const float4*)key, (const float4*)value,
        (const float4*)Wq, (const float4*)Wk, (const float4*)Wv, (const float4*)Wo,
        (__half2*)inq, (__half2*)ink, (__half2*)inv,
        (__half2*)(wh + WQ_OFF), (__half2*)(wh + WK_OFF),
        (__half2*)(wh + WV_OFF), (__half2*)(wh + WO_OFF));

    // Q/K/V projections in ONE launch (1280 blocks)
    gemm_qkv<<<1280, 256, SMEM_GEMM>>>(inq, ink, inv, wh, bq, bk, bv, qh, kh, vhp);

    // Attention
    scores_h<<<dim3(LK / 128, LQ / 128, BB * NH), 256, SMEM_SC>>>(qh, kh, php, pm, ps);
    reduce_stats_k<<<TOTROWS / 256, 256>>>(pm, ps, facp);
    ctx_h<<<dim3(LQ / 128, BB * NH), 256, SMEM_CTX>>>(php, vhp, attn, ctxh, facp);

    // Output projection (fp32 out)
    gemm_o<<<dim3(QD / 128, (BB * LQ) / 128), 256, SMEM_GEMM>>>(ctxh, wh + WO_OFF, bo, out);
}

// round 11
// speedup vs baseline: 4.6524x; 1.0418x over previous
#include <cuda_runtime.h>
#include <cuda_fp16.h>
#include <cstdint>
#include <cstddef>

// Problem constants
#define BB   4
#define LQ   1024
#define LK   2048
#define NH   16
#define HD   64
#define QD   1024
#define KD   512
#define SCALE 0.125f   // 1/sqrt(64)

#define NSUB (LK / 64)           // 32 col-subtiles of 64 per attention row
#define TOTROWS (BB * NH * LQ)   // 65536 attention rows

// ---------------------------------------------------------------------------
// Scratch (device globals; allocation-free per harness rules).
// ---------------------------------------------------------------------------
__device__ __half g_inq [(size_t)BB * LQ * QD];      // 8 MB
__device__ __half g_ink [(size_t)BB * LK * KD];      // 8 MB
__device__ __half g_inv [(size_t)BB * LK * KD];      // 8 MB
__device__ __half g_wh  [(size_t)3 * 1024 * 1024];   // 6 MB  Wq|Wk|Wv|Wo
__device__ __half g_qh  [(size_t)BB * LQ * QD];      // 8 MB
__device__ __half g_kh  [(size_t)BB * LK * QD];      // 16 MB
__device__ __half g_vh  [(size_t)BB * LK * QD];      // 16 MB
__device__ __half g_ctxh[(size_t)BB * LQ * QD];      // 8 MB
__device__ __half g_ph  [(size_t)BB * NH * LQ * LK]; // 268 MB  p_tile (fp16)
__device__ float  g_pm  [(size_t)TOTROWS * NSUB];    // 8 MB
__device__ float  g_ps  [(size_t)TOTROWS * NSUB];    // 8 MB
__device__ float  g_fac [(size_t)TOTROWS * NSUB];    // 8 MB

// weight offsets in g_wh (halves)
#define WQ_OFF 0
#define WK_OFF (1024 * 1024)
#define WV_OFF (1024 * 1024 + 512 * 1024)
#define WO_OFF (2 * 1024 * 1024)

// ---------------------------------------------------------------------------
// Helpers
// ---------------------------------------------------------------------------
__device__ __forceinline__ void mma_f16(float c[4],
                                        const uint32_t a[4],
                                        const uint32_t b[2]) {
    asm volatile(
        "mma.sync.aligned.m16n8k16.row.col.f32.f16.f16.f32 "
        "{%0,%1,%2,%3}, {%4,%5,%6,%7}, {%8,%9}, {%0,%1,%2,%3};\n"
        : "+f"(c[0]), "+f"(c[1]), "+f"(c[2]), "+f"(c[3])
        : "r"(a[0]), "r"(a[1]), "r"(a[2]), "r"(a[3]),
          "r"(b[0]), "r"(b[1]));
}

__device__ __forceinline__ uint32_t smem_u32(const void* p) {
    uint32_t r;
    asm("{ .reg .u64 t; cvta.to.shared.u64 t, %1; cvt.u32.u64 %0, t; }"
        : "=r"(r) : "l"(p));
    return r;
}
__device__ __forceinline__ void cp16(void* dst_smem, const void* src_gmem) {
    asm volatile("cp.async.cg.shared.global [%0], [%1], 16;\n"
                 :: "r"(smem_u32(dst_smem)), "l"(src_gmem));
}
__device__ __forceinline__ void cp_commit() {
    asm volatile("cp.async.commit_group;\n");
}
template <int N>
__device__ __forceinline__ void cp_wait() {
    asm volatile("cp.async.wait_group %0;\n" :: "n"(N));
}

__device__ __forceinline__ uint32_t lds32h(const __half* p) {
    return *(const uint32_t*)p;
}
__device__ __forceinline__ uint32_t h2scale(uint32_t a, __half2 f) {
    __half2 r = __hmul2(*(__half2*)&a, f);
    return *(uint32_t*)&r;
}

// smem stride (halves): rows are 144 B (odd multiple of 16B -> conflict-free)
#define STRH64 72

// ---------------------------------------------------------------------------
// Merged fp32 -> fp16 conversion for all 7 buffers (compile-time boundaries)
// ---------------------------------------------------------------------------
#define C_N1 1048576u            // query float4s
#define C_N2 2097152u            // + key
#define C_N3 3145728u            // + value
#define C_N4 3407872u            // + Wq
#define C_N5 3538944u            // + Wk
#define C_N6 3670016u            // + Wv
#define C_NT 3932160u            // + Wo

__global__ void conv_all(const float4* __restrict__ q, const float4* __restrict__ k,
                         const float4* __restrict__ v, const float4* __restrict__ wq,
                         const float4* __restrict__ wk, const float4* __restrict__ wv,
                         const float4* __restrict__ wo,
                         __half2* dq, __half2* dk, __half2* dv, __half2* dwq,
                         __half2* dwk, __half2* dwv, __half2* dwo) {
    unsigned i = blockIdx.x * 256 + threadIdx.x;
    if (i >= C_NT) return;
    const float4* s; __half2* d; unsigned off;
    if (i < C_N3) {
        if (i < C_N1)      { s = q; d = dq; off = i; }
        else if (i < C_N2) { s = k; d = dk; off = i - C_N1; }
        else               { s = v; d = dv; off = i - C_N2; }
    } else {
        if (i < C_N4)      { s = wq; d = dwq; off = i - C_N3; }
        else if (i < C_N5) { s = wk; d = dwk; off = i - C_N4; }
        else if (i < C_N6) { s = wv; d = dwv; off = i - C_N5; }
        else               { s = wo; d = dwo; off = i - C_N6; }
    }
    float4 vv = s[off];
    d[2 * off]     = __floats2half2_rn(vv.x, vv.y);
    d[2 * off + 1] = __floats2half2_rn(vv.z, vv.w);
}

// ===========================================================================
// GEMM core (BK=64, block 128x128, 8 warps 4x2, warp tile 32x64).
// ===========================================================================
template <bool HALF_OUT>
__device__ __forceinline__
void gemm_body(const __half* __restrict__ A, const __half* __restrict__ W,
               const float* __restrict__ bias, void* __restrict__ Cv,
               int N, int K, int bm, int bn, __half* smh) {
    __half* As = smh;                      // [2][128][STRH64]
    __half* Bs = smh + 2 * 128 * STRH64;   // [2][128][STRH64]

    const int tid = threadIdx.x;
    const int w = tid >> 5, lane = tid & 31;
    const int g = lane >> 2, tig = lane & 3;
    const int wm = (w & 3) * 32, wn = (w >> 2) * 64;

    float acc[2][8][4] = {};
    const int S = K >> 6;

    auto prefetch = [&](int s, int buf) {
        const int k0 = s * 64;
        __half* Ab = As + buf * 128 * STRH64;
        __half* Bb = Bs + buf * 128 * STRH64;
        #pragma unroll
        for (int i = 0; i < 4; i++) {
            int ch = tid + i * 256;       // 0..1023
            int row = ch >> 3;            // 0..127
            int kc = (ch & 7) * 8;        // 0..56 halves
            cp16(Ab + row * STRH64 + kc, A + (size_t)(bm + row) * K + k0 + kc);
            cp16(Bb + row * STRH64 + kc, W + (size_t)(bn + row) * K + k0 + kc);
        }
    };

    prefetch(0, 0);
    cp_commit();

    for (int s = 0; s < S; s++) {
        const int buf = s & 1;
        if (s + 1 < S) { prefetch(s + 1, buf ^ 1); cp_commit(); cp_wait<1>(); }
        else           { cp_wait<0>(); }
        __syncthreads();

        const __half* Ab = As + buf * 128 * STRH64;
        const __half* Bb = Bs + buf * 128 * STRH64;
        #pragma unroll
        for (int kk = 0; kk < 64; kk += 16) {
            uint32_t af[2][4], bf[8][2];
            #pragma unroll
            for (int mf = 0; mf < 2; mf++) {
                int mb = wm + mf * 16;
                af[mf][0] = lds32h(Ab + (mb + g) * STRH64 + kk + 2 * tig);
                af[mf][1] = lds32h(Ab + (mb + g + 8) * STRH64 + kk + 2 * tig);
                af[mf][2] = lds32h(Ab + (mb + g) * STRH64 + kk + 2 * tig + 8);
                af[mf][3] = lds32h(Ab + (mb + g + 8) * STRH64 + kk + 2 * tig + 8);
            }
            #pragma unroll
            for (int nf = 0; nf < 8; nf++) {
                int nb = wn + nf * 8 + g;
                bf[nf][0] = lds32h(Bb + nb * STRH64 + kk + 2 * tig);
                bf[nf][1] = lds32h(Bb + nb * STRH64 + kk + 2 * tig + 8);
            }
            #pragma unroll
            for (int mf = 0; mf < 2; mf++)
                #pragma unroll
                for (int nf = 0; nf < 8; nf++)
                    mma_f16(acc[mf][nf], af[mf], bf[nf]);
        }
        __syncthreads();
    }

    #pragma unroll
    for (int mf = 0; mf < 2; mf++) {
        #pragma unroll
        for (int nf = 0; nf < 8; nf++) {
            int row = bm + wm + mf * 16 + g;
            int col = bn + wn + nf * 8 + tig * 2;
            float b0 = __ldg(bias + col);
            float b1 = __ldg(bias + col + 1);
            float c0 = acc[mf][nf][0] + b0, c1 = acc[mf][nf][1] + b1;
            float c2 = acc[mf][nf][2] + b0, c3 = acc[mf][nf][3] + b1;
            if (HALF_OUT) {
                __half* C = (__half*)Cv;
                *(__half2*)(C + (size_t)row * N + col) = __floats2half2_rn(c0, c1);
                *(__half2*)(C + (size_t)(row + 8) * N + col) = __floats2half2_rn(c2, c3);
            } else {
                float* C = (float*)Cv;
                *(float2*)(C + (size_t)row * N + col) = make_float2(c0, c1);
                *(float2*)(C + (size_t)(row + 8) * N + col) = make_float2(c2, c3);
            }
        }
    }
}

// ===========================================================================
// Merged Q/K/V projection: one launch, 1280 blocks.
// ===========================================================================
__global__ __launch_bounds__(256, 2)
void gemm_qkv(const __half* __restrict__ inq, const __half* __restrict__ ink,
              const __half* __restrict__ inv, const __half* __restrict__ wh,
              const float* __restrict__ bq, const float* __restrict__ bk,
              const float* __restrict__ bv,
              __half* __restrict__ qh, __half* __restrict__ kh,
              __half* __restrict__ vh) {
    extern __shared__ __half smh[];
    int blk = blockIdx.x;
    const __half *A, *W;
    const float* bias;
    __half* C;
    int K;
    if (blk < 256) {
        A = inq; W = wh + WQ_OFF; bias = bq; C = qh; K = QD;
    } else if (blk < 768) {
        blk -= 256;
        A = ink; W = wh + WK_OFF; bias = bk; C = kh; K = KD;
    } else {
        blk -= 768;
        A = inv; W = wh + WV_OFF; bias = bv; C = vh; K = KD;
    }
    const int bn = (blk & 7) * 128;
    const int bm = (blk >> 3) * 128;
    gemm_body<true>(A, W, bias, C, QD, K, bm, bn, smh);
}

// ===========================================================================
// O projection (fp32 out): grid (QD/128, BB*LQ/128)
// ===========================================================================
__global__ __launch_bounds__(256, 2)
void gemm_o(const __half* __restrict__ ctxh, const __half* __restrict__ wo,
            const float* __restrict__ bo, float* __restrict__ out) {
    extern __shared__ __half smh[];
    gemm_body<false>(ctxh, wo, bo, out, QD, QD,
                     blockIdx.y * 128, blockIdx.x * 128, smh);
}

// ===========================================================================
// Scores: p_tile = exp(SCALE*q.k - m_sub) fp16 + per-(row, 64-col) stats.
// Grid: (LK/128, LQ/128, BB*NH)
// ===========================================================================
__global__ __launch_bounds__(256, 2)
void scores_h(const __half* __restrict__ qm, const __half* __restrict__ km,
              __half* __restrict__ ph, float* __restrict__ pm,
              float* __restrict__ ps) {
    extern __shared__ __half smh[];
    __half* As = smh;                      // [128][STRH64]
    __half* Bs = smh + 128 * STRH64;       // [128][STRH64]

    const int bh = blockIdx.z;
    const int b = bh >> 4, h = bh & 15;
    const __half* Aq = qm + (size_t)b * LQ * QD + h * HD;
    const __half* Ak = km + (size_t)b * LK * QD + h * HD;
    __half* Pp = ph + (size_t)bh * LQ * LK;

    const int tid = threadIdx.x;
    const int bm = blockIdx.y * 128;
    const int bn = blockIdx.x * 128;
    const int w = tid >> 5, lane = tid & 31;
    const int g = lane >> 2, tig = lane & 3;
    const int wm = (w & 3) * 32, wn = (w >> 2) * 64;
    const int sub = blockIdx.x * 2 + (w >> 2);

    #pragma unroll
    for (int i = 0; i < 4; i++) {
        int ch = tid + i * 256;
        int row = ch >> 3;
        int kc = (ch & 7) * 8;
        cp16(As + row * STRH64 + kc, Aq + (size_t)(bm + row) * QD + kc);
        cp16(Bs + row * STRH64 + kc, Ak + (size_t)(bn + row) * QD + kc);
    }
    cp_commit();
    cp_wait<0>();
    __syncthreads();

    float acc[2][8][4] = {};
    #pragma unroll
    for (int kk = 0; kk < 64; kk += 16) {
        uint32_t af[2][4], bf[8][2];
        #pragma unroll
        for (int mf = 0; mf < 2; mf++) {
            int mb = wm + mf * 16;
            af[mf][0] = lds32h(As + (mb + g) * STRH64 + kk + 2 * tig);
            af[mf][1] = lds32h(As + (mb + g + 8) * STRH64 + kk + 2 * tig);
            af[mf][2] = lds32h(As + (mb + g) * STRH64 + kk + 2 * tig + 8);
            af[mf][3] = lds32h(As + (mb + g + 8) * STRH64 + kk + 2 * tig + 8);
        }
        #pragma unroll
        for (int nf = 0; nf < 8; nf++) {
            int nb = wn + nf * 8 + g;
            bf[nf][0] = lds32h(Bs + nb * STRH64 + kk + 2 * tig);
            bf[nf][1] = lds32h(Bs + nb * STRH64 + kk + 2 * tig + 8);
        }
        #pragma unroll
        for (int mf = 0; mf < 2; mf++)
            #pragma unroll
            for (int nf = 0; nf < 8; nf++)
                mma_f16(acc[mf][nf], af[mf], bf[nf]);
    }

    #pragma unroll
    for (int mf = 0; mf < 2; mf++) {
        float mA = -1e30f, mB = -1e30f;
        #pragma unroll
        for (int nf = 0; nf < 8; nf++) {
            #pragma unroll
            for (int q = 0; q < 4; q++) acc[mf][nf][q] *= SCALE;
            mA = fmaxf(mA, fmaxf(acc[mf][nf][0], acc[mf][nf][1]));
            mB = fmaxf(mB, fmaxf(acc[mf][nf][2], acc[mf][nf][3]));
        }
        mA = fmaxf(mA, __shfl_xor_sync(0xFFFFFFFFu, mA, 1));
        mA = fmaxf(mA, __shfl_xor_sync(0xFFFFFFFFu, mA, 2));
        mB = fmaxf(mB, __shfl_xor_sync(0xFFFFFFFFu, mB, 1));
        mB = fmaxf(mB, __shfl_xor_sync(0xFFFFFFFFu, mB, 2));

        float sA = 0.f, sB = 0.f;
        #pragma unroll
        for (int nf = 0; nf < 8; nf++) {
            acc[mf][nf][0] = __expf(acc[mf][nf][0] - mA);
            acc[mf][nf][1] = __expf(acc[mf][nf][1] - mA);
            acc[mf][nf][2] = __expf(acc[mf][nf][2] - mB);
            acc[mf][nf][3] = __expf(acc[mf][nf][3] - mB);
            sA += acc[mf][nf][0] + acc[mf][nf][1];
            sB += acc[mf][nf][2] + acc[mf][nf][3];
        }
        sA += __shfl_xor_sync(0xFFFFFFFFu, sA, 1);
        sA += __shfl_xor_sync(0xFFFFFFFFu, sA, 2);
        sB += __shfl_xor_sync(0xFFFFFFFFu, sB, 1);
        sB += __shfl_xor_sync(0xFFFFFFFFu, sB, 2);

        int rowA = bm + wm + mf * 16 + g;
        #pragma unroll
        for (int nf = 0; nf < 8; nf++) {
            int col = bn + wn + nf * 8 + tig * 2;
            *(__half2*)(Pp + (size_t)rowA * LK + col) =
                __floats2half2_rn(acc[mf][nf][0], acc[mf][nf][1]);
            *(__half2*)(Pp + (size_t)(rowA + 8) * LK + col) =
                __floats2half2_rn(acc[mf][nf][2], acc[mf][nf][3]);
        }
        if (tig == 0) {
            size_t rA = (size_t)bh * LQ + rowA;
            pm[rA * NSUB + sub] = mA; ps[rA * NSUB + sub] = sA;
            pm[(rA + 8) * NSUB + sub] = mB; ps[(rA + 8) * NSUB + sub] = sB;
        }
    }
}

// ===========================================================================
// Per-row factors: ONE WARP PER ROW (lane t owns subtile t; NSUB == 32).
// Coalesced loads (each row's 32 stats = two 128B lines), shfl reductions,
// no local-array spill. Grid: TOTROWS/8 blocks x 256 threads (8 warps).
// ===========================================================================
__global__ __launch_bounds__(256)
void reduce_stats_k(const float* __restrict__ pm,
                    const float* __restrict__ ps,
                    float* __restrict__ fac) {
    const int row = blockIdx.x * 8 + (threadIdx.x >> 5);
    const int lane = threadIdx.x & 31;
    const size_t idx = (size_t)row * NSUB + lane;

    float m = pm[idx];
    float s = ps[idx];

    float mr = m;
    #pragma unroll
    for (int o = 16; o > 0; o >>= 1)
        mr = fmaxf(mr, __shfl_xor_sync(0xFFFFFFFFu, mr, o));

    float e = __expf(m - mr);
    float le = s * e;
    #pragma unroll
    for (int o = 16; o > 0; o >>= 1)
        le += __shfl_xor_sync(0xFFFFFFFFu, le, o);

    fac[idx] = e / le;
}

// ===========================================================================
// Context (BK=64): attn fp32 = p*fac (streaming store); ctx = (p*fac) @ V.
// Grid: (LQ/128, BB*NH). Slab s == stat subtile s.
// ===========================================================================
__global__ __launch_bounds__(256, 2)
void ctx_h(const __half* __restrict__ ph, const __half* __restrict__ vh,
           float* __restrict__ attn, __half* __restrict__ ctx,
           const float* __restrict__ fac) {
    extern __shared__ char smraw2[];
    __half* Ps = (__half*)smraw2;                              // [2][128][STRH64]
    __half* Vs = (__half*)(smraw2 + 2 * 128 * STRH64 * 2);     // [2][64][STRH64]
    float* facs = (float*)(smraw2 + 2 * 128 * STRH64 * 2 + 2 * 64 * STRH64 * 2);

    const int bh = blockIdx.y;
    const int b = bh >> 4, h = bh & 15;
    const __half* Pp = ph + (size_t)bh * LQ * LK;
    const __half* Vp = vh + (size_t)b * LK * QD + h * HD;
    float* Ap = attn + (size_t)bh * LQ * LK;

    const int tid = threadIdx.x;
    const int bm = blockIdx.x * 128;
    const int w = tid >> 5, lane = tid & 31;
    const int g = lane >> 2, tig = lane & 3;
    const int wm = (w & 3) * 32, wn = (w >> 2) * 32;

    {
        const float* fsrc = fac + ((size_t)bh * LQ + bm) * NSUB;
        #pragma unroll
        for (int i = 0; i < (128 * NSUB) / 256; i++)
            facs[i * 256 + tid] = fsrc[i * 256 + tid];
    }

    float acc[2][4][4] = {};

    auto prefetch = [&](int s, int buf) {
        const int k0 = s * 64;
        __half* Pb = Ps + buf * 128 * STRH64;
        __half* Vb = Vs + buf * 64 * STRH64;
        #pragma unroll
        for (int i = 0; i < 4; i++) {
            int ch = tid + i * 256;       // 0..1023
            int row = ch >> 3;            // 0..127
            int kc = (ch & 7) * 8;        // 0..56
            cp16(Pb + row * STRH64 + kc, Pp + (size_t)(bm + row) * LK + k0 + kc);
        }
        #pragma unroll
        for (int i = 0; i < 2; i++) {
            int ch = tid + i * 256;       // 0..511
            int kr = ch >> 3;             // 0..63
            int nc = (ch & 7) * 8;        // 0..56
            cp16(Vb + kr * STRH64 + nc, Vp + (size_t)(k0 + kr) * QD + nc);
        }
    };

    prefetch(0, 0);
    cp_commit();

    const int S = LK / 64;   // 32 slabs; slab s == subtile s
    for (int s = 0; s < S; s++) {
        const int buf = s & 1;
        if (s + 1 < S) { prefetch(s + 1, buf ^ 1); cp_commit(); cp_wait<1>(); }
        else           { cp_wait<0>(); }
        __syncthreads();

        const __half* Pb = Ps + buf * 128 * STRH64;
        const __half* Vb = Vs + buf * 64 * STRH64;
        const int k0 = s * 64;

        // attn write: p_fp32 = half(p) * factor (streaming store, no reuse)
        #pragma unroll
        for (int i = 0; i < 8; i++) {
            int ch = tid + i * 256;       // 0..2047
            int row = ch >> 4;            // 0..127
            int kc = (ch & 15) * 4;       // 0..60
            float f = facs[row * NSUB + s];
            __half2 h0 = *(const __half2*)(Pb + row * STRH64 + kc);
            __half2 h1 = *(const __half2*)(Pb + row * STRH64 + kc + 2);
            float4 o;
            o.x = __low2float(h0) * f;  o.y = __high2float(h0) * f;
            o.z = __low2float(h1) * f;  o.w = __high2float(h1) * f;
            __stcs((float4*)(Ap + (size_t)(bm + row) * LK + k0 + kc), o);
        }

        #pragma unroll
        for (int kk = 0; kk < 64; kk += 16) {
            uint32_t af[2][4], bf[4][2];
            #pragma unroll
            for (int mf = 0; mf < 2; mf++) {
                int mb = wm + mf * 16;
                __half2 fg = __float2half2_rn(facs[(mb + g) * NSUB + s]);
                __half2 f8 = __float2half2_rn(facs[(mb + g + 8) * NSUB + s]);
                af[mf][0] = h2scale(lds32h(Pb + (mb + g) * STRH64 + kk + 2 * tig), fg);
                af[mf][1] = h2scale(lds32h(Pb + (mb + g + 8) * STRH64 + kk + 2 * tig), f8);
                af[mf][2] = h2scale(lds32h(Pb + (mb + g) * STRH64 + kk + 2 * tig + 8), fg);
                af[mf][3] = h2scale(lds32h(Pb + (mb + g + 8) * STRH64 + kk + 2 * tig + 8), f8);
            }
            #pragma unroll
            for (int nf = 0; nf < 4; nf++) {
                int nb = wn + nf * 8 + g;
                __half2 b0 = __halves2half2(Vb[(kk + 2 * tig) * STRH64 + nb],
                                            Vb[(kk + 2 * tig + 1) * STRH64 + nb]);
                __half2 b1 = __halves2half2(Vb[(kk + 2 * tig + 8) * STRH64 + nb],
                                            Vb[(kk + 2 * tig + 9) * STRH64 + nb]);
                bf[nf][0] = *(uint32_t*)&b0;
                bf[nf][1] = *(uint32_t*)&b1;
            }
            #pragma unroll
            for (int mf = 0; mf < 2; mf++)
                #pragma unroll
                for (int nf = 0; nf < 4; nf++)
                    mma_f16(acc[mf][nf], af[mf], bf[nf]);
        }
        __syncthreads();
    }

    #pragma unroll
    for (int mf = 0; mf < 2; mf++) {
        #pragma unroll
        for (int nf = 0; nf < 4; nf++) {
            int row = bm + wm + mf * 16 + g;
            int col = h * HD + wn + nf * 8 + tig * 2;
            *(__half2*)(ctx + (size_t)(b * LQ + row) * QD + col) =
                __floats2half2_rn(acc[mf][nf][0], acc[mf][nf][1]);
            *(__half2*)(ctx + (size_t)(b * LQ + row + 8) * QD + col) =
                __floats2half2_rn(acc[mf][nf][2], acc[mf][nf][3]);
        }
    }
}

// ---------------------------------------------------------------------------
// kernel_launch
// ---------------------------------------------------------------------------
extern "C" void kernel_launch(void* const* d_in, const int* in_sizes, int n_in,
                              void* d_out, int out_size) {
    const float* query = (const float*)d_in[0];
    const float* key   = (const float*)d_in[1];
    const float* value = (const float*)d_in[2];
    const float* Wq = (const float*)d_in[3];
    const float* bq = (const float*)d_in[4];
    const float* Wk = (const float*)d_in[5];
    const float* bk = (const float*)d_in[6];
    const float* Wv = (const float*)d_in[7];
    const float* bv = (const float*)d_in[8];
    const float* Wo = (const float*)d_in[9];
    const float* bo = (const float*)d_in[10];

    float* out  = (float*)d_out;
    float* attn = out + (size_t)BB * LQ * QD;

    __half *inq, *ink, *inv, *wh, *qh, *kh, *vhp, *ctxh, *php;
    float *pm, *ps, *facp;
    cudaGetSymbolAddress((void**)&inq, g_inq);
    cudaGetSymbolAddress((void**)&ink, g_ink);
    cudaGetSymbolAddress((void**)&inv, g_inv);
    cudaGetSymbolAddress((void**)&wh,  g_wh);
    cudaGetSymbolAddress((void**)&qh,  g_qh);
    cudaGetSymbolAddress((void**)&kh,  g_kh);
    cudaGetSymbolAddress((void**)&vhp, g_vh);
    cudaGetSymbolAddress((void**)&ctxh, g_ctxh);
    cudaGetSymbolAddress((void**)&php, g_ph);
    cudaGetSymbolAddress((void**)&pm, g_pm);
    cudaGetSymbolAddress((void**)&ps, g_ps);
    cudaGetSymbolAddress((void**)&facp, g_fac);

    const int SMEM_GEMM = 2 * 2 * 128 * STRH64 * 2;                      // 73728 B
    const int SMEM_SC   = 2 * 128 * STRH64 * 2;                          // 36864 B
    const int SMEM_CTX  = 2 * 128 * STRH64 * 2 + 2 * 64 * STRH64 * 2
                        + 128 * NSUB * 4;                                // 71680 B
    cudaFuncSetAttribute(gemm_qkv, cudaFuncAttributeMaxDynamicSharedMemorySize, SMEM_GEMM);
    cudaFuncSetAttribute(gemm_o,   cudaFuncAttributeMaxDynamicSharedMemorySize, SMEM_GEMM);
    cudaFuncSetAttribute(scores_h, cudaFuncAttributeMaxDynamicSharedMemorySize, SMEM_SC);
    cudaFuncSetAttribute(ctx_h,    cudaFuncAttributeMaxDynamicSharedMemorySize, SMEM_CTX);

    // fp32 -> fp16 conversions (single merged launch)
    conv_all<<<C_NT / 256, 256>>>(
        (const float4*)query, (const float4*)key, (const float4*)value,
        (const float4*)Wq, (const float4*)Wk, (const float4*)Wv, (const float4*)Wo,
        (__half2*)inq, (__half2*)ink, (__half2*)inv,
        (__half2*)(wh + WQ_OFF), (__half2*)(wh + WK_OFF),
        (__half2*)(wh + WV_OFF), (__half2*)(wh + WO_OFF));

    // Q/K/V projections in ONE launch (1280 blocks)
    gemm_qkv<<<1280, 256, SMEM_GEMM>>>(inq, ink, inv, wh, bq, bk, bv, qh, kh, vhp);

    // Attention
    scores_h<<<dim3(LK / 128, LQ / 128, BB * NH), 256, SMEM_SC>>>(qh, kh, php, pm, ps);
    reduce_stats_k<<<TOTROWS / 8, 256>>>(pm, ps, facp);
    ctx_h<<<dim3(LQ / 128, BB * NH), 256, SMEM_CTX>>>(php, vhp, attn, ctxh, facp);

    // Output projection (fp32 out)
    gemm_o<<<dim3(QD / 128, (BB * LQ) / 128), 256, SMEM_GEMM>>>(ctxh, wh + WO_OFF, bo, out);
}